// round 2
// baseline (speedup 1.0000x reference)
#include <cuda_runtime.h>
#include <math.h>

#define BB 16
#define NN 8192
#define CC 128
#define KK 128
#define LL 4
#define J1 257          // 2K + 1 (cos rows, sin rows, mask row)
#define JA 392          // 385 (2K + 1 + C) padded to multiple of 8
#define NSPLIT 8

// ---------------- scratch (device globals; no allocation allowed) ----------
__device__ float g_bases[(size_t)BB * J1 * NN];          // [b][j][x]; j<128 cos, <256 sin, 256 mask
__device__ float g_wsz[BB * NN];                         // weights * size
__device__ float g_h[2][(size_t)BB * CC * NN];           // ping-pong h
__device__ float g_part[(size_t)NSPLIT * BB * CC * J1];  // split-x partials of G1
__device__ float g_A[(size_t)BB * CC * JA];              // [2f_c, -2f_s, f_0, conv_w, pad]
__device__ float g_wct[(size_t)LL * KK * CC * CC];       // wc/size transposed to [l][k][i][o]
__device__ float g_wst[(size_t)LL * KK * CC * CC];

__device__ __forceinline__ float gelu_f(float v) {
    return 0.5f * v * (1.0f + erff(v * 0.70710678118654752f));
}

// ---------------- weight transpose: wc/ws (l,i,o,k) -> (l,k,i,o), /size ----
__global__ void k_wtrans(const float* __restrict__ wc, const float* __restrict__ ws) {
    __shared__ float sm[32][33];
    const int tile = blockIdx.x;              // 16 tiles: (o-tile, k-tile)
    const int o0 = (tile >> 2) * 32, k0 = (tile & 3) * 32;
    const int i = blockIdx.y, l = blockIdx.z;
    const float scale = 1.0f / 8192.0f;
    for (int w = 0; w < 2; w++) {
        const float* src = w ? ws : wc;
        float* dst = w ? g_wst : g_wct;
        #pragma unroll
        for (int s = 0; s < 4; s++) {
            int oo = threadIdx.y + 8 * s, kk = threadIdx.x;
            sm[oo][kk] = src[(((size_t)l * CC + i) * CC + (o0 + oo)) * KK + (k0 + kk)] * scale;
        }
        __syncthreads();
        #pragma unroll
        for (int s = 0; s < 4; s++) {
            int kk = threadIdx.y + 8 * s, oo = threadIdx.x;
            dst[(((size_t)l * KK + (k0 + kk)) * CC + i) * CC + (o0 + oo)] = sm[oo][kk];
        }
        __syncthreads();
    }
}

// ---------------- precompute bases, wsz, h0 = fc0(x) ------------------------
__global__ __launch_bounds__(256) void k_pre(const float* __restrict__ xin,
                                             const float* __restrict__ modes,
                                             const float* __restrict__ fc0_w,
                                             const float* __restrict__ fc0_b) {
    __shared__ float sm_modes[256];
    __shared__ float sm_w[384];
    __shared__ float sm_b[128];
    const int t = threadIdx.x;
    sm_modes[t] = modes[t];
    sm_w[t] = fc0_w[t];
    if (t < 128) { sm_w[256 + t] = fc0_w[256 + t]; sm_b[t] = fc0_b[t]; }
    __syncthreads();

    const int gid = blockIdx.x * 256 + t;     // over B*N
    const int b = gid / NN, xx = gid - b * NN;
    const float* xr = xin + (size_t)gid * 7;
    const float i0 = xr[0], i1 = xr[1], i2 = xr[2];
    const float d0 = xr[3], d1 = xr[4], wgt = xr[5], msk = xr[6];

    g_wsz[gid] = wgt * (float)NN;
    float* bb = g_bases + (size_t)b * J1 * NN + xx;
    bb[(size_t)256 * NN] = msk;
    #pragma unroll 4
    for (int k = 0; k < KK; k++) {
        float tt = fmaf(d0, sm_modes[2 * k], d1 * sm_modes[2 * k + 1]);
        float s, c;
        sincosf(tt, &s, &c);
        bb[(size_t)k * NN] = c * msk;
        bb[(size_t)(128 + k) * NN] = s * msk;
    }
    float* hh = g_h[0] + (size_t)b * CC * NN + xx;
    #pragma unroll 4
    for (int c = 0; c < CC; c++) {
        float v = sm_b[c];
        v = fmaf(i0, sm_w[c], v);
        v = fmaf(i1, sm_w[128 + c], v);
        v = fmaf(i2, sm_w[256 + c], v);
        hh[(size_t)c * NN] = v;
    }
}

// ---------------- G1: partials[s][b][i][j] = sum_x h*wsz * bases[j] --------
// grid (jtile=5, split=8, b=16); block (16,16); 128(i) x 64(j) tile, 8x4 micro
__global__ __launch_bounds__(256) void k_gemm1(int cur) {
    __shared__ float As[32][128];   // [x][i]
    __shared__ float Bs[32][64];    // [x][j] (scaled by wsz)
    __shared__ float wzs[32];
    const int jt = blockIdx.x, sp = blockIdx.y, b = blockIdx.z;
    const int tx = threadIdx.x, ty = threadIdx.y;
    const int tid = ty * 16 + tx;
    const float* hsrc = g_h[cur] + (size_t)b * CC * NN;
    const float* bsrc = g_bases + (size_t)b * J1 * NN;
    const int j0 = jt * 64;
    float acc[8][4];
    #pragma unroll
    for (int i = 0; i < 8; i++)
        #pragma unroll
        for (int j = 0; j < 4; j++) acc[i][j] = 0.f;

    const int ai = tid >> 1;
    const int axs = (tid & 1) * 16;
    const int bjj = tid >> 2;
    const int bxs = (tid & 3) * 8;
    const int jg = j0 + bjj;

    const int xbeg = sp * (NN / NSPLIT), xend = xbeg + (NN / NSPLIT);
    for (int x0 = xbeg; x0 < xend; x0 += 32) {
        if (tid < 32) wzs[tid] = g_wsz[b * NN + x0 + tid];
        __syncthreads();
        {   // A tile: h rows
            const float4* hp = (const float4*)(hsrc + (size_t)ai * NN + x0 + axs);
            #pragma unroll
            for (int u = 0; u < 4; u++) {
                float4 v = hp[u];
                As[axs + u * 4 + 0][ai] = v.x;
                As[axs + u * 4 + 1][ai] = v.y;
                As[axs + u * 4 + 2][ai] = v.z;
                As[axs + u * 4 + 3][ai] = v.w;
            }
        }
        {   // B tile: bases rows * wsz
            float bv[8];
            if (jg < J1) {
                const float* bp = bsrc + (size_t)jg * NN + x0 + bxs;
                #pragma unroll
                for (int u = 0; u < 8; u++) bv[u] = bp[u] * wzs[bxs + u];
            } else {
                #pragma unroll
                for (int u = 0; u < 8; u++) bv[u] = 0.f;
            }
            #pragma unroll
            for (int u = 0; u < 8; u++) Bs[bxs + u][bjj] = bv[u];
        }
        __syncthreads();
        #pragma unroll
        for (int x = 0; x < 32; x++) {
            float a[8], bq[4];
            *(float4*)&a[0] = *(const float4*)&As[x][ty * 8];
            *(float4*)&a[4] = *(const float4*)&As[x][ty * 8 + 4];
            *(float4*)&bq[0] = *(const float4*)&Bs[x][tx * 4];
            #pragma unroll
            for (int i = 0; i < 8; i++)
                #pragma unroll
                for (int j = 0; j < 4; j++) acc[i][j] = fmaf(a[i], bq[j], acc[i][j]);
        }
        // next iter's wzs write only touches wzs (not read in inner loop);
        // the sync after it protects As/Bs reuse.
    }
    float* pp = g_part + (((size_t)sp * BB + b) * CC) * J1;
    #pragma unroll
    for (int i = 0; i < 8; i++) {
        const int row = ty * 8 + i;
        #pragma unroll
        for (int j = 0; j < 4; j++) {
            const int jc = j0 + tx * 4 + j;
            if (jc < J1) pp[(size_t)row * J1 + jc] = acc[i][j];
        }
    }
}

// ---------------- per-k complex mix: build g_A ------------------------------
// grid (K, B); block 128 (= o)
__global__ __launch_bounds__(128) void k_f(const float* __restrict__ w0,
                                           const float* __restrict__ conv_w, int l) {
    const int k = blockIdx.x, b = blockIdx.y;
    const int o = threadIdx.x;
    __shared__ float xc[128], xs[128], x0v[128];
    {
        float sc = 0.f, ss = 0.f, s0 = 0.f;
        #pragma unroll
        for (int s = 0; s < NSPLIT; s++) {
            const float* pp = g_part + (((size_t)s * BB + b) * CC + o) * J1;
            sc += pp[k]; ss += pp[128 + k]; s0 += pp[256];
        }
        xc[o] = sc;
        xs[o] = -ss;      // x_s = -einsum(h, wbases_s)
        x0v[o] = s0;
    }
    __syncthreads();
    const float* wct = g_wct + (((size_t)l * KK + k) * CC) * CC + o;
    const float* wst = g_wst + (((size_t)l * KK + k) * CC) * CC + o;
    float fc = 0.f, fs = 0.f;
    #pragma unroll 8
    for (int i = 0; i < 128; i++) {
        const float wcv = wct[(size_t)i * CC], wsv = wst[(size_t)i * CC];
        const float cv = xc[i], sv = xs[i];
        fc = fmaf(cv, wcv, fc); fc = fmaf(-sv, wsv, fc);
        fs = fmaf(sv, wcv, fs); fs = fmaf(cv, wsv, fs);
    }
    float* Ar = g_A + ((size_t)b * CC + o) * JA;
    Ar[k] = 2.f * fc;
    Ar[128 + k] = -2.f * fs;
    if (k == 0) {
        float f0 = 0.f;
        const float* w0p = w0 + (size_t)l * CC * CC;
        for (int i = 0; i < 128; i++) f0 = fmaf(x0v[i], w0p[(size_t)i * CC + o], f0);
        Ar[256] = f0 * (1.0f / 8192.0f);
        const float* cw = conv_w + ((size_t)l * CC + o) * CC;
        for (int i = 0; i < 128; i++) Ar[257 + i] = cw[i];
        #pragma unroll
        for (int j = 385; j < JA; j++) Ar[j] = 0.f;
    }
}

// ---------------- G2: h' = A @ [bases_c; bases_s; mask; h] + conv_b, gelu ---
// grid (N/128, B); block (16,16); 128(o) x 128(x), 8x8 micro
__global__ __launch_bounds__(256) void k_gemm2(int cur, int nxt,
                                               const float* __restrict__ conv_b, int l) {
    __shared__ float As[8][128];  // [j][o]
    __shared__ float Bs[8][128];  // [j][x]
    const int xt = blockIdx.x, b = blockIdx.y;
    const int tx = threadIdx.x, ty = threadIdx.y;
    const int tid = ty * 16 + tx;
    const int x0 = xt * 128;
    const float* Ab = g_A + (size_t)b * CC * JA;
    const float* bases = g_bases + (size_t)b * J1 * NN;
    const float* hcur = g_h[cur] + (size_t)b * CC * NN;
    float acc[8][8];
    #pragma unroll
    for (int i = 0; i < 8; i++)
        #pragma unroll
        for (int j = 0; j < 8; j++) acc[i][j] = 0.f;

    const int ao = tid >> 1;
    const int ajj = (tid & 1) * 4;
    const int bjj = tid >> 5;
    const int bxx = (tid & 31) * 4;

    for (int j0 = 0; j0 < JA; j0 += 8) {
        float4 av = *(const float4*)(Ab + (size_t)ao * JA + j0 + ajj);
        As[ajj + 0][ao] = av.x; As[ajj + 1][ao] = av.y;
        As[ajj + 2][ao] = av.z; As[ajj + 3][ao] = av.w;
        const int jgl = j0 + bjj;
        float4 bv;
        if (jgl < J1)       bv = *(const float4*)(bases + (size_t)jgl * NN + x0 + bxx);
        else if (jgl < 385) bv = *(const float4*)(hcur + (size_t)(jgl - J1) * NN + x0 + bxx);
        else                bv = make_float4(0.f, 0.f, 0.f, 0.f);
        *(float4*)&Bs[bjj][bxx] = bv;
        __syncthreads();
        #pragma unroll
        for (int jj = 0; jj < 8; jj++) {
            float a[8], bw[8];
            *(float4*)&a[0]  = *(const float4*)&As[jj][ty * 8];
            *(float4*)&a[4]  = *(const float4*)&As[jj][ty * 8 + 4];
            *(float4*)&bw[0] = *(const float4*)&Bs[jj][tx * 8];
            *(float4*)&bw[4] = *(const float4*)&Bs[jj][tx * 8 + 4];
            #pragma unroll
            for (int i = 0; i < 8; i++)
                #pragma unroll
                for (int j = 0; j < 8; j++) acc[i][j] = fmaf(a[i], bw[j], acc[i][j]);
        }
        __syncthreads();
    }
    float* hout = g_h[nxt] + (size_t)b * CC * NN;
    #pragma unroll
    for (int i = 0; i < 8; i++) {
        const int o = ty * 8 + i;
        const float cb = conv_b[l * CC + o];
        float v[8];
        #pragma unroll
        for (int j = 0; j < 8; j++) {
            float t = acc[i][j] + cb;
            v[j] = (l < LL - 1) ? gelu_f(t) : t;
        }
        float* op = hout + (size_t)o * NN + x0 + tx * 8;
        *(float4*)op       = make_float4(v[0], v[1], v[2], v[3]);
        *(float4*)(op + 4) = make_float4(v[4], v[5], v[6], v[7]);
    }
}

// ---------------- final MLP: y = fc2(gelu(fc1(h^T))) ------------------------
// grid (N/128, B); block (16,16); tile 128(f) x 128(x)
__global__ __launch_bounds__(256) void k_final(const float* __restrict__ fc1_w,
                                               const float* __restrict__ fc1_b,
                                               const float* __restrict__ fc2_w,
                                               const float* __restrict__ fc2_b,
                                               float* __restrict__ out) {
    __shared__ float Hs[8][128];   // [c][x]
    __shared__ float Ws[8][128];   // [c][f]
    __shared__ float red[16][128];
    const int xt = blockIdx.x, b = blockIdx.y;
    const int tx = threadIdx.x, ty = threadIdx.y;
    const int tid = ty * 16 + tx;
    const int x0 = xt * 128;
    const float* h = g_h[0] + (size_t)b * CC * NN;   // after L=4 layers, h is in buffer 0
    float acc[8][8];
    #pragma unroll
    for (int i = 0; i < 8; i++)
        #pragma unroll
        for (int j = 0; j < 8; j++) acc[i][j] = 0.f;

    const int lcc = tid >> 5;
    const int lxx = (tid & 31) * 4;
    for (int c0 = 0; c0 < CC; c0 += 8) {
        *(float4*)&Hs[lcc][lxx] = *(const float4*)(h + (size_t)(c0 + lcc) * NN + x0 + lxx);
        *(float4*)&Ws[lcc][lxx] = *(const float4*)(fc1_w + (c0 + lcc) * 128 + lxx);
        __syncthreads();
        #pragma unroll
        for (int cc = 0; cc < 8; cc++) {
            float a[8], bw[8];
            *(float4*)&a[0]  = *(const float4*)&Ws[cc][ty * 8];
            *(float4*)&a[4]  = *(const float4*)&Ws[cc][ty * 8 + 4];
            *(float4*)&bw[0] = *(const float4*)&Hs[cc][tx * 8];
            *(float4*)&bw[4] = *(const float4*)&Hs[cc][tx * 8 + 4];
            #pragma unroll
            for (int i = 0; i < 8; i++)
                #pragma unroll
                for (int j = 0; j < 8; j++) acc[i][j] = fmaf(a[i], bw[j], acc[i][j]);
        }
        __syncthreads();
    }
    float yp[8];
    #pragma unroll
    for (int j = 0; j < 8; j++) yp[j] = 0.f;
    #pragma unroll
    for (int i = 0; i < 8; i++) {
        const int f = ty * 8 + i;
        const float b1 = fc1_b[f], w2 = fc2_w[f];
        #pragma unroll
        for (int j = 0; j < 8; j++) yp[j] = fmaf(w2, gelu_f(acc[i][j] + b1), yp[j]);
    }
    #pragma unroll
    for (int j = 0; j < 8; j++) red[ty][tx * 8 + j] = yp[j];
    __syncthreads();
    if (ty == 0) {
        #pragma unroll
        for (int j = 0; j < 8; j++) {
            float s = fc2_b[0];
            #pragma unroll
            for (int r = 0; r < 16; r++) s += red[r][tx * 8 + j];
            out[(size_t)b * NN + x0 + tx * 8 + j] = s;
        }
    }
}

// ---------------- launch -----------------------------------------------------
extern "C" void kernel_launch(void* const* d_in, const int* in_sizes, int n_in,
                              void* d_out, int out_size) {
    const float* x      = (const float*)d_in[0];
    const float* modes  = (const float*)d_in[1];
    const float* fc0_w  = (const float*)d_in[2];
    const float* fc0_b  = (const float*)d_in[3];
    const float* wc     = (const float*)d_in[4];
    const float* ws     = (const float*)d_in[5];
    const float* w0     = (const float*)d_in[6];
    const float* conv_w = (const float*)d_in[7];
    const float* conv_b = (const float*)d_in[8];
    const float* fc1_w  = (const float*)d_in[9];
    const float* fc1_b  = (const float*)d_in[10];
    const float* fc2_w  = (const float*)d_in[11];
    const float* fc2_b  = (const float*)d_in[12];
    float* out = (float*)d_out;

    k_wtrans<<<dim3(16, 128, 4), dim3(32, 8)>>>(wc, ws);
    k_pre<<<(BB * NN) / 256, 256>>>(x, modes, fc0_w, fc0_b);
    for (int l = 0; l < LL; l++) {
        const int cur = l & 1, nxt = cur ^ 1;
        k_gemm1<<<dim3(5, NSPLIT, BB), dim3(16, 16)>>>(cur);
        k_f<<<dim3(KK, BB), 128>>>(w0, conv_w, l);
        k_gemm2<<<dim3(NN / 128, BB), dim3(16, 16)>>>(cur, nxt, conv_b, l);
    }
    k_final<<<dim3(NN / 128, BB), dim3(16, 16)>>>(fc1_w, fc1_b, fc2_w, fc2_b, out);
}

// round 3
// speedup vs baseline: 1.0042x; 1.0042x over previous
#include <cuda_runtime.h>
#include <math.h>

#define BB 16
#define NN 8192
#define CC 128
#define KK 128
#define LL 4
#define J1 257          // 2K + 1 (cos rows, sin rows, mask row)
#define JA 392          // 385 (2K + 1 + C) padded to multiple of 8
#define NSPLIT 8

// ---------------- scratch (device globals; no allocation allowed) ----------
__device__ float g_bases[(size_t)BB * J1 * NN];          // [b][j][x]; j<128 cos, <256 sin, 256 mask
__device__ float g_wsz[BB * NN];                         // weights * size
__device__ float g_h[2][(size_t)BB * CC * NN];           // ping-pong h
__device__ float g_part[(size_t)NSPLIT * BB * CC * J1];  // split-x partials of G1
__device__ float g_A[(size_t)BB * CC * JA];              // [2f_c, -2f_s, f_0, conv_w, pad]
__device__ float g_wct[(size_t)LL * KK * CC * CC];       // wc/size transposed to [l][k][i][o]
__device__ float g_wst[(size_t)LL * KK * CC * CC];

__device__ __forceinline__ float gelu_f(float v) {
    return 0.5f * v * (1.0f + erff(v * 0.70710678118654752f));
}

// ---------------- weight transpose: wc/ws (l,i,o,k) -> (l,k,i,o), /size ----
__global__ void k_wtrans(const float* __restrict__ wc, const float* __restrict__ ws) {
    __shared__ float sm[32][33];
    const int tile = blockIdx.x;              // 16 tiles: (o-tile, k-tile)
    const int o0 = (tile >> 2) * 32, k0 = (tile & 3) * 32;
    const int i = blockIdx.y, l = blockIdx.z;
    const float scale = 1.0f / 8192.0f;
    for (int w = 0; w < 2; w++) {
        const float* src = w ? ws : wc;
        float* dst = w ? g_wst : g_wct;
        #pragma unroll
        for (int s = 0; s < 4; s++) {
            int oo = threadIdx.y + 8 * s, kk = threadIdx.x;
            sm[oo][kk] = src[(((size_t)l * CC + i) * CC + (o0 + oo)) * KK + (k0 + kk)] * scale;
        }
        __syncthreads();
        #pragma unroll
        for (int s = 0; s < 4; s++) {
            int kk = threadIdx.y + 8 * s, oo = threadIdx.x;
            dst[(((size_t)l * KK + (k0 + kk)) * CC + i) * CC + (o0 + oo)] = sm[oo][kk];
        }
        __syncthreads();
    }
}

// ---------------- precompute bases, wsz, h0 = fc0(x) ------------------------
__global__ __launch_bounds__(256) void k_pre(const float* __restrict__ xin,
                                             const float* __restrict__ modes,
                                             const float* __restrict__ fc0_w,
                                             const float* __restrict__ fc0_b) {
    __shared__ float sm_modes[256];
    __shared__ float sm_w[384];
    __shared__ float sm_b[128];
    const int t = threadIdx.x;
    sm_modes[t] = modes[t];
    sm_w[t] = fc0_w[t];
    if (t < 128) { sm_w[256 + t] = fc0_w[256 + t]; sm_b[t] = fc0_b[t]; }
    __syncthreads();

    const int gid = blockIdx.x * 256 + t;     // over B*N
    const int b = gid / NN, xx = gid - b * NN;
    const float* xr = xin + (size_t)gid * 7;
    const float i0 = xr[0], i1 = xr[1], i2 = xr[2];
    const float d0 = xr[3], d1 = xr[4], wgt = xr[5], msk = xr[6];

    g_wsz[gid] = wgt * (float)NN;
    float* bb = g_bases + (size_t)b * J1 * NN + xx;
    bb[(size_t)256 * NN] = msk;
    #pragma unroll 4
    for (int k = 0; k < KK; k++) {
        float tt = fmaf(d0, sm_modes[2 * k], d1 * sm_modes[2 * k + 1]);
        float s, c;
        sincosf(tt, &s, &c);
        bb[(size_t)k * NN] = c * msk;
        bb[(size_t)(128 + k) * NN] = s * msk;
    }
    float* hh = g_h[0] + (size_t)b * CC * NN + xx;
    #pragma unroll 4
    for (int c = 0; c < CC; c++) {
        float v = sm_b[c];
        v = fmaf(i0, sm_w[c], v);
        v = fmaf(i1, sm_w[128 + c], v);
        v = fmaf(i2, sm_w[256 + c], v);
        hh[(size_t)c * NN] = v;
    }
}

// ---------------- G1: partials[s][b][i][j] = sum_x h*wsz * bases[j] --------
// grid (jtile=5, split=8, b=16); block (16,16); 128(i) x 64(j) tile, 8x4 micro
__global__ __launch_bounds__(256) void k_gemm1(int cur) {
    __shared__ float As[32][128];   // [x][i]
    __shared__ float Bs[32][64];    // [x][j] (scaled by wsz)
    __shared__ float wzs[32];
    const int jt = blockIdx.x, sp = blockIdx.y, b = blockIdx.z;
    const int tx = threadIdx.x, ty = threadIdx.y;
    const int tid = ty * 16 + tx;
    const float* hsrc = g_h[cur] + (size_t)b * CC * NN;
    const float* bsrc = g_bases + (size_t)b * J1 * NN;
    const int j0 = jt * 64;
    float acc[8][4];
    #pragma unroll
    for (int i = 0; i < 8; i++)
        #pragma unroll
        for (int j = 0; j < 4; j++) acc[i][j] = 0.f;

    const int ai = tid >> 1;
    const int axs = (tid & 1) * 16;
    const int bjj = tid >> 2;
    const int bxs = (tid & 3) * 8;
    const int jg = j0 + bjj;

    const int xbeg = sp * (NN / NSPLIT), xend = xbeg + (NN / NSPLIT);
    for (int x0 = xbeg; x0 < xend; x0 += 32) {
        if (tid < 32) wzs[tid] = g_wsz[b * NN + x0 + tid];
        __syncthreads();
        {   // A tile: h rows
            const float4* hp = (const float4*)(hsrc + (size_t)ai * NN + x0 + axs);
            #pragma unroll
            for (int u = 0; u < 4; u++) {
                float4 v = hp[u];
                As[axs + u * 4 + 0][ai] = v.x;
                As[axs + u * 4 + 1][ai] = v.y;
                As[axs + u * 4 + 2][ai] = v.z;
                As[axs + u * 4 + 3][ai] = v.w;
            }
        }
        {   // B tile: bases rows * wsz
            float bv[8];
            if (jg < J1) {
                const float* bp = bsrc + (size_t)jg * NN + x0 + bxs;
                #pragma unroll
                for (int u = 0; u < 8; u++) bv[u] = bp[u] * wzs[bxs + u];
            } else {
                #pragma unroll
                for (int u = 0; u < 8; u++) bv[u] = 0.f;
            }
            #pragma unroll
            for (int u = 0; u < 8; u++) Bs[bxs + u][bjj] = bv[u];
        }
        __syncthreads();
        #pragma unroll
        for (int x = 0; x < 32; x++) {
            float a[8], bq[4];
            *(float4*)&a[0] = *(const float4*)&As[x][ty * 8];
            *(float4*)&a[4] = *(const float4*)&As[x][ty * 8 + 4];
            *(float4*)&bq[0] = *(const float4*)&Bs[x][tx * 4];
            #pragma unroll
            for (int i = 0; i < 8; i++)
                #pragma unroll
                for (int j = 0; j < 4; j++) acc[i][j] = fmaf(a[i], bq[j], acc[i][j]);
        }
        // next iter's wzs write only touches wzs (not read in inner loop);
        // the sync after it protects As/Bs reuse.
    }
    float* pp = g_part + (((size_t)sp * BB + b) * CC) * J1;
    #pragma unroll
    for (int i = 0; i < 8; i++) {
        const int row = ty * 8 + i;
        #pragma unroll
        for (int j = 0; j < 4; j++) {
            const int jc = j0 + tx * 4 + j;
            if (jc < J1) pp[(size_t)row * J1 + jc] = acc[i][j];
        }
    }
}

// ---------------- per-k complex mix: build g_A ------------------------------
// grid (K, B); block 128 (= o)
__global__ __launch_bounds__(128) void k_f(const float* __restrict__ w0,
                                           const float* __restrict__ conv_w, int l) {
    const int k = blockIdx.x, b = blockIdx.y;
    const int o = threadIdx.x;
    __shared__ float xc[128], xs[128], x0v[128];
    {
        float sc = 0.f, ss = 0.f, s0 = 0.f;
        #pragma unroll
        for (int s = 0; s < NSPLIT; s++) {
            const float* pp = g_part + (((size_t)s * BB + b) * CC + o) * J1;
            sc += pp[k]; ss += pp[128 + k]; s0 += pp[256];
        }
        xc[o] = sc;
        xs[o] = -ss;      // x_s = -einsum(h, wbases_s)
        x0v[o] = s0;
    }
    __syncthreads();
    const float* wct = g_wct + (((size_t)l * KK + k) * CC) * CC + o;
    const float* wst = g_wst + (((size_t)l * KK + k) * CC) * CC + o;
    float fc = 0.f, fs = 0.f;
    #pragma unroll 8
    for (int i = 0; i < 128; i++) {
        const float wcv = wct[(size_t)i * CC], wsv = wst[(size_t)i * CC];
        const float cv = xc[i], sv = xs[i];
        fc = fmaf(cv, wcv, fc); fc = fmaf(-sv, wsv, fc);
        fs = fmaf(sv, wcv, fs); fs = fmaf(cv, wsv, fs);
    }
    float* Ar = g_A + ((size_t)b * CC + o) * JA;
    Ar[k] = 2.f * fc;
    Ar[128 + k] = -2.f * fs;
    if (k == 0) {
        float f0 = 0.f;
        const float* w0p = w0 + (size_t)l * CC * CC;
        for (int i = 0; i < 128; i++) f0 = fmaf(x0v[i], w0p[(size_t)i * CC + o], f0);
        Ar[256] = f0 * (1.0f / 8192.0f);
        const float* cw = conv_w + ((size_t)l * CC + o) * CC;
        for (int i = 0; i < 128; i++) Ar[257 + i] = cw[i];
        #pragma unroll
        for (int j = 385; j < JA; j++) Ar[j] = 0.f;
    }
}

// ---------------- G2: h' = A @ [bases_c; bases_s; mask; h] + conv_b, gelu ---
// grid (N/128, B); block (16,16); 128(o) x 128(x), 8x8 micro
__global__ __launch_bounds__(256) void k_gemm2(int cur, int nxt,
                                               const float* __restrict__ conv_b, int l) {
    __shared__ float As[8][128];  // [j][o]
    __shared__ float Bs[8][128];  // [j][x]
    const int xt = blockIdx.x, b = blockIdx.y;
    const int tx = threadIdx.x, ty = threadIdx.y;
    const int tid = ty * 16 + tx;
    const int x0 = xt * 128;
    const float* Ab = g_A + (size_t)b * CC * JA;
    const float* bases = g_bases + (size_t)b * J1 * NN;
    const float* hcur = g_h[cur] + (size_t)b * CC * NN;
    float acc[8][8];
    #pragma unroll
    for (int i = 0; i < 8; i++)
        #pragma unroll
        for (int j = 0; j < 8; j++) acc[i][j] = 0.f;

    const int ao = tid >> 1;
    const int ajj = (tid & 1) * 4;
    const int bjj = tid >> 5;
    const int bxx = (tid & 31) * 4;

    for (int j0 = 0; j0 < JA; j0 += 8) {
        float4 av = *(const float4*)(Ab + (size_t)ao * JA + j0 + ajj);
        As[ajj + 0][ao] = av.x; As[ajj + 1][ao] = av.y;
        As[ajj + 2][ao] = av.z; As[ajj + 3][ao] = av.w;
        const int jgl = j0 + bjj;
        float4 bv;
        if (jgl < J1)       bv = *(const float4*)(bases + (size_t)jgl * NN + x0 + bxx);
        else if (jgl < 385) bv = *(const float4*)(hcur + (size_t)(jgl - J1) * NN + x0 + bxx);
        else                bv = make_float4(0.f, 0.f, 0.f, 0.f);
        *(float4*)&Bs[bjj][bxx] = bv;
        __syncthreads();
        #pragma unroll
        for (int jj = 0; jj < 8; jj++) {
            float a[8], bw[8];
            *(float4*)&a[0]  = *(const float4*)&As[jj][ty * 8];
            *(float4*)&a[4]  = *(const float4*)&As[jj][ty * 8 + 4];
            *(float4*)&bw[0] = *(const float4*)&Bs[jj][tx * 8];
            *(float4*)&bw[4] = *(const float4*)&Bs[jj][tx * 8 + 4];
            #pragma unroll
            for (int i = 0; i < 8; i++)
                #pragma unroll
                for (int j = 0; j < 8; j++) acc[i][j] = fmaf(a[i], bw[j], acc[i][j]);
        }
        __syncthreads();
    }
    float* hout = g_h[nxt] + (size_t)b * CC * NN;
    #pragma unroll
    for (int i = 0; i < 8; i++) {
        const int o = ty * 8 + i;
        const float cb = conv_b[l * CC + o];
        float v[8];
        #pragma unroll
        for (int j = 0; j < 8; j++) {
            float t = acc[i][j] + cb;
            v[j] = (l < LL - 1) ? gelu_f(t) : t;
        }
        float* op = hout + (size_t)o * NN + x0 + tx * 8;
        *(float4*)op       = make_float4(v[0], v[1], v[2], v[3]);
        *(float4*)(op + 4) = make_float4(v[4], v[5], v[6], v[7]);
    }
}

// ---------------- final MLP: y = fc2(gelu(fc1(h^T))) ------------------------
// grid (N/128, B); block (16,16); tile 128(f) x 128(x)
__global__ __launch_bounds__(256) void k_final(const float* __restrict__ fc1_w,
                                               const float* __restrict__ fc1_b,
                                               const float* __restrict__ fc2_w,
                                               const float* __restrict__ fc2_b,
                                               float* __restrict__ out) {
    __shared__ float Hs[8][128];   // [c][x]
    __shared__ float Ws[8][128];   // [c][f]
    __shared__ float red[16][128];
    const int xt = blockIdx.x, b = blockIdx.y;
    const int tx = threadIdx.x, ty = threadIdx.y;
    const int tid = ty * 16 + tx;
    const int x0 = xt * 128;
    const float* h = g_h[0] + (size_t)b * CC * NN;   // after L=4 layers, h is in buffer 0
    float acc[8][8];
    #pragma unroll
    for (int i = 0; i < 8; i++)
        #pragma unroll
        for (int j = 0; j < 8; j++) acc[i][j] = 0.f;

    const int lcc = tid >> 5;
    const int lxx = (tid & 31) * 4;
    for (int c0 = 0; c0 < CC; c0 += 8) {
        *(float4*)&Hs[lcc][lxx] = *(const float4*)(h + (size_t)(c0 + lcc) * NN + x0 + lxx);
        *(float4*)&Ws[lcc][lxx] = *(const float4*)(fc1_w + (c0 + lcc) * 128 + lxx);
        __syncthreads();
        #pragma unroll
        for (int cc = 0; cc < 8; cc++) {
            float a[8], bw[8];
            *(float4*)&a[0]  = *(const float4*)&Ws[cc][ty * 8];
            *(float4*)&a[4]  = *(const float4*)&Ws[cc][ty * 8 + 4];
            *(float4*)&bw[0] = *(const float4*)&Hs[cc][tx * 8];
            *(float4*)&bw[4] = *(const float4*)&Hs[cc][tx * 8 + 4];
            #pragma unroll
            for (int i = 0; i < 8; i++)
                #pragma unroll
                for (int j = 0; j < 8; j++) acc[i][j] = fmaf(a[i], bw[j], acc[i][j]);
        }
        __syncthreads();
    }
    float yp[8];
    #pragma unroll
    for (int j = 0; j < 8; j++) yp[j] = 0.f;
    #pragma unroll
    for (int i = 0; i < 8; i++) {
        const int f = ty * 8 + i;
        const float b1 = fc1_b[f], w2 = fc2_w[f];
        #pragma unroll
        for (int j = 0; j < 8; j++) yp[j] = fmaf(w2, gelu_f(acc[i][j] + b1), yp[j]);
    }
    #pragma unroll
    for (int j = 0; j < 8; j++) red[ty][tx * 8 + j] = yp[j];
    __syncthreads();
    if (ty == 0) {
        #pragma unroll
        for (int j = 0; j < 8; j++) {
            float s = fc2_b[0];
            #pragma unroll
            for (int r = 0; r < 16; r++) s += red[r][tx * 8 + j];
            out[(size_t)b * NN + x0 + tx * 8 + j] = s;
        }
    }
}

// ---------------- launch -----------------------------------------------------
extern "C" void kernel_launch(void* const* d_in, const int* in_sizes, int n_in,
                              void* d_out, int out_size) {
    const float* x      = (const float*)d_in[0];
    const float* modes  = (const float*)d_in[1];
    const float* fc0_w  = (const float*)d_in[2];
    const float* fc0_b  = (const float*)d_in[3];
    const float* wc     = (const float*)d_in[4];
    const float* ws     = (const float*)d_in[5];
    const float* w0     = (const float*)d_in[6];
    const float* conv_w = (const float*)d_in[7];
    const float* conv_b = (const float*)d_in[8];
    const float* fc1_w  = (const float*)d_in[9];
    const float* fc1_b  = (const float*)d_in[10];
    const float* fc2_w  = (const float*)d_in[11];
    const float* fc2_b  = (const float*)d_in[12];
    float* out = (float*)d_out;

    k_wtrans<<<dim3(16, 128, 4), dim3(32, 8)>>>(wc, ws);
    k_pre<<<(BB * NN) / 256, 256>>>(x, modes, fc0_w, fc0_b);
    for (int l = 0; l < LL; l++) {
        const int cur = l & 1, nxt = cur ^ 1;
        k_gemm1<<<dim3(5, NSPLIT, BB), dim3(16, 16)>>>(cur);
        k_f<<<dim3(KK, BB), 128>>>(w0, conv_w, l);
        k_gemm2<<<dim3(NN / 128, BB), dim3(16, 16)>>>(cur, nxt, conv_b, l);
    }
    k_final<<<dim3(NN / 128, BB), dim3(16, 16)>>>(fc1_w, fc1_b, fc2_w, fc2_b, out);
}

// round 4
// speedup vs baseline: 1.1057x; 1.1010x over previous
#include <cuda_runtime.h>
#include <math.h>

#define BB 16
#define NN 8192
#define CC 128
#define KK 128
#define LL 4
#define J1 257          // 2K + 1 rows in g_bases (cos, sin, mask)
#define JP 256          // G1 output columns (cos+sin only; mask handled separately)
#define JA 392          // 385 (2K + 1 + C) padded to multiple of 8
#define NSPLIT 8

typedef unsigned long long ull;

// ---------------- f32x2 helpers ---------------------------------------------
__device__ __forceinline__ ull pk2(float x) {
    ull r; asm("mov.b64 %0,{%1,%1};" : "=l"(r) : "f"(x)); return r;
}
__device__ __forceinline__ void fma2(ull& d, ull a, ull b) {
    asm("fma.rn.f32x2 %0,%1,%2,%0;" : "+l"(d) : "l"(a), "l"(b));
}
__device__ __forceinline__ float2 up2(ull v) {
    float2 f; asm("mov.b64 {%0,%1},%2;" : "=f"(f.x), "=f"(f.y) : "l"(v)); return f;
}

// ---------------- scratch (device globals; no allocation allowed) ----------
__device__ float g_bases[(size_t)BB * J1 * NN];          // [b][j][x]
__device__ float g_wsz[BB * NN];                         // weights * size
__device__ float g_wm[BB * NN];                          // weights * size * mask
__device__ float g_h[2][(size_t)BB * CC * NN];           // ping-pong h
__device__ float g_part[(size_t)NSPLIT * BB * CC * JP];  // split-x partials of G1
__device__ float g_x0[BB * CC];                          // x_0[b][i]
__device__ float g_A[(size_t)BB * CC * JA];              // [2f_c, -2f_s, f_0, conv_w, pad]
__device__ float g_wct[(size_t)LL * KK * CC * CC];       // wc/size -> [l][k][i][o]
__device__ float g_wst[(size_t)LL * KK * CC * CC];

__device__ __forceinline__ float gelu_f(float v) {
    return 0.5f * v * (1.0f + erff(v * 0.70710678118654752f));
}

// ---------------- weight transpose: wc/ws (l,i,o,k) -> (l,k,i,o), /size ----
__global__ void k_wtrans(const float* __restrict__ wc, const float* __restrict__ ws) {
    __shared__ float sm[32][33];
    const int tile = blockIdx.x;              // 16 tiles: (o-tile, k-tile)
    const int o0 = (tile >> 2) * 32, k0 = (tile & 3) * 32;
    const int i = blockIdx.y, l = blockIdx.z;
    const float scale = 1.0f / 8192.0f;
    for (int w = 0; w < 2; w++) {
        const float* src = w ? ws : wc;
        float* dst = w ? g_wst : g_wct;
        #pragma unroll
        for (int s = 0; s < 4; s++) {
            int oo = threadIdx.y + 8 * s, kk = threadIdx.x;
            sm[oo][kk] = src[(((size_t)l * CC + i) * CC + (o0 + oo)) * KK + (k0 + kk)] * scale;
        }
        __syncthreads();
        #pragma unroll
        for (int s = 0; s < 4; s++) {
            int kk = threadIdx.y + 8 * s, oo = threadIdx.x;
            dst[(((size_t)l * KK + (k0 + kk)) * CC + i) * CC + (o0 + oo)] = sm[oo][kk];
        }
        __syncthreads();
    }
}

// ---------------- precompute bases, wsz, wm, h0 = fc0(x) ---------------------
__global__ __launch_bounds__(256) void k_pre(const float* __restrict__ xin,
                                             const float* __restrict__ modes,
                                             const float* __restrict__ fc0_w,
                                             const float* __restrict__ fc0_b) {
    __shared__ float sm_modes[256];
    __shared__ float sm_w[384];
    __shared__ float sm_b[128];
    const int t = threadIdx.x;
    sm_modes[t] = modes[t];
    sm_w[t] = fc0_w[t];
    if (t < 128) { sm_w[256 + t] = fc0_w[256 + t]; sm_b[t] = fc0_b[t]; }
    __syncthreads();

    const int gid = blockIdx.x * 256 + t;     // over B*N
    const int b = gid / NN, xx = gid - b * NN;
    const float* xr = xin + (size_t)gid * 7;
    const float i0 = xr[0], i1 = xr[1], i2 = xr[2];
    const float d0 = xr[3], d1 = xr[4], wgt = xr[5], msk = xr[6];

    const float wsz = wgt * (float)NN;
    g_wsz[gid] = wsz;
    g_wm[gid] = wsz * msk;
    float* bb = g_bases + (size_t)b * J1 * NN + xx;
    bb[(size_t)256 * NN] = msk;
    #pragma unroll 4
    for (int k = 0; k < KK; k++) {
        float tt = fmaf(d0, sm_modes[2 * k], d1 * sm_modes[2 * k + 1]);
        float s, c;
        sincosf(tt, &s, &c);
        bb[(size_t)k * NN] = c * msk;
        bb[(size_t)(128 + k) * NN] = s * msk;
    }
    float* hh = g_h[0] + (size_t)b * CC * NN + xx;
    #pragma unroll 4
    for (int c = 0; c < CC; c++) {
        float v = sm_b[c];
        v = fmaf(i0, sm_w[c], v);
        v = fmaf(i1, sm_w[128 + c], v);
        v = fmaf(i2, sm_w[256 + c], v);
        hh[(size_t)c * NN] = v;
    }
}

// ---------------- G1: partials[s][b][i][j] = sum_x h*wsz * bases[j] --------
// grid (jtile=4, split=8, b=16); block (16,16); 128(i) x 64(j) tile,
// ffma2 micro-tile: 4 i-pairs x 4 j per thread
__global__ __launch_bounds__(256) void k_gemm1(int cur) {
    __align__(16) __shared__ float As[32][128];   // [x][i]
    __align__(16) __shared__ float Bs[32][64];    // [x][j] (scaled by wsz)
    __shared__ float wzs[32];
    const int jt = blockIdx.x, sp = blockIdx.y, b = blockIdx.z;
    const int tx = threadIdx.x, ty = threadIdx.y;
    const int tid = ty * 16 + tx;
    const float* hsrc = g_h[cur] + (size_t)b * CC * NN;
    const float* bsrc = g_bases + (size_t)b * J1 * NN;
    const int j0 = jt * 64;
    ull acc2[4][4] = {};

    const int ai = tid >> 1;
    const int axs = (tid & 1) * 16;
    const int bjj = tid >> 2;
    const int bxs = (tid & 3) * 8;
    const int jg = j0 + bjj;                  // always < 256

    const int xbeg = sp * (NN / NSPLIT), xend = xbeg + (NN / NSPLIT);
    for (int x0 = xbeg; x0 < xend; x0 += 32) {
        if (tid < 32) wzs[tid] = g_wsz[b * NN + x0 + tid];
        __syncthreads();
        {   // A tile: h rows
            const float4* hp = (const float4*)(hsrc + (size_t)ai * NN + x0 + axs);
            #pragma unroll
            for (int u = 0; u < 4; u++) {
                float4 v = hp[u];
                As[axs + u * 4 + 0][ai] = v.x;
                As[axs + u * 4 + 1][ai] = v.y;
                As[axs + u * 4 + 2][ai] = v.z;
                As[axs + u * 4 + 3][ai] = v.w;
            }
        }
        {   // B tile: bases rows * wsz
            const float* bp = bsrc + (size_t)jg * NN + x0 + bxs;
            float bv[8];
            #pragma unroll
            for (int u = 0; u < 8; u++) bv[u] = bp[u] * wzs[bxs + u];
            #pragma unroll
            for (int u = 0; u < 8; u++) Bs[bxs + u][bjj] = bv[u];
        }
        __syncthreads();
        #pragma unroll
        for (int x = 0; x < 32; x++) {
            const ull* ap = (const ull*)&As[x][ty * 8];
            ull a2[4];
            #pragma unroll
            for (int p = 0; p < 4; p++) a2[p] = ap[p];
            float4 bq = *(const float4*)&Bs[x][tx * 4];
            ull b2[4] = { pk2(bq.x), pk2(bq.y), pk2(bq.z), pk2(bq.w) };
            #pragma unroll
            for (int ii = 0; ii < 4; ii++)
                #pragma unroll
                for (int j = 0; j < 4; j++) fma2(acc2[ii][j], a2[ii], b2[j]);
        }
        // next iter's wzs write only touches wzs (not read in inner loop);
        // the sync after it protects As/Bs reuse.
    }
    float* pp = g_part + (((size_t)sp * BB + b) * CC) * JP;
    #pragma unroll
    for (int ii = 0; ii < 4; ii++) {
        const int r0 = ty * 8 + ii * 2;
        float2 f0 = up2(acc2[ii][0]), f1 = up2(acc2[ii][1]);
        float2 f2 = up2(acc2[ii][2]), f3 = up2(acc2[ii][3]);
        *(float4*)(pp + (size_t)r0 * JP + j0 + tx * 4)       = make_float4(f0.x, f1.x, f2.x, f3.x);
        *(float4*)(pp + (size_t)(r0 + 1) * JP + j0 + tx * 4) = make_float4(f0.y, f1.y, f2.y, f3.y);
    }
}

// ---------------- x_0[b][i] = sum_x h * wsz * mask ---------------------------
__global__ __launch_bounds__(256) void k_x0(int cur) {
    const int b = blockIdx.x;
    const int i = blockIdx.y * 8 + (threadIdx.x >> 5);
    const int lane = threadIdx.x & 31;
    const float4* hp = (const float4*)(g_h[cur] + ((size_t)b * CC + i) * NN);
    const float4* wp = (const float4*)(g_wm + (size_t)b * NN);
    float s = 0.f;
    for (int t = lane; t < NN / 4; t += 32) {
        float4 h4 = hp[t], w4 = wp[t];
        s = fmaf(h4.x, w4.x, s);
        s = fmaf(h4.y, w4.y, s);
        s = fmaf(h4.z, w4.z, s);
        s = fmaf(h4.w, w4.w, s);
    }
    #pragma unroll
    for (int off = 16; off; off >>= 1) s += __shfl_xor_sync(0xffffffffu, s, off);
    if (!lane) g_x0[b * CC + i] = s;
}

// ---------------- f_0 + conv rows of g_A -------------------------------------
__global__ __launch_bounds__(128) void k_f0(const float* __restrict__ w0,
                                            const float* __restrict__ conv_w, int l) {
    const int b = blockIdx.x, o = threadIdx.x;
    __shared__ float x0s[128];
    x0s[o] = g_x0[b * CC + o];
    __syncthreads();
    float f0 = 0.f;
    const float* w0p = w0 + (size_t)l * CC * CC;
    #pragma unroll 8
    for (int i = 0; i < 128; i++) f0 = fmaf(x0s[i], w0p[(size_t)i * CC + o], f0);
    float* Ar = g_A + ((size_t)b * CC + o) * JA;
    Ar[256] = f0 * (1.0f / 8192.0f);
    const float* cw = conv_w + ((size_t)(l * CC) + o) * CC;
    #pragma unroll 8
    for (int i = 0; i < 128; i++) Ar[257 + i] = cw[i];
    #pragma unroll
    for (int j = 385; j < JA; j++) Ar[j] = 0.f;
}

// ---------------- per-k complex mix: g_A rows [2f_c, -2f_s] ------------------
// grid (K, 2); block 128 (= o); weights reused across 8 batches, ffma2.
__global__ __launch_bounds__(128) void k_fmix(int l) {
    const int k = blockIdx.x;
    const int bh = blockIdx.y * 8;
    const int t = threadIdx.x;
    __align__(16) __shared__ float xc_s[128][8];
    __align__(16) __shared__ float xs_s[128][8];
    #pragma unroll
    for (int b = 0; b < 8; b++) {
        float sc = 0.f, ss = 0.f;
        #pragma unroll
        for (int s = 0; s < NSPLIT; s++) {
            const float* pp = g_part + (((size_t)s * BB + bh + b) * CC + t) * JP;
            sc += pp[k];
            ss += pp[128 + k];
        }
        xc_s[t][b] = sc;
        xs_s[t][b] = -ss;     // x_s = -einsum(h, wbases_s)
    }
    __syncthreads();
    ull fc2[4] = {}, fs2[4] = {};
    const float* wcp = g_wct + ((size_t)(l * KK + k)) * CC * CC + t;
    const float* wsp = g_wst + ((size_t)(l * KK + k)) * CC * CC + t;
    #pragma unroll 4
    for (int i = 0; i < 128; i++) {
        const float wcv = wcp[(size_t)i * CC], wsv = wsp[(size_t)i * CC];
        const ull wc2 = pk2(wcv), ws2 = pk2(wsv), wsn2 = pk2(-wsv);
        #pragma unroll
        for (int p = 0; p < 4; p++) {
            const ull xc2 = *(const ull*)&xc_s[i][2 * p];
            const ull xs2 = *(const ull*)&xs_s[i][2 * p];
            fma2(fc2[p], xc2, wc2);   // f_c += x_c*Wc
            fma2(fc2[p], xs2, wsn2);  // f_c -= x_s*Ws
            fma2(fs2[p], xs2, wc2);   // f_s += x_s*Wc
            fma2(fs2[p], xc2, ws2);   // f_s += x_c*Ws
        }
    }
    #pragma unroll
    for (int p = 0; p < 4; p++) {
        float2 c = up2(fc2[p]), s = up2(fs2[p]);
        const int b0 = bh + 2 * p;
        float* A0 = g_A + ((size_t)b0 * CC + t) * JA;
        float* A1 = g_A + ((size_t)(b0 + 1) * CC + t) * JA;
        A0[k] = 2.f * c.x;  A0[128 + k] = -2.f * s.x;
        A1[k] = 2.f * c.y;  A1[128 + k] = -2.f * s.y;
    }
}

// ---------------- G2: h' = A @ [bases; h] + conv_b, gelu ---------------------
// grid (N/128, B); block (16,16); 128(o) x 128(x), ffma2: 4 o-pairs x 8 x
__global__ __launch_bounds__(256) void k_gemm2(int cur, int nxt,
                                               const float* __restrict__ conv_b, int l) {
    __align__(16) __shared__ float As[8][128];  // [j][o]
    __align__(16) __shared__ float Bs[8][128];  // [j][x]
    const int xt = blockIdx.x, b = blockIdx.y;
    const int tx = threadIdx.x, ty = threadIdx.y;
    const int tid = ty * 16 + tx;
    const int x0 = xt * 128;
    const float* Ab = g_A + (size_t)b * CC * JA;
    const float* bases = g_bases + (size_t)b * J1 * NN;
    const float* hcur = g_h[cur] + (size_t)b * CC * NN;
    ull acc2[4][8] = {};

    const int ao = tid >> 1;
    const int ajj = (tid & 1) * 4;
    const int bjj = tid >> 5;
    const int bxx = (tid & 31) * 4;

    for (int j0 = 0; j0 < JA; j0 += 8) {
        float4 av = *(const float4*)(Ab + (size_t)ao * JA + j0 + ajj);
        As[ajj + 0][ao] = av.x; As[ajj + 1][ao] = av.y;
        As[ajj + 2][ao] = av.z; As[ajj + 3][ao] = av.w;
        const int jgl = j0 + bjj;
        float4 bv;
        if (jgl < J1)       bv = *(const float4*)(bases + (size_t)jgl * NN + x0 + bxx);
        else if (jgl < 385) bv = *(const float4*)(hcur + (size_t)(jgl - J1) * NN + x0 + bxx);
        else                bv = make_float4(0.f, 0.f, 0.f, 0.f);
        *(float4*)&Bs[bjj][bxx] = bv;
        __syncthreads();
        #pragma unroll
        for (int jj = 0; jj < 8; jj++) {
            const ull* ap = (const ull*)&As[jj][ty * 8];
            ull a2[4];
            #pragma unroll
            for (int p = 0; p < 4; p++) a2[p] = ap[p];
            float4 bw0 = *(const float4*)&Bs[jj][tx * 8];
            float4 bw1 = *(const float4*)&Bs[jj][tx * 8 + 4];
            ull b2[8] = { pk2(bw0.x), pk2(bw0.y), pk2(bw0.z), pk2(bw0.w),
                          pk2(bw1.x), pk2(bw1.y), pk2(bw1.z), pk2(bw1.w) };
            #pragma unroll
            for (int ii = 0; ii < 4; ii++)
                #pragma unroll
                for (int j = 0; j < 8; j++) fma2(acc2[ii][j], a2[ii], b2[j]);
        }
        __syncthreads();
    }
    float* hout = g_h[nxt] + (size_t)b * CC * NN;
    #pragma unroll
    for (int ii = 0; ii < 4; ii++) {
        const int o0 = ty * 8 + ii * 2;
        const float cb0 = conv_b[l * CC + o0];
        const float cb1 = conv_b[l * CC + o0 + 1];
        float v0[8], v1[8];
        #pragma unroll
        for (int j = 0; j < 8; j++) {
            float2 f = up2(acc2[ii][j]);
            float t0 = f.x + cb0, t1 = f.y + cb1;
            v0[j] = (l < LL - 1) ? gelu_f(t0) : t0;
            v1[j] = (l < LL - 1) ? gelu_f(t1) : t1;
        }
        float* op0 = hout + (size_t)o0 * NN + x0 + tx * 8;
        float* op1 = hout + (size_t)(o0 + 1) * NN + x0 + tx * 8;
        *(float4*)op0       = make_float4(v0[0], v0[1], v0[2], v0[3]);
        *(float4*)(op0 + 4) = make_float4(v0[4], v0[5], v0[6], v0[7]);
        *(float4*)op1       = make_float4(v1[0], v1[1], v1[2], v1[3]);
        *(float4*)(op1 + 4) = make_float4(v1[4], v1[5], v1[6], v1[7]);
    }
}

// ---------------- final MLP: y = fc2(gelu(fc1(h^T))) -------------------------
// grid (N/128, B); block (16,16); tile 128(f) x 128(x), ffma2
__global__ __launch_bounds__(256) void k_final(const float* __restrict__ fc1_w,
                                               const float* __restrict__ fc1_b,
                                               const float* __restrict__ fc2_w,
                                               const float* __restrict__ fc2_b,
                                               float* __restrict__ out) {
    __align__(16) __shared__ float Hs[8][128];   // [c][x]
    __align__(16) __shared__ float Ws[8][128];   // [c][f]
    __shared__ float red[16][128];
    const int xt = blockIdx.x, b = blockIdx.y;
    const int tx = threadIdx.x, ty = threadIdx.y;
    const int tid = ty * 16 + tx;
    const int x0 = xt * 128;
    const float* h = g_h[0] + (size_t)b * CC * NN;   // after L=4 layers, h is in buffer 0
    ull acc2[4][8] = {};

    const int lcc = tid >> 5;
    const int lxx = (tid & 31) * 4;
    for (int c0 = 0; c0 < CC; c0 += 8) {
        *(float4*)&Hs[lcc][lxx] = *(const float4*)(h + (size_t)(c0 + lcc) * NN + x0 + lxx);
        *(float4*)&Ws[lcc][lxx] = *(const float4*)(fc1_w + (c0 + lcc) * 128 + lxx);
        __syncthreads();
        #pragma unroll
        for (int cc = 0; cc < 8; cc++) {
            const ull* ap = (const ull*)&Ws[cc][ty * 8];
            ull a2[4];
            #pragma unroll
            for (int p = 0; p < 4; p++) a2[p] = ap[p];
            float4 bw0 = *(const float4*)&Hs[cc][tx * 8];
            float4 bw1 = *(const float4*)&Hs[cc][tx * 8 + 4];
            ull b2[8] = { pk2(bw0.x), pk2(bw0.y), pk2(bw0.z), pk2(bw0.w),
                          pk2(bw1.x), pk2(bw1.y), pk2(bw1.z), pk2(bw1.w) };
            #pragma unroll
            for (int ii = 0; ii < 4; ii++)
                #pragma unroll
                for (int j = 0; j < 8; j++) fma2(acc2[ii][j], a2[ii], b2[j]);
        }
        __syncthreads();
    }
    float yp[8];
    #pragma unroll
    for (int j = 0; j < 8; j++) yp[j] = 0.f;
    #pragma unroll
    for (int ii = 0; ii < 4; ii++) {
        const int f0 = ty * 8 + ii * 2;
        const float b10 = fc1_b[f0],     w20 = fc2_w[f0];
        const float b11 = fc1_b[f0 + 1], w21 = fc2_w[f0 + 1];
        #pragma unroll
        for (int j = 0; j < 8; j++) {
            float2 f = up2(acc2[ii][j]);
            yp[j] = fmaf(w20, gelu_f(f.x + b10), yp[j]);
            yp[j] = fmaf(w21, gelu_f(f.y + b11), yp[j]);
        }
    }
    #pragma unroll
    for (int j = 0; j < 8; j++) red[ty][tx * 8 + j] = yp[j];
    __syncthreads();
    if (ty == 0) {
        #pragma unroll
        for (int j = 0; j < 8; j++) {
            float s = fc2_b[0];
            #pragma unroll
            for (int r = 0; r < 16; r++) s += red[r][tx * 8 + j];
            out[(size_t)b * NN + x0 + tx * 8 + j] = s;
        }
    }
}

// ---------------- launch -----------------------------------------------------
extern "C" void kernel_launch(void* const* d_in, const int* in_sizes, int n_in,
                              void* d_out, int out_size) {
    const float* x      = (const float*)d_in[0];
    const float* modes  = (const float*)d_in[1];
    const float* fc0_w  = (const float*)d_in[2];
    const float* fc0_b  = (const float*)d_in[3];
    const float* wc     = (const float*)d_in[4];
    const float* ws     = (const float*)d_in[5];
    const float* w0     = (const float*)d_in[6];
    const float* conv_w = (const float*)d_in[7];
    const float* conv_b = (const float*)d_in[8];
    const float* fc1_w  = (const float*)d_in[9];
    const float* fc1_b  = (const float*)d_in[10];
    const float* fc2_w  = (const float*)d_in[11];
    const float* fc2_b  = (const float*)d_in[12];
    float* out = (float*)d_out;

    k_wtrans<<<dim3(16, 128, 4), dim3(32, 8)>>>(wc, ws);
    k_pre<<<(BB * NN) / 256, 256>>>(x, modes, fc0_w, fc0_b);
    for (int l = 0; l < LL; l++) {
        const int cur = l & 1, nxt = cur ^ 1;
        k_gemm1<<<dim3(4, NSPLIT, BB), dim3(16, 16)>>>(cur);
        k_x0<<<dim3(BB, 16), 256>>>(cur);
        k_f0<<<BB, 128>>>(w0, conv_w, l);
        k_fmix<<<dim3(KK, 2), 128>>>(l);
        k_gemm2<<<dim3(NN / 128, BB), dim3(16, 16)>>>(cur, nxt, conv_b, l);
    }
    k_final<<<dim3(NN / 128, BB), dim3(16, 16)>>>(fc1_w, fc1_b, fc2_w, fc2_b, out);
}

// round 6
// speedup vs baseline: 1.9223x; 1.7385x over previous
#include <cuda_runtime.h>
#include <cuda_bf16.h>
#include <math.h>
#include <stdint.h>

#define BB 16
#define NN 8192
#define CC 128
#define KK 128
#define LL 4
#define JP 256
#define K448 448
#define NSPLIT 4
#define KSP (NN / NSPLIT)     // 2048

// ---------------- scratch (device globals) ----------------------------------
__device__ float g_wm[BB * NN];                                 // weights*size*mask
__device__ float g_h[2][(size_t)BB * CC * NN];                  // fp32 h ping-pong
__device__ __nv_bfloat16 g_h16h[2][(size_t)BB * CC * NN];       // h split hi/lo
__device__ __nv_bfloat16 g_h16l[2][(size_t)BB * CC * NN];
__device__ __nv_bfloat16 g_wb16h[(size_t)BB * 256 * NN];        // bases*wsz split [b][j][x]
__device__ __nv_bfloat16 g_wb16l[(size_t)BB * 256 * NN];
__device__ __nv_bfloat16 g_b16h[(size_t)BB * 257 * NN];         // bases split [b][j][x] (j=256 mask)
__device__ __nv_bfloat16 g_b16l[(size_t)BB * 257 * NN];
__device__ float g_part[(size_t)NSPLIT * BB * CC * JP];         // G1 split partials
__device__ float g_x0p[4][BB * CC];
__device__ __nv_bfloat16 g_Ah[(size_t)BB * CC * K448];          // G2 A split [b][o][j]
__device__ __nv_bfloat16 g_Al[(size_t)BB * CC * K448];
__device__ float g_wct[(size_t)LL * KK * CC * CC];
__device__ float g_wst[(size_t)LL * KK * CC * CC];

__device__ __forceinline__ float gelu_f(float v) {
    return 0.5f * v * (1.0f + erff(v * 0.70710678118654752f));
}
__device__ __forceinline__ void split_bf16(float v, __nv_bfloat16* hi, __nv_bfloat16* lo) {
    __nv_bfloat16 h = __float2bfloat16(v);
    *hi = h;
    *lo = __float2bfloat16(v - __bfloat162float(h));
}
__device__ __forceinline__ uint32_t smem_to_u32(const void* p) {
    uint32_t a;
    asm("{ .reg .u64 t; cvta.to.shared.u64 t, %1; cvt.u32.u64 %0, t; }" : "=r"(a) : "l"(p));
    return a;
}

// ---------------- mma.sync / ldmatrix / cp.async primitives -----------------
__device__ __forceinline__ void ldsm4(uint32_t (&d)[4], uint32_t a) {
    asm volatile("ldmatrix.sync.aligned.m8n8.x4.shared.b16 {%0,%1,%2,%3}, [%4];"
        : "=r"(d[0]), "=r"(d[1]), "=r"(d[2]), "=r"(d[3]) : "r"(a));
}
__device__ __forceinline__ void ldsm4t(uint32_t (&d)[4], uint32_t a) {
    asm volatile("ldmatrix.sync.aligned.m8n8.x4.trans.shared.b16 {%0,%1,%2,%3}, [%4];"
        : "=r"(d[0]), "=r"(d[1]), "=r"(d[2]), "=r"(d[3]) : "r"(a));
}
__device__ __forceinline__ void mma16816(float (&c)[4], const uint32_t (&a)[4], const uint32_t (&b)[2]) {
    asm volatile("mma.sync.aligned.m16n8k16.row.col.f32.bf16.bf16.f32 "
        "{%0,%1,%2,%3},{%4,%5,%6,%7},{%8,%9},{%0,%1,%2,%3};"
        : "+f"(c[0]), "+f"(c[1]), "+f"(c[2]), "+f"(c[3])
        : "r"(a[0]), "r"(a[1]), "r"(a[2]), "r"(a[3]), "r"(b[0]), "r"(b[1]));
}
__device__ __forceinline__ void cpasync16(uint32_t s, const void* g) {
    asm volatile("cp.async.cg.shared.global [%0], [%1], 16;" :: "r"(s), "l"(g));
}
__device__ __forceinline__ void cpasync16z(uint32_t s, const void* g, int sz) {
    asm volatile("cp.async.cg.shared.global [%0], [%1], 16, %2;" :: "r"(s), "l"(g), "r"(sz));
}
#define CP_COMMIT asm volatile("cp.async.commit_group;" ::: "memory")
#define CP_WAIT0  asm volatile("cp.async.wait_group 0;" ::: "memory")
#define CP_WAIT1  asm volatile("cp.async.wait_group 1;" ::: "memory")

// stage layout (bytes): Ah @0, Al @8192, Bh @16384, Bl @24576; stage = 32KB, 2 stages
#define STG 32768u

// A-style tile [128 rows][32 k] bf16 (64B/row): phys chunk = c ^ ((r>>1)&3)
__device__ __forceinline__ uint32_t swzA(int r, int c) {
    return (uint32_t)(r * 64 + ((c ^ ((r >> 1) & 3)) << 4));
}
// B-trans tile [32 k rows][128 n] bf16 (256B/row): phys chunk = c ^ (r&7)
__device__ __forceinline__ uint32_t swzB(int r, int c) {
    return (uint32_t)(r * 256 + ((c ^ (r & 7)) << 4));
}

// ---------------- stage fills ------------------------------------------------
// G1: A rows=h16 (stride NN), B rows=wb16 (stride NN); both [128][32]
__device__ __forceinline__ void fill_g1(uint32_t sb, int k0, int tid,
    const __nv_bfloat16* Ah, const __nv_bfloat16* Al,
    const __nv_bfloat16* Bh, const __nv_bfloat16* Bl)
{
    #pragma unroll
    for (int q = 0; q < 8; q++) {
        const int op = q >> 1;
        const int local = ((q & 1) << 8) + tid;
        const int r = local >> 2, c = local & 3;
        const __nv_bfloat16* base = (op == 0) ? Ah : (op == 1) ? Al : (op == 2) ? Bh : Bl;
        cpasync16(sb + (uint32_t)op * 8192u + swzA(r, c),
                  base + (size_t)r * NN + k0 + c * 8);
    }
}
// G2: A rows [128][32] stride K448; B [32 k rows][128 n] sourced from bases16/h16
__device__ __forceinline__ void fill_g2(uint32_t sb, int k0, int tid,
    const __nv_bfloat16* Ah, const __nv_bfloat16* Al,
    const __nv_bfloat16* Bbh, const __nv_bfloat16* Bbl,   // bases16 + b*257*NN + x0
    const __nv_bfloat16* Hh, const __nv_bfloat16* Hl)     // h16[cur] + b*CC*NN + x0
{
    #pragma unroll
    for (int q = 0; q < 8; q++) {
        const int op = q >> 1;
        const int local = ((q & 1) << 8) + tid;
        if (q < 4) {
            const int r = local >> 2, c = local & 3;
            const __nv_bfloat16* base = (op == 0) ? Ah : Al;
            cpasync16(sb + (uint32_t)op * 8192u + swzA(r, c),
                      base + (size_t)r * K448 + k0 + c * 8);
        } else {
            const int r = local >> 4, c = local & 15;
            const int jg = k0 + r;
            const bool ishi = (q < 6);
            const __nv_bfloat16* src;
            int sz = 16;
            if (jg < 257)      src = (ishi ? Bbh : Bbl) + (size_t)jg * NN;
            else if (jg < 385) src = (ishi ? Hh : Hl) + (size_t)(jg - 257) * NN;
            else             { src = ishi ? Bbh : Bbl; sz = 0; }
            cpasync16z(sb + (uint32_t)op * 8192u + swzB(r, c), src + c * 8, sz);
        }
    }
}

// ---------------- warp compute: one k32 chunk, 3-term bf16 emulation --------
template<bool BT>
__device__ __forceinline__ void compute_chunk(uint32_t sb, int wm, int wn, int lane,
                                              float (&acc)[4][4][4]) {
    #pragma unroll
    for (int k16 = 0; k16 < 2; k16++) {
        uint32_t ah[4][4], al[4][4];
        #pragma unroll
        for (int mi = 0; mi < 4; mi++) {
            const int r = wm * 64 + mi * 16 + (lane & 15);
            const int c = k16 * 2 + (lane >> 4);
            const uint32_t ad = sb + swzA(r, c);
            ldsm4(ah[mi], ad);
            ldsm4(al[mi], ad + 8192u);
        }
        uint32_t bh[4][2], bl[4][2];
        #pragma unroll
        for (int g = 0; g < 2; g++) {
            uint32_t t[4], u[4];
            if (!BT) {
                const int r = wn * 32 + g * 16 + (lane & 15);
                const int c = k16 * 2 + (lane >> 4);
                const uint32_t bd = sb + 16384u + swzA(r, c);
                ldsm4(t, bd);
                ldsm4(u, bd + 8192u);
                bh[g*2+0][0] = t[0]; bh[g*2+0][1] = t[2];
                bh[g*2+1][0] = t[1]; bh[g*2+1][1] = t[3];
                bl[g*2+0][0] = u[0]; bl[g*2+0][1] = u[2];
                bl[g*2+1][0] = u[1]; bl[g*2+1][1] = u[3];
            } else {
                const int r = k16 * 16 + (lane & 15);
                const int c = wn * 4 + g * 2 + (lane >> 4);
                const uint32_t bd = sb + 16384u + swzB(r, c);
                ldsm4t(t, bd);
                ldsm4t(u, bd + 8192u);
                bh[g*2+0][0] = t[0]; bh[g*2+0][1] = t[1];
                bh[g*2+1][0] = t[2]; bh[g*2+1][1] = t[3];
                bl[g*2+0][0] = u[0]; bl[g*2+0][1] = u[1];
                bl[g*2+1][0] = u[2]; bl[g*2+1][1] = u[3];
            }
        }
        #pragma unroll
        for (int mi = 0; mi < 4; mi++)
            #pragma unroll
            for (int ni = 0; ni < 4; ni++) {
                mma16816(acc[mi][ni], ah[mi], bh[ni]);
                mma16816(acc[mi][ni], ah[mi], bl[ni]);
                mma16816(acc[mi][ni], al[mi], bh[ni]);
            }
    }
}

// ---------------- G1: D[i=128][j=128-tile] = sum_x h*wb -------------------
__global__ __launch_bounds__(256, 1) void k_mma_g1(int cur) {
    extern __shared__ __align__(128) char dsm[];
    const uint32_t sb0 = smem_to_u32(dsm);
    const int tid = threadIdx.x, lane = tid & 31, wid = tid >> 5;
    const int wm = wid >> 2, wn = wid & 3;
    const int nt = blockIdx.x, sp = blockIdx.y, b = blockIdx.z;
    const __nv_bfloat16* Ah = g_h16h[cur] + (size_t)b * CC * NN + (size_t)sp * KSP;
    const __nv_bfloat16* Al = g_h16l[cur] + (size_t)b * CC * NN + (size_t)sp * KSP;
    const __nv_bfloat16* Bh = g_wb16h + ((size_t)b * 256 + nt * 128) * NN + (size_t)sp * KSP;
    const __nv_bfloat16* Bl = g_wb16l + ((size_t)b * 256 + nt * 128) * NN + (size_t)sp * KSP;
    float acc[4][4][4] = {};
    const int niter = KSP / 32;    // 64
    fill_g1(sb0, 0, tid, Ah, Al, Bh, Bl);
    CP_COMMIT;
    for (int it = 0; it < niter; ++it) {
        if (it + 1 < niter) {
            fill_g1(sb0 + (uint32_t)((it + 1) & 1) * STG, (it + 1) * 32, tid, Ah, Al, Bh, Bl);
            CP_COMMIT;
            CP_WAIT1;
        } else {
            CP_WAIT0;
        }
        __syncthreads();
        compute_chunk<false>(sb0 + (uint32_t)(it & 1) * STG, wm, wn, lane, acc);
        __syncthreads();
    }
    float* pp = g_part + (((size_t)sp * BB + b) * CC) * JP + nt * 128;
    #pragma unroll
    for (int mi = 0; mi < 4; mi++) {
        #pragma unroll
        for (int ni = 0; ni < 4; ni++) {
            const int m = wm * 64 + mi * 16 + (lane >> 2);
            const int n = wn * 32 + ni * 8 + (lane & 3) * 2;
            *(float2*)&pp[(size_t)m * JP + n]       = make_float2(acc[mi][ni][0], acc[mi][ni][1]);
            *(float2*)&pp[(size_t)(m + 8) * JP + n] = make_float2(acc[mi][ni][2], acc[mi][ni][3]);
        }
    }
}

// ---------------- G2: D[o=128][x=128-tile] = sum_j A*[bases;h] -------------
__global__ __launch_bounds__(256, 1) void k_mma_g2(int cur, int nxt,
                                                   const float* __restrict__ conv_b,
                                                   int l, int dogelu, int dosplit) {
    extern __shared__ __align__(128) char dsm[];
    __shared__ float scb[128];
    const uint32_t sb0 = smem_to_u32(dsm);
    const int tid = threadIdx.x, lane = tid & 31, wid = tid >> 5;
    const int wm = wid >> 2, wn = wid & 3;
    const int xt = blockIdx.x, b = blockIdx.y;
    if (tid < 128) scb[tid] = conv_b[l * CC + tid];
    const __nv_bfloat16* Ah = g_Ah + (size_t)b * CC * K448;
    const __nv_bfloat16* Al = g_Al + (size_t)b * CC * K448;
    const __nv_bfloat16* Bbh = g_b16h + (size_t)b * 257 * NN + (size_t)xt * 128;
    const __nv_bfloat16* Bbl = g_b16l + (size_t)b * 257 * NN + (size_t)xt * 128;
    const __nv_bfloat16* Hh = g_h16h[cur] + (size_t)b * CC * NN + (size_t)xt * 128;
    const __nv_bfloat16* Hl = g_h16l[cur] + (size_t)b * CC * NN + (size_t)xt * 128;
    float acc[4][4][4] = {};
    const int niter = K448 / 32;   // 14
    fill_g2(sb0, 0, tid, Ah, Al, Bbh, Bbl, Hh, Hl);
    CP_COMMIT;
    for (int it = 0; it < niter; ++it) {
        if (it + 1 < niter) {
            fill_g2(sb0 + (uint32_t)((it + 1) & 1) * STG, (it + 1) * 32, tid, Ah, Al, Bbh, Bbl, Hh, Hl);
            CP_COMMIT;
            CP_WAIT1;
        } else {
            CP_WAIT0;
        }
        __syncthreads();
        compute_chunk<true>(sb0 + (uint32_t)(it & 1) * STG, wm, wn, lane, acc);
        __syncthreads();
    }
    float* hout = g_h[nxt] + (size_t)b * CC * NN + (size_t)xt * 128;
    __nv_bfloat16* hh = g_h16h[nxt] + (size_t)b * CC * NN + (size_t)xt * 128;
    __nv_bfloat16* hl = g_h16l[nxt] + (size_t)b * CC * NN + (size_t)xt * 128;
    #pragma unroll
    for (int mi = 0; mi < 4; mi++) {
        #pragma unroll
        for (int ni = 0; ni < 4; ni++) {
            const int n = wn * 32 + ni * 8 + (lane & 3) * 2;
            #pragma unroll
            for (int half = 0; half < 2; half++) {
                const int o = wm * 64 + mi * 16 + (lane >> 2) + half * 8;
                float v0 = acc[mi][ni][half * 2 + 0] + scb[o];
                float v1 = acc[mi][ni][half * 2 + 1] + scb[o];
                if (dogelu) { v0 = gelu_f(v0); v1 = gelu_f(v1); }
                *(float2*)&hout[(size_t)o * NN + n] = make_float2(v0, v1);
                if (dosplit) {
                    __nv_bfloat16 h0, l0, h1, l1;
                    split_bf16(v0, &h0, &l0);
                    split_bf16(v1, &h1, &l1);
                    __nv_bfloat162 ph; ph.x = h0; ph.y = h1;
                    __nv_bfloat162 pl; pl.x = l0; pl.y = l1;
                    *(__nv_bfloat162*)&hh[(size_t)o * NN + n] = ph;
                    *(__nv_bfloat162*)&hl[(size_t)o * NN + n] = pl;
                }
            }
        }
    }
}

// ---------------- weight transpose (once) ------------------------------------
__global__ void k_wtrans(const float* __restrict__ wc, const float* __restrict__ ws) {
    __shared__ float sm[32][33];
    const int tile = blockIdx.x;
    const int o0 = (tile >> 2) * 32, k0 = (tile & 3) * 32;
    const int i = blockIdx.y, l = blockIdx.z;
    const float scale = 1.0f / 8192.0f;
    for (int w = 0; w < 2; w++) {
        const float* src = w ? ws : wc;
        float* dst = w ? g_wst : g_wct;
        #pragma unroll
        for (int s = 0; s < 4; s++) {
            int oo = threadIdx.y + 8 * s, kk = threadIdx.x;
            sm[oo][kk] = src[(((size_t)l * CC + i) * CC + (o0 + oo)) * KK + (k0 + kk)] * scale;
        }
        __syncthreads();
        #pragma unroll
        for (int s = 0; s < 4; s++) {
            int kk = threadIdx.y + 8 * s, oo = threadIdx.x;
            dst[(((size_t)l * KK + (k0 + kk)) * CC + i) * CC + (o0 + oo)] = sm[oo][kk];
        }
        __syncthreads();
    }
}

// ---------------- precompute: bases16, wb16, wm, h0 (fp32 + split) -----------
__global__ __launch_bounds__(256) void k_pre(const float* __restrict__ xin,
                                             const float* __restrict__ modes,
                                             const float* __restrict__ fc0_w,
                                             const float* __restrict__ fc0_b) {
    __shared__ float sm_modes[256];
    __shared__ float sm_w[384];
    __shared__ float sm_b[128];
    const int t = threadIdx.x;
    sm_modes[t] = modes[t];
    sm_w[t] = fc0_w[t];
    if (t < 128) { sm_w[256 + t] = fc0_w[256 + t]; sm_b[t] = fc0_b[t]; }
    __syncthreads();

    const int gid = blockIdx.x * 256 + t;
    const int b = gid / NN, xx = gid - b * NN;
    const float* xr = xin + (size_t)gid * 7;
    const float i0 = xr[0], i1 = xr[1], i2 = xr[2];
    const float d0 = xr[3], d1 = xr[4], wgt = xr[5], msk = xr[6];

    const float wsz = wgt * (float)NN;
    g_wm[gid] = wsz * msk;
    __nv_bfloat16* bh = g_b16h + (size_t)b * 257 * NN + xx;
    __nv_bfloat16* bl = g_b16l + (size_t)b * 257 * NN + xx;
    __nv_bfloat16* wbh = g_wb16h + (size_t)b * 256 * NN + xx;
    __nv_bfloat16* wbl = g_wb16l + (size_t)b * 256 * NN + xx;
    bh[(size_t)256 * NN] = __float2bfloat16(msk);   // exact (0/1)
    bl[(size_t)256 * NN] = __float2bfloat16(0.f);
    #pragma unroll 4
    for (int k = 0; k < KK; k++) {
        float tt = fmaf(d0, sm_modes[2 * k], d1 * sm_modes[2 * k + 1]);
        float s, c;
        sincosf(tt, &s, &c);
        const float cm = c * msk, smm = s * msk;
        __nv_bfloat16 hi, lo;
        split_bf16(cm, &hi, &lo);
        bh[(size_t)k * NN] = hi; bl[(size_t)k * NN] = lo;
        split_bf16(smm, &hi, &lo);
        bh[(size_t)(128 + k) * NN] = hi; bl[(size_t)(128 + k) * NN] = lo;
        split_bf16(cm * wsz, &hi, &lo);
        wbh[(size_t)k * NN] = hi; wbl[(size_t)k * NN] = lo;
        split_bf16(smm * wsz, &hi, &lo);
        wbh[(size_t)(128 + k) * NN] = hi; wbl[(size_t)(128 + k) * NN] = lo;
    }
    float* hhp = g_h[0] + (size_t)b * CC * NN + xx;
    __nv_bfloat16* h16h = g_h16h[0] + (size_t)b * CC * NN + xx;
    __nv_bfloat16* h16l = g_h16l[0] + (size_t)b * CC * NN + xx;
    #pragma unroll 4
    for (int c = 0; c < CC; c++) {
        float v = sm_b[c];
        v = fmaf(i0, sm_w[c], v);
        v = fmaf(i1, sm_w[128 + c], v);
        v = fmaf(i2, sm_w[256 + c], v);
        hhp[(size_t)c * NN] = v;
        __nv_bfloat16 hi, lo;
        split_bf16(v, &hi, &lo);
        h16h[(size_t)c * NN] = hi;
        h16l[(size_t)c * NN] = lo;
    }
}

// ---------------- x_0 partials (4-way x split) --------------------------------
__global__ __launch_bounds__(256) void k_x0(int cur) {
    const int b = blockIdx.x;
    const int i = blockIdx.y * 8 + (threadIdx.x >> 5);
    const int z = blockIdx.z;
    const int lane = threadIdx.x & 31;
    const int q = NN / 16;
    const float4* hp = (const float4*)(g_h[cur] + ((size_t)b * CC + i) * NN) + (size_t)z * q;
    const float4* wp = (const float4*)(g_wm + (size_t)b * NN) + (size_t)z * q;
    float s = 0.f;
    for (int t = lane; t < q; t += 32) {
        float4 h4 = hp[t], w4 = wp[t];
        s = fmaf(h4.x, w4.x, s);
        s = fmaf(h4.y, w4.y, s);
        s = fmaf(h4.z, w4.z, s);
        s = fmaf(h4.w, w4.w, s);
    }
    #pragma unroll
    for (int off = 16; off; off >>= 1) s += __shfl_xor_sync(0xffffffffu, s, off);
    if (!lane) g_x0p[z][b * CC + i] = s;
}

// ---------------- f_0 + conv rows of A (bf16 split) ---------------------------
__global__ __launch_bounds__(128) void k_f0(const float* __restrict__ w0,
                                            const float* __restrict__ conv_w, int l) {
    const int b = blockIdx.x, o = threadIdx.x;
    __shared__ float x0s[128];
    x0s[o] = g_x0p[0][b * CC + o] + g_x0p[1][b * CC + o] + g_x0p[2][b * CC + o] + g_x0p[3][b * CC + o];
    __syncthreads();
    float f0 = 0.f;
    const float* w0p = w0 + (size_t)l * CC * CC;
    #pragma unroll 8
    for (int i = 0; i < 128; i++) f0 = fmaf(x0s[i], w0p[(size_t)i * CC + o], f0);
    const size_t base = ((size_t)b * CC + o) * K448;
    __nv_bfloat16 hi, lo;
    split_bf16(f0 * (1.0f / 8192.0f), &hi, &lo);
    g_Ah[base + 256] = hi; g_Al[base + 256] = lo;
    const float* cw = conv_w + ((size_t)(l * CC) + o) * CC;
    #pragma unroll 8
    for (int i = 0; i < 128; i++) {
        split_bf16(cw[i], &hi, &lo);
        g_Ah[base + 257 + i] = hi; g_Al[base + 257 + i] = lo;
    }
    const __nv_bfloat16 z = __float2bfloat16(0.f);
    #pragma unroll
    for (int j = 385; j < K448; j++) { g_Ah[base + j] = z; g_Al[base + j] = z; }
}

// ---------------- per-k complex mix -> A rows [2f_c, -2f_s] -------------------
__global__ __launch_bounds__(128) void k_fmix(int l) {
    const int k = blockIdx.x;
    const int bh = blockIdx.y * 8;
    const int t = threadIdx.x;
    __shared__ float xc_s[128][8];
    __shared__ float xs_s[128][8];
    #pragma unroll
    for (int b = 0; b < 8; b++) {
        float sc = 0.f, ss = 0.f;
        #pragma unroll
        for (int s = 0; s < NSPLIT; s++) {
            const float* pp = g_part + (((size_t)s * BB + bh + b) * CC + t) * JP;
            sc += pp[k];
            ss += pp[128 + k];
        }
        xc_s[t][b] = sc;
        xs_s[t][b] = -ss;
    }
    __syncthreads();
    float fc[8] = {}, fs[8] = {};
    const float* wcp = g_wct + ((size_t)(l * KK + k)) * CC * CC + t;
    const float* wsp = g_wst + ((size_t)(l * KK + k)) * CC * CC + t;
    #pragma unroll 4
    for (int i = 0; i < 128; i++) {
        const float wcv = wcp[(size_t)i * CC], wsv = wsp[(size_t)i * CC];
        #pragma unroll
        for (int b = 0; b < 8; b++) {
            const float cv = xc_s[i][b], sv = xs_s[i][b];
            fc[b] = fmaf(cv, wcv, fc[b]); fc[b] = fmaf(-sv, wsv, fc[b]);
            fs[b] = fmaf(sv, wcv, fs[b]); fs[b] = fmaf(cv, wsv, fs[b]);
        }
    }
    #pragma unroll
    for (int b = 0; b < 8; b++) {
        const size_t base = ((size_t)(bh + b) * CC + t) * K448;
        __nv_bfloat16 hi, lo;
        split_bf16(2.f * fc[b], &hi, &lo);
        g_Ah[base + k] = hi; g_Al[base + k] = lo;
        split_bf16(-2.f * fs[b], &hi, &lo);
        g_Ah[base + 128 + k] = hi; g_Al[base + 128 + k] = lo;
    }
}

// ---------------- final MLP (SIMT fp32) ---------------------------------------
__global__ __launch_bounds__(256) void k_final(const float* __restrict__ fc1_w,
                                               const float* __restrict__ fc1_b,
                                               const float* __restrict__ fc2_w,
                                               const float* __restrict__ fc2_b,
                                               float* __restrict__ out) {
    __shared__ float Hs[8][128];
    __shared__ float Ws[8][128];
    __shared__ float red[16][128];
    const int xt = blockIdx.x, b = blockIdx.y;
    const int tid = threadIdx.x;
    const int tx = tid & 15, ty = tid >> 4;
    const int x0 = xt * 128;
    const float* h = g_h[0] + (size_t)b * CC * NN;
    float acc[8][8];
    #pragma unroll
    for (int i = 0; i < 8; i++)
        #pragma unroll
        for (int j = 0; j < 8; j++) acc[i][j] = 0.f;

    const int lcc = tid >> 5;
    const int lxx = (tid & 31) * 4;
    for (int c0 = 0; c0 < CC; c0 += 8) {
        *(float4*)&Hs[lcc][lxx] = *(const float4*)(h + (size_t)(c0 + lcc) * NN + x0 + lxx);
        *(float4*)&Ws[lcc][lxx] = *(const float4*)(fc1_w + (c0 + lcc) * 128 + lxx);
        __syncthreads();
        #pragma unroll
        for (int cc = 0; cc < 8; cc++) {
            float a[8], bw[8];
            *(float4*)&a[0]  = *(const float4*)&Ws[cc][ty * 8];
            *(float4*)&a[4]  = *(const float4*)&Ws[cc][ty * 8 + 4];
            *(float4*)&bw[0] = *(const float4*)&Hs[cc][tx * 8];
            *(float4*)&bw[4] = *(const float4*)&Hs[cc][tx * 8 + 4];
            #pragma unroll
            for (int i = 0; i < 8; i++)
                #pragma unroll
                for (int j = 0; j < 8; j++) acc[i][j] = fmaf(a[i], bw[j], acc[i][j]);
        }
        __syncthreads();
    }
    float yp[8];
    #pragma unroll
    for (int j = 0; j < 8; j++) yp[j] = 0.f;
    #pragma unroll
    for (int i = 0; i < 8; i++) {
        const int f = ty * 8 + i;
        const float b1 = fc1_b[f], w2 = fc2_w[f];
        #pragma unroll
        for (int j = 0; j < 8; j++) yp[j] = fmaf(w2, gelu_f(acc[i][j] + b1), yp[j]);
    }
    #pragma unroll
    for (int j = 0; j < 8; j++) red[ty][tx * 8 + j] = yp[j];
    __syncthreads();
    if (ty == 0) {
        #pragma unroll
        for (int j = 0; j < 8; j++) {
            float s = fc2_b[0];
            #pragma unroll
            for (int r = 0; r < 16; r++) s += red[r][tx * 8 + j];
            out[(size_t)b * NN + x0 + tx * 8 + j] = s;
        }
    }
}

// ---------------- launch -------------------------------------------------------
extern "C" void kernel_launch(void* const* d_in, const int* in_sizes, int n_in,
                              void* d_out, int out_size) {
    const float* x      = (const float*)d_in[0];
    const float* modes  = (const float*)d_in[1];
    const float* fc0_w  = (const float*)d_in[2];
    const float* fc0_b  = (const float*)d_in[3];
    const float* wc     = (const float*)d_in[4];
    const float* ws     = (const float*)d_in[5];
    const float* w0     = (const float*)d_in[6];
    const float* conv_w = (const float*)d_in[7];
    const float* conv_b = (const float*)d_in[8];
    const float* fc1_w  = (const float*)d_in[9];
    const float* fc1_b  = (const float*)d_in[10];
    const float* fc2_w  = (const float*)d_in[11];
    const float* fc2_b  = (const float*)d_in[12];
    float* out = (float*)d_out;

    const int smem = 2 * (int)STG;   // 64KB
    cudaFuncSetAttribute(k_mma_g1, cudaFuncAttributeMaxDynamicSharedMemorySize, smem);
    cudaFuncSetAttribute(k_mma_g2, cudaFuncAttributeMaxDynamicSharedMemorySize, smem);

    k_wtrans<<<dim3(16, 128, 4), dim3(32, 8)>>>(wc, ws);
    k_pre<<<(BB * NN) / 256, 256>>>(x, modes, fc0_w, fc0_b);
    for (int l = 0; l < LL; l++) {
        const int cur = l & 1, nxt = cur ^ 1;
        k_mma_g1<<<dim3(2, NSPLIT, BB), 256, smem>>>(cur);
        k_x0<<<dim3(BB, 16, 4), 256>>>(cur);
        k_f0<<<BB, 128>>>(w0, conv_w, l);
        k_fmix<<<dim3(KK, 2), 128>>>(l);
        k_mma_g2<<<dim3(NN / 128, BB), 256, smem>>>(cur, nxt, conv_b, l,
                                                    (l < LL - 1) ? 1 : 0,
                                                    (l < LL - 1) ? 1 : 0);
    }
    k_final<<<dim3(NN / 128, BB), 256>>>(fc1_w, fc1_b, fc2_w, fc2_b, out);
}

// round 7
// speedup vs baseline: 2.3905x; 1.2435x over previous
#include <cuda_runtime.h>
#include <cuda_bf16.h>
#include <math.h>
#include <stdint.h>

#define BB 16
#define NN 8192
#define CC 128
#define KK 128
#define LL 4
#define JP 256
#define KA 416            // padded K for G2 (385 -> 416 = 13*32)
#define NSPLIT 4
#define KSP (NN / NSPLIT) // 2048

// ---------------- scratch (device globals) ----------------------------------
__device__ float g_wm[BB * NN];                                 // weights*size*mask
__device__ float g_h[(size_t)BB * CC * NN];                     // fp32 h (final layer only)
__device__ __nv_bfloat16 g_h16h[2][(size_t)BB * CC * NN];       // h split hi/lo ping-pong
__device__ __nv_bfloat16 g_h16l[2][(size_t)BB * CC * NN];
__device__ __nv_bfloat16 g_wb16h[(size_t)BB * 256 * NN];        // bases*wsz split [b][j][x]
__device__ __nv_bfloat16 g_wb16l[(size_t)BB * 256 * NN];
__device__ __nv_bfloat16 g_b16h[(size_t)BB * 257 * NN];         // bases split [b][j][x] (j=256 mask)
__device__ __nv_bfloat16 g_b16l[(size_t)BB * 257 * NN];
__device__ float g_part[(size_t)NSPLIT * BB * CC * JP];         // G1 split partials
__device__ float g_x0p[64][BB * CC];                            // x0 partials
__device__ __nv_bfloat16 g_Ah[(size_t)BB * CC * KA];            // G2 A split [b][o][j]
__device__ __nv_bfloat16 g_Al[(size_t)BB * CC * KA];
__device__ float g_wct[(size_t)LL * KK * CC * CC];
__device__ float g_wst[(size_t)LL * KK * CC * CC];

__device__ __forceinline__ float gelu_f(float v) {
    return 0.5f * v * (1.0f + erff(v * 0.70710678118654752f));
}
__device__ __forceinline__ void split_bf16(float v, __nv_bfloat16* hi, __nv_bfloat16* lo) {
    __nv_bfloat16 h = __float2bfloat16(v);
    *hi = h;
    *lo = __float2bfloat16(v - __bfloat162float(h));
}
__device__ __forceinline__ uint32_t smem_to_u32(const void* p) {
    uint32_t a;
    asm("{ .reg .u64 t; cvta.to.shared.u64 t, %1; cvt.u32.u64 %0, t; }" : "=r"(a) : "l"(p));
    return a;
}
__device__ __forceinline__ float2 rec2(uint32_t h, uint32_t l) {
    __nv_bfloat162 hh = *(__nv_bfloat162*)&h;
    __nv_bfloat162 ll = *(__nv_bfloat162*)&l;
    return make_float2(__bfloat162float(hh.x) + __bfloat162float(ll.x),
                       __bfloat162float(hh.y) + __bfloat162float(ll.y));
}

// ---------------- mma.sync / ldmatrix / cp.async primitives -----------------
__device__ __forceinline__ void ldsm4(uint32_t (&d)[4], uint32_t a) {
    asm volatile("ldmatrix.sync.aligned.m8n8.x4.shared.b16 {%0,%1,%2,%3}, [%4];"
        : "=r"(d[0]), "=r"(d[1]), "=r"(d[2]), "=r"(d[3]) : "r"(a));
}
__device__ __forceinline__ void ldsm4t(uint32_t (&d)[4], uint32_t a) {
    asm volatile("ldmatrix.sync.aligned.m8n8.x4.trans.shared.b16 {%0,%1,%2,%3}, [%4];"
        : "=r"(d[0]), "=r"(d[1]), "=r"(d[2]), "=r"(d[3]) : "r"(a));
}
__device__ __forceinline__ void mma16816(float (&c)[4], const uint32_t (&a)[4], const uint32_t (&b)[2]) {
    asm volatile("mma.sync.aligned.m16n8k16.row.col.f32.bf16.bf16.f32 "
        "{%0,%1,%2,%3},{%4,%5,%6,%7},{%8,%9},{%0,%1,%2,%3};"
        : "+f"(c[0]), "+f"(c[1]), "+f"(c[2]), "+f"(c[3])
        : "r"(a[0]), "r"(a[1]), "r"(a[2]), "r"(a[3]), "r"(b[0]), "r"(b[1]));
}
__device__ __forceinline__ void cpasync16(uint32_t s, const void* g) {
    asm volatile("cp.async.cg.shared.global [%0], [%1], 16;" :: "r"(s), "l"(g));
}
__device__ __forceinline__ void cpasync16z(uint32_t s, const void* g, int sz) {
    asm volatile("cp.async.cg.shared.global [%0], [%1], 16, %2;" :: "r"(s), "l"(g), "r"(sz));
}
#define CP_COMMIT asm volatile("cp.async.commit_group;" ::: "memory")
#define CP_WAIT0  asm volatile("cp.async.wait_group 0;" ::: "memory")
#define CP_WAIT1  asm volatile("cp.async.wait_group 1;" ::: "memory")

// stage layout (bytes): Ah @0, Al @8192, Bh @16384, Bl @24576; stage = 32KB, 2 stages
#define STG 32768u

__device__ __forceinline__ uint32_t swzA(int r, int c) {
    return (uint32_t)(r * 64 + ((c ^ ((r >> 1) & 3)) << 4));
}
__device__ __forceinline__ uint32_t swzB(int r, int c) {
    return (uint32_t)(r * 256 + ((c ^ (r & 7)) << 4));
}

// ---------------- stage fills ------------------------------------------------
__device__ __forceinline__ void fill_g1(uint32_t sb, int k0, int tid,
    const __nv_bfloat16* Ah, const __nv_bfloat16* Al,
    const __nv_bfloat16* Bh, const __nv_bfloat16* Bl)
{
    #pragma unroll
    for (int q = 0; q < 8; q++) {
        const int op = q >> 1;
        const int local = ((q & 1) << 8) + tid;
        const int r = local >> 2, c = local & 3;
        const __nv_bfloat16* base = (op == 0) ? Ah : (op == 1) ? Al : (op == 2) ? Bh : Bl;
        cpasync16(sb + (uint32_t)op * 8192u + swzA(r, c),
                  base + (size_t)r * NN + k0 + c * 8);
    }
}
__device__ __forceinline__ void fill_g2(uint32_t sb, int k0, int tid,
    const __nv_bfloat16* Ah, const __nv_bfloat16* Al,
    const __nv_bfloat16* Bbh, const __nv_bfloat16* Bbl,
    const __nv_bfloat16* Hh, const __nv_bfloat16* Hl)
{
    #pragma unroll
    for (int q = 0; q < 8; q++) {
        const int op = q >> 1;
        const int local = ((q & 1) << 8) + tid;
        if (q < 4) {
            const int r = local >> 2, c = local & 3;
            const __nv_bfloat16* base = (op == 0) ? Ah : Al;
            cpasync16(sb + (uint32_t)op * 8192u + swzA(r, c),
                      base + (size_t)r * KA + k0 + c * 8);
        } else {
            const int r = local >> 4, c = local & 15;
            const int jg = k0 + r;
            const bool ishi = (q < 6);
            const __nv_bfloat16* src;
            int sz = 16;
            if (jg < 257)      src = (ishi ? Bbh : Bbl) + (size_t)jg * NN;
            else if (jg < 385) src = (ishi ? Hh : Hl) + (size_t)(jg - 257) * NN;
            else             { src = ishi ? Bbh : Bbl; sz = 0; }
            cpasync16z(sb + (uint32_t)op * 8192u + swzB(r, c), src + c * 8, sz);
        }
    }
}

// ---------------- warp compute: one k32 chunk, 3-term bf16 emulation --------
template<bool BT>
__device__ __forceinline__ void compute_chunk(uint32_t sb, int wmi, int wni, int lane,
                                              float (&acc)[4][4][4]) {
    #pragma unroll
    for (int k16 = 0; k16 < 2; k16++) {
        uint32_t ah[4][4], al[4][4];
        #pragma unroll
        for (int mi = 0; mi < 4; mi++) {
            const int r = wmi * 64 + mi * 16 + (lane & 15);
            const int c = k16 * 2 + (lane >> 4);
            const uint32_t ad = sb + swzA(r, c);
            ldsm4(ah[mi], ad);
            ldsm4(al[mi], ad + 8192u);
        }
        uint32_t bh[4][2], bl[4][2];
        #pragma unroll
        for (int g = 0; g < 2; g++) {
            uint32_t t[4], u[4];
            if (!BT) {
                const int r = wni * 32 + g * 16 + (lane & 15);
                const int c = k16 * 2 + (lane >> 4);
                const uint32_t bd = sb + 16384u + swzA(r, c);
                ldsm4(t, bd);
                ldsm4(u, bd + 8192u);
                bh[g*2+0][0] = t[0]; bh[g*2+0][1] = t[2];
                bh[g*2+1][0] = t[1]; bh[g*2+1][1] = t[3];
                bl[g*2+0][0] = u[0]; bl[g*2+0][1] = u[2];
                bl[g*2+1][0] = u[1]; bl[g*2+1][1] = u[3];
            } else {
                const int r = k16 * 16 + (lane & 15);
                const int c = wni * 4 + g * 2 + (lane >> 4);
                const uint32_t bd = sb + 16384u + swzB(r, c);
                ldsm4t(t, bd);
                ldsm4t(u, bd + 8192u);
                bh[g*2+0][0] = t[0]; bh[g*2+0][1] = t[1];
                bh[g*2+1][0] = t[2]; bh[g*2+1][1] = t[3];
                bl[g*2+0][0] = u[0]; bl[g*2+0][1] = u[1];
                bl[g*2+1][0] = u[2]; bl[g*2+1][1] = u[3];
            }
        }
        #pragma unroll
        for (int mi = 0; mi < 4; mi++)
            #pragma unroll
            for (int ni = 0; ni < 4; ni++) {
                mma16816(acc[mi][ni], ah[mi], bh[ni]);
                mma16816(acc[mi][ni], ah[mi], bl[ni]);
                mma16816(acc[mi][ni], al[mi], bh[ni]);
            }
    }
}

// ---------------- G1: D[i=128][j=128-tile] = sum_x h*wb ----------------------
__global__ __launch_bounds__(256, 1) void k_mma_g1(int cur) {
    extern __shared__ __align__(128) char dsm[];
    const uint32_t sb0 = smem_to_u32(dsm);
    const int tid = threadIdx.x, lane = tid & 31, wid = tid >> 5;
    const int wmi = wid >> 2, wni = wid & 3;
    const int nt = blockIdx.x, sp = blockIdx.y, b = blockIdx.z;
    const __nv_bfloat16* Ah = g_h16h[cur] + (size_t)b * CC * NN + (size_t)sp * KSP;
    const __nv_bfloat16* Al = g_h16l[cur] + (size_t)b * CC * NN + (size_t)sp * KSP;
    const __nv_bfloat16* Bh = g_wb16h + ((size_t)b * 256 + nt * 128) * NN + (size_t)sp * KSP;
    const __nv_bfloat16* Bl = g_wb16l + ((size_t)b * 256 + nt * 128) * NN + (size_t)sp * KSP;
    float acc[4][4][4] = {};
    const int niter = KSP / 32;    // 64
    fill_g1(sb0, 0, tid, Ah, Al, Bh, Bl);
    CP_COMMIT;
    for (int it = 0; it < niter; ++it) {
        if (it + 1 < niter) {
            fill_g1(sb0 + (uint32_t)((it + 1) & 1) * STG, (it + 1) * 32, tid, Ah, Al, Bh, Bl);
            CP_COMMIT;
            CP_WAIT1;
        } else {
            CP_WAIT0;
        }
        __syncthreads();
        compute_chunk<false>(sb0 + (uint32_t)(it & 1) * STG, wmi, wni, lane, acc);
        __syncthreads();
    }
    float* pp = g_part + (((size_t)sp * BB + b) * CC) * JP + nt * 128;
    #pragma unroll
    for (int mi = 0; mi < 4; mi++) {
        #pragma unroll
        for (int ni = 0; ni < 4; ni++) {
            const int m = wmi * 64 + mi * 16 + (lane >> 2);
            const int n = wni * 32 + ni * 8 + (lane & 3) * 2;
            *(float2*)&pp[(size_t)m * JP + n]       = make_float2(acc[mi][ni][0], acc[mi][ni][1]);
            *(float2*)&pp[(size_t)(m + 8) * JP + n] = make_float2(acc[mi][ni][2], acc[mi][ni][3]);
        }
    }
}

// ---------------- G2: D[o=128][x=128-tile] = sum_j A*[bases;h] ---------------
// epilogue: +conv_b, gelu, bf16 split write, deterministic x0 partials for next layer
__global__ __launch_bounds__(256, 1) void k_mma_g2(int cur, int nxt,
                                                   const float* __restrict__ conv_b,
                                                   int l, int dogelu, int dosplit) {
    extern __shared__ __align__(128) char dsm[];
    __shared__ float scb[128];
    __shared__ float s_wm[128];
    __shared__ float s_part[128][16];
    const uint32_t sb0 = smem_to_u32(dsm);
    const int tid = threadIdx.x, lane = tid & 31, wid = tid >> 5;
    const int wmi = wid >> 2, wni = wid & 3;
    const int xt = blockIdx.x, b = blockIdx.y;
    if (tid < 128) {
        scb[tid] = conv_b[l * CC + tid];
        s_wm[tid] = g_wm[(size_t)b * NN + (size_t)xt * 128 + tid];
    }
    const __nv_bfloat16* Ah = g_Ah + (size_t)b * CC * KA;
    const __nv_bfloat16* Al = g_Al + (size_t)b * CC * KA;
    const __nv_bfloat16* Bbh = g_b16h + (size_t)b * 257 * NN + (size_t)xt * 128;
    const __nv_bfloat16* Bbl = g_b16l + (size_t)b * 257 * NN + (size_t)xt * 128;
    const __nv_bfloat16* Hh = g_h16h[cur] + (size_t)b * CC * NN + (size_t)xt * 128;
    const __nv_bfloat16* Hl = g_h16l[cur] + (size_t)b * CC * NN + (size_t)xt * 128;
    float acc[4][4][4] = {};
    const int niter = KA / 32;   // 13
    fill_g2(sb0, 0, tid, Ah, Al, Bbh, Bbl, Hh, Hl);
    CP_COMMIT;
    for (int it = 0; it < niter; ++it) {
        if (it + 1 < niter) {
            fill_g2(sb0 + (uint32_t)((it + 1) & 1) * STG, (it + 1) * 32, tid, Ah, Al, Bbh, Bbl, Hh, Hl);
            CP_COMMIT;
            CP_WAIT1;
        } else {
            CP_WAIT0;
        }
        __syncthreads();
        compute_chunk<true>(sb0 + (uint32_t)(it & 1) * STG, wmi, wni, lane, acc);
        __syncthreads();
    }
    float* hout = g_h + (size_t)b * CC * NN + (size_t)xt * 128;
    __nv_bfloat16* hh = g_h16h[nxt] + (size_t)b * CC * NN + (size_t)xt * 128;
    __nv_bfloat16* hl = g_h16l[nxt] + (size_t)b * CC * NN + (size_t)xt * 128;
    float sx[8] = {};
    #pragma unroll
    for (int mi = 0; mi < 4; mi++) {
        #pragma unroll
        for (int ni = 0; ni < 4; ni++) {
            const int n = wni * 32 + ni * 8 + (lane & 3) * 2;
            #pragma unroll
            for (int half = 0; half < 2; half++) {
                const int o = wmi * 64 + mi * 16 + (lane >> 2) + half * 8;
                float v0 = acc[mi][ni][half * 2 + 0] + scb[o];
                float v1 = acc[mi][ni][half * 2 + 1] + scb[o];
                if (dogelu) { v0 = gelu_f(v0); v1 = gelu_f(v1); }
                if (dosplit) {
                    __nv_bfloat16 h0, l0, h1, l1;
                    split_bf16(v0, &h0, &l0);
                    split_bf16(v1, &h1, &l1);
                    __nv_bfloat162 ph; ph.x = h0; ph.y = h1;
                    __nv_bfloat162 pl; pl.x = l0; pl.y = l1;
                    *(__nv_bfloat162*)&hh[(size_t)o * NN + n] = ph;
                    *(__nv_bfloat162*)&hl[(size_t)o * NN + n] = pl;
                    sx[mi * 2 + half] = fmaf(v0, s_wm[n], sx[mi * 2 + half]);
                    sx[mi * 2 + half] = fmaf(v1, s_wm[n + 1], sx[mi * 2 + half]);
                } else {
                    *(float2*)&hout[(size_t)o * NN + n] = make_float2(v0, v1);
                }
            }
        }
    }
    if (dosplit) {
        const int slot = wni * 4 + (lane & 3);
        #pragma unroll
        for (int mi = 0; mi < 4; mi++)
            #pragma unroll
            for (int half = 0; half < 2; half++) {
                const int o = wmi * 64 + mi * 16 + (lane >> 2) + half * 8;
                s_part[o][slot] = sx[mi * 2 + half];
            }
        __syncthreads();
        if (tid < 128) {
            float s = 0.f;
            #pragma unroll
            for (int q = 0; q < 16; q++) s += s_part[tid][q];
            g_x0p[xt][b * CC + tid] = s;
        }
    }
}

// ---------------- weight transpose (once) ------------------------------------
__global__ void k_wtrans(const float* __restrict__ wc, const float* __restrict__ ws) {
    __shared__ float sm[32][33];
    const int tile = blockIdx.x;
    const int o0 = (tile >> 2) * 32, k0 = (tile & 3) * 32;
    const int i = blockIdx.y, l = blockIdx.z;
    const float scale = 1.0f / 8192.0f;
    for (int w = 0; w < 2; w++) {
        const float* src = w ? ws : wc;
        float* dst = w ? g_wst : g_wct;
        #pragma unroll
        for (int s = 0; s < 4; s++) {
            int oo = threadIdx.y + 8 * s, kk = threadIdx.x;
            sm[oo][kk] = src[(((size_t)l * CC + i) * CC + (o0 + oo)) * KK + (k0 + kk)] * scale;
        }
        __syncthreads();
        #pragma unroll
        for (int s = 0; s < 4; s++) {
            int kk = threadIdx.y + 8 * s, oo = threadIdx.x;
            dst[(((size_t)l * KK + (k0 + kk)) * CC + i) * CC + (o0 + oo)] = sm[oo][kk];
        }
        __syncthreads();
    }
}

// ---------------- precompute: bases16, wb16, wm, h0 splits --------------------
__global__ __launch_bounds__(256) void k_pre(const float* __restrict__ xin,
                                             const float* __restrict__ modes,
                                             const float* __restrict__ fc0_w,
                                             const float* __restrict__ fc0_b) {
    __shared__ float sm_modes[256];
    __shared__ float sm_w[384];
    __shared__ float sm_b[128];
    const int t = threadIdx.x;
    sm_modes[t] = modes[t];
    sm_w[t] = fc0_w[t];
    if (t < 128) { sm_w[256 + t] = fc0_w[256 + t]; sm_b[t] = fc0_b[t]; }
    __syncthreads();

    const int gid = blockIdx.x * 256 + t;
    const int b = gid / NN, xx = gid - b * NN;
    const float* xr = xin + (size_t)gid * 7;
    const float i0 = xr[0], i1 = xr[1], i2 = xr[2];
    const float d0 = xr[3], d1 = xr[4], wgt = xr[5], msk = xr[6];

    const float wsz = wgt * (float)NN;
    g_wm[gid] = wsz * msk;
    __nv_bfloat16* bh = g_b16h + (size_t)b * 257 * NN + xx;
    __nv_bfloat16* bl = g_b16l + (size_t)b * 257 * NN + xx;
    __nv_bfloat16* wbh = g_wb16h + (size_t)b * 256 * NN + xx;
    __nv_bfloat16* wbl = g_wb16l + (size_t)b * 256 * NN + xx;
    bh[(size_t)256 * NN] = __float2bfloat16(msk);
    bl[(size_t)256 * NN] = __float2bfloat16(0.f);
    #pragma unroll 4
    for (int k = 0; k < KK; k++) {
        float tt = fmaf(d0, sm_modes[2 * k], d1 * sm_modes[2 * k + 1]);
        float s, c;
        __sincosf(tt, &s, &c);
        const float cm = c * msk, smm = s * msk;
        __nv_bfloat16 hi, lo;
        split_bf16(cm, &hi, &lo);
        bh[(size_t)k * NN] = hi; bl[(size_t)k * NN] = lo;
        split_bf16(smm, &hi, &lo);
        bh[(size_t)(128 + k) * NN] = hi; bl[(size_t)(128 + k) * NN] = lo;
        split_bf16(cm * wsz, &hi, &lo);
        wbh[(size_t)k * NN] = hi; wbl[(size_t)k * NN] = lo;
        split_bf16(smm * wsz, &hi, &lo);
        wbh[(size_t)(128 + k) * NN] = hi; wbl[(size_t)(128 + k) * NN] = lo;
    }
    __nv_bfloat16* h16h = g_h16h[0] + (size_t)b * CC * NN + xx;
    __nv_bfloat16* h16l = g_h16l[0] + (size_t)b * CC * NN + xx;
    #pragma unroll 4
    for (int c = 0; c < CC; c++) {
        float v = sm_b[c];
        v = fmaf(i0, sm_w[c], v);
        v = fmaf(i1, sm_w[128 + c], v);
        v = fmaf(i2, sm_w[256 + c], v);
        __nv_bfloat16 hi, lo;
        split_bf16(v, &hi, &lo);
        h16h[(size_t)c * NN] = hi;
        h16l[(size_t)c * NN] = lo;
    }
}

// ---------------- x_0 partials for layer 0 (reads h0 splits) ------------------
__global__ __launch_bounds__(256) void k_x0() {
    const int b = blockIdx.x;
    const int i = blockIdx.y * 8 + (threadIdx.x >> 5);
    const int z = blockIdx.z;
    const int lane = threadIdx.x & 31;
    const int q = NN / 32;    // uint4 (8 bf16) per quarter = 256
    const uint4* hp = (const uint4*)(g_h16h[0] + ((size_t)b * CC + i) * NN) + (size_t)z * q;
    const uint4* lp = (const uint4*)(g_h16l[0] + ((size_t)b * CC + i) * NN) + (size_t)z * q;
    const float4* wp = (const float4*)(g_wm + (size_t)b * NN) + (size_t)z * q * 2;
    float s = 0.f;
    for (int t = lane; t < q; t += 32) {
        uint4 hv = hp[t], lv = lp[t];
        float4 w0 = wp[2 * t], w1 = wp[2 * t + 1];
        float2 v0 = rec2(hv.x, lv.x), v1 = rec2(hv.y, lv.y);
        float2 v2 = rec2(hv.z, lv.z), v3 = rec2(hv.w, lv.w);
        s = fmaf(v0.x, w0.x, s); s = fmaf(v0.y, w0.y, s);
        s = fmaf(v1.x, w0.z, s); s = fmaf(v1.y, w0.w, s);
        s = fmaf(v2.x, w1.x, s); s = fmaf(v2.y, w1.y, s);
        s = fmaf(v3.x, w1.z, s); s = fmaf(v3.y, w1.w, s);
    }
    #pragma unroll
    for (int off = 16; off; off >>= 1) s += __shfl_xor_sync(0xffffffffu, s, off);
    if (!lane) g_x0p[z][b * CC + i] = s;
}

// ---------------- k_mid: fused fmix (bx<128) + f0/conv/pad (bx>=128) ----------
__global__ __launch_bounds__(128) void k_mid(const float* __restrict__ w0,
                                             const float* __restrict__ conv_w,
                                             int l, int npart) {
    const int t = threadIdx.x;
    if (blockIdx.x < 128) {
        // per-k complex mix -> A rows [2f_c, -2f_s]
        const int k = blockIdx.x;
        const int bh = blockIdx.y * 8;
        __shared__ float xc_s[128][8];
        __shared__ float xs_s[128][8];
        #pragma unroll
        for (int b = 0; b < 8; b++) {
            float sc = 0.f, ss = 0.f;
            #pragma unroll
            for (int s = 0; s < NSPLIT; s++) {
                const float* pp = g_part + (((size_t)s * BB + bh + b) * CC + t) * JP;
                sc += pp[k];
                ss += pp[128 + k];
            }
            xc_s[t][b] = sc;
            xs_s[t][b] = -ss;
        }
        __syncthreads();
        float fc[8] = {}, fs[8] = {};
        const float* wcp = g_wct + ((size_t)(l * KK + k)) * CC * CC + t;
        const float* wsp = g_wst + ((size_t)(l * KK + k)) * CC * CC + t;
        #pragma unroll 4
        for (int i = 0; i < 128; i++) {
            const float wcv = wcp[(size_t)i * CC], wsv = wsp[(size_t)i * CC];
            #pragma unroll
            for (int b = 0; b < 8; b++) {
                const float cv = xc_s[i][b], sv = xs_s[i][b];
                fc[b] = fmaf(cv, wcv, fc[b]); fc[b] = fmaf(-sv, wsv, fc[b]);
                fs[b] = fmaf(sv, wcv, fs[b]); fs[b] = fmaf(cv, wsv, fs[b]);
            }
        }
        #pragma unroll
        for (int b = 0; b < 8; b++) {
            const size_t base = ((size_t)(bh + b) * CC + t) * KA;
            __nv_bfloat16 hi, lo;
            split_bf16(2.f * fc[b], &hi, &lo);
            g_Ah[base + k] = hi; g_Al[base + k] = lo;
            split_bf16(-2.f * fs[b], &hi, &lo);
            g_Ah[base + 128 + k] = hi; g_Al[base + 128 + k] = lo;
        }
    } else {
        // f_0 + conv rows + padding of A for one batch
        const int b = (blockIdx.x - 128) + blockIdx.y * 8;
        __shared__ float x0s[128];
        float s = 0.f;
        for (int p = 0; p < npart; p++) s += g_x0p[p][b * CC + t];
        x0s[t] = s;
        __syncthreads();
        float f0 = 0.f;
        const float* w0p = w0 + (size_t)l * CC * CC;
        #pragma unroll 8
        for (int i = 0; i < 128; i++) f0 = fmaf(x0s[i], w0p[(size_t)i * CC + t], f0);
        const size_t base = ((size_t)b * CC + t) * KA;
        __nv_bfloat16 hi, lo;
        split_bf16(f0 * (1.0f / 8192.0f), &hi, &lo);
        g_Ah[base + 256] = hi; g_Al[base + 256] = lo;
        const float* cw = conv_w + ((size_t)(l * CC) + t) * CC;
        #pragma unroll 8
        for (int i = 0; i < 128; i++) {
            split_bf16(cw[i], &hi, &lo);
            g_Ah[base + 257 + i] = hi; g_Al[base + 257 + i] = lo;
        }
        const __nv_bfloat16 z = __float2bfloat16(0.f);
        #pragma unroll
        for (int j = 385; j < KA; j++) { g_Ah[base + j] = z; g_Al[base + j] = z; }
    }
}

// ---------------- final MLP (SIMT fp32) ---------------------------------------
__global__ __launch_bounds__(256) void k_final(const float* __restrict__ fc1_w,
                                               const float* __restrict__ fc1_b,
                                               const float* __restrict__ fc2_w,
                                               const float* __restrict__ fc2_b,
                                               float* __restrict__ out) {
    __shared__ float Hs[8][128];
    __shared__ float Ws[8][128];
    __shared__ float red[16][128];
    const int xt = blockIdx.x, b = blockIdx.y;
    const int tid = threadIdx.x;
    const int tx = tid & 15, ty = tid >> 4;
    const int x0 = xt * 128;
    const float* h = g_h + (size_t)b * CC * NN;
    float acc[8][8];
    #pragma unroll
    for (int i = 0; i < 8; i++)
        #pragma unroll
        for (int j = 0; j < 8; j++) acc[i][j] = 0.f;

    const int lcc = tid >> 5;
    const int lxx = (tid & 31) * 4;
    for (int c0 = 0; c0 < CC; c0 += 8) {
        *(float4*)&Hs[lcc][lxx] = *(const float4*)(h + (size_t)(c0 + lcc) * NN + x0 + lxx);
        *(float4*)&Ws[lcc][lxx] = *(const float4*)(fc1_w + (c0 + lcc) * 128 + lxx);
        __syncthreads();
        #pragma unroll
        for (int cc = 0; cc < 8; cc++) {
            float a[8], bw[8];
            *(float4*)&a[0]  = *(const float4*)&Ws[cc][ty * 8];
            *(float4*)&a[4]  = *(const float4*)&Ws[cc][ty * 8 + 4];
            *(float4*)&bw[0] = *(const float4*)&Hs[cc][tx * 8];
            *(float4*)&bw[4] = *(const float4*)&Hs[cc][tx * 8 + 4];
            #pragma unroll
            for (int i = 0; i < 8; i++)
                #pragma unroll
                for (int j = 0; j < 8; j++) acc[i][j] = fmaf(a[i], bw[j], acc[i][j]);
        }
        __syncthreads();
    }
    float yp[8];
    #pragma unroll
    for (int j = 0; j < 8; j++) yp[j] = 0.f;
    #pragma unroll
    for (int i = 0; i < 8; i++) {
        const int f = ty * 8 + i;
        const float b1 = fc1_b[f], w2 = fc2_w[f];
        #pragma unroll
        for (int j = 0; j < 8; j++) yp[j] = fmaf(w2, gelu_f(acc[i][j] + b1), yp[j]);
    }
    #pragma unroll
    for (int j = 0; j < 8; j++) red[ty][tx * 8 + j] = yp[j];
    __syncthreads();
    if (ty == 0) {
        #pragma unroll
        for (int j = 0; j < 8; j++) {
            float s = fc2_b[0];
            #pragma unroll
            for (int r = 0; r < 16; r++) s += red[r][tx * 8 + j];
            out[(size_t)b * NN + x0 + tx * 8 + j] = s;
        }
    }
}

// ---------------- launch -------------------------------------------------------
extern "C" void kernel_launch(void* const* d_in, const int* in_sizes, int n_in,
                              void* d_out, int out_size) {
    const float* x      = (const float*)d_in[0];
    const float* modes  = (const float*)d_in[1];
    const float* fc0_w  = (const float*)d_in[2];
    const float* fc0_b  = (const float*)d_in[3];
    const float* wc     = (const float*)d_in[4];
    const float* ws     = (const float*)d_in[5];
    const float* w0     = (const float*)d_in[6];
    const float* conv_w = (const float*)d_in[7];
    const float* conv_b = (const float*)d_in[8];
    const float* fc1_w  = (const float*)d_in[9];
    const float* fc1_b  = (const float*)d_in[10];
    const float* fc2_w  = (const float*)d_in[11];
    const float* fc2_b  = (const float*)d_in[12];
    float* out = (float*)d_out;

    const int smem = 2 * (int)STG;   // 64KB
    cudaFuncSetAttribute(k_mma_g1, cudaFuncAttributeMaxDynamicSharedMemorySize, smem);
    cudaFuncSetAttribute(k_mma_g2, cudaFuncAttributeMaxDynamicSharedMemorySize, smem);

    k_wtrans<<<dim3(16, 128, 4), dim3(32, 8)>>>(wc, ws);
    k_pre<<<(BB * NN) / 256, 256>>>(x, modes, fc0_w, fc0_b);
    k_x0<<<dim3(BB, 16, 4), 256>>>();
    for (int l = 0; l < LL; l++) {
        const int cur = l & 1, nxt = cur ^ 1;
        k_mma_g1<<<dim3(2, NSPLIT, BB), 256, smem>>>(cur);
        k_mid<<<dim3(136, 2), 128>>>(w0, conv_w, l, (l == 0) ? 4 : 64);
        k_mma_g2<<<dim3(NN / 128, BB), 256, smem>>>(cur, nxt, conv_b, l,
                                                    (l < LL - 1) ? 1 : 0,
                                                    (l < LL - 1) ? 1 : 0);
    }
    k_final<<<dim3(NN / 128, BB), 256>>>(fc1_w, fc1_b, fc2_w, fc2_b, out);
}

// round 8
// speedup vs baseline: 2.6173x; 1.0949x over previous
#include <cuda_runtime.h>
#include <cuda_bf16.h>
#include <math.h>
#include <stdint.h>

#define BB 16
#define NN 8192
#define CC 128
#define KK 128
#define LL 4
#define JP 256
#define KA 416            // padded K for G2 (385 -> 416 = 13*32)
#define NSPLIT 8
#define KSP (NN / NSPLIT) // 1024

// ---------------- scratch (device globals) ----------------------------------
__device__ float g_wm[BB * NN];                                 // weights*size*mask
__device__ float g_h[(size_t)BB * CC * NN];                     // fp32 h (final layer only)
__device__ __nv_bfloat16 g_h16h[2][(size_t)BB * CC * NN];       // h split hi/lo ping-pong
__device__ __nv_bfloat16 g_h16l[2][(size_t)BB * CC * NN];
__device__ __nv_bfloat16 g_wb16h[(size_t)BB * 256 * NN];        // bases*wsz split [b][j][x]
__device__ __nv_bfloat16 g_wb16l[(size_t)BB * 256 * NN];
__device__ __nv_bfloat16 g_b16h[(size_t)BB * 257 * NN];         // bases split [b][j][x] (j=256 mask)
__device__ __nv_bfloat16 g_b16l[(size_t)BB * 257 * NN];
__device__ float g_part[(size_t)NSPLIT * BB * CC * JP];         // G1 split partials
__device__ float g_x0p[64][BB * CC];                            // x0 partials
__device__ __nv_bfloat16 g_Ah[(size_t)BB * CC * KA];            // G2 A split [b][o][j]
__device__ __nv_bfloat16 g_Al[(size_t)BB * CC * KA];
__device__ float g_wct[(size_t)LL * KK * CC * CC];
__device__ float g_wst[(size_t)LL * KK * CC * CC];

__device__ __forceinline__ float gelu_f(float v) {
    return 0.5f * v * (1.0f + erff(v * 0.70710678118654752f));
}
__device__ __forceinline__ void split_bf16(float v, __nv_bfloat16* hi, __nv_bfloat16* lo) {
    __nv_bfloat16 h = __float2bfloat16(v);
    *hi = h;
    *lo = __float2bfloat16(v - __bfloat162float(h));
}
__device__ __forceinline__ uint32_t smem_to_u32(const void* p) {
    uint32_t a;
    asm("{ .reg .u64 t; cvta.to.shared.u64 t, %1; cvt.u32.u64 %0, t; }" : "=r"(a) : "l"(p));
    return a;
}
__device__ __forceinline__ float2 rec2(uint32_t h, uint32_t l) {
    __nv_bfloat162 hh = *(__nv_bfloat162*)&h;
    __nv_bfloat162 ll = *(__nv_bfloat162*)&l;
    return make_float2(__bfloat162float(hh.x) + __bfloat162float(ll.x),
                       __bfloat162float(hh.y) + __bfloat162float(ll.y));
}

// ---------------- mma.sync / ldmatrix / cp.async primitives -----------------
__device__ __forceinline__ void ldsm4(uint32_t (&d)[4], uint32_t a) {
    asm volatile("ldmatrix.sync.aligned.m8n8.x4.shared.b16 {%0,%1,%2,%3}, [%4];"
        : "=r"(d[0]), "=r"(d[1]), "=r"(d[2]), "=r"(d[3]) : "r"(a));
}
__device__ __forceinline__ void ldsm4t(uint32_t (&d)[4], uint32_t a) {
    asm volatile("ldmatrix.sync.aligned.m8n8.x4.trans.shared.b16 {%0,%1,%2,%3}, [%4];"
        : "=r"(d[0]), "=r"(d[1]), "=r"(d[2]), "=r"(d[3]) : "r"(a));
}
__device__ __forceinline__ void mma16816(float (&c)[4], const uint32_t (&a)[4], const uint32_t (&b)[2]) {
    asm volatile("mma.sync.aligned.m16n8k16.row.col.f32.bf16.bf16.f32 "
        "{%0,%1,%2,%3},{%4,%5,%6,%7},{%8,%9},{%0,%1,%2,%3};"
        : "+f"(c[0]), "+f"(c[1]), "+f"(c[2]), "+f"(c[3])
        : "r"(a[0]), "r"(a[1]), "r"(a[2]), "r"(a[3]), "r"(b[0]), "r"(b[1]));
}
__device__ __forceinline__ void cpasync16(uint32_t s, const void* g) {
    asm volatile("cp.async.cg.shared.global [%0], [%1], 16;" :: "r"(s), "l"(g));
}
__device__ __forceinline__ void cpasync16z(uint32_t s, const void* g, int sz) {
    asm volatile("cp.async.cg.shared.global [%0], [%1], 16, %2;" :: "r"(s), "l"(g), "r"(sz));
}
#define CP_COMMIT asm volatile("cp.async.commit_group;" ::: "memory")
#define CP_WAIT0  asm volatile("cp.async.wait_group 0;" ::: "memory")
#define CP_WAIT1  asm volatile("cp.async.wait_group 1;" ::: "memory")

// stage layout (bytes): Ah @0, Al @8192, Bh @16384, Bl @24576; stage = 32KB, 3 stages
#define STG 32768u
#define NSTAGE 3

__device__ __forceinline__ uint32_t swzA(int r, int c) {
    return (uint32_t)(r * 64 + ((c ^ ((r >> 1) & 3)) << 4));
}
__device__ __forceinline__ uint32_t swzB(int r, int c) {
    return (uint32_t)(r * 256 + ((c ^ (r & 7)) << 4));
}

// ---------------- stage fills ------------------------------------------------
__device__ __forceinline__ void fill_g1(uint32_t sb, int k0, int tid,
    const __nv_bfloat16* Ah, const __nv_bfloat16* Al,
    const __nv_bfloat16* Bh, const __nv_bfloat16* Bl)
{
    #pragma unroll
    for (int q = 0; q < 8; q++) {
        const int op = q >> 1;
        const int local = ((q & 1) << 8) + tid;
        const int r = local >> 2, c = local & 3;
        const __nv_bfloat16* base = (op == 0) ? Ah : (op == 1) ? Al : (op == 2) ? Bh : Bl;
        cpasync16(sb + (uint32_t)op * 8192u + swzA(r, c),
                  base + (size_t)r * NN + k0 + c * 8);
    }
}
__device__ __forceinline__ void fill_g2(uint32_t sb, int k0, int tid,
    const __nv_bfloat16* Ah, const __nv_bfloat16* Al,
    const __nv_bfloat16* Bbh, const __nv_bfloat16* Bbl,
    const __nv_bfloat16* Hh, const __nv_bfloat16* Hl)
{
    #pragma unroll
    for (int q = 0; q < 8; q++) {
        const int op = q >> 1;
        const int local = ((q & 1) << 8) + tid;
        if (q < 4) {
            const int r = local >> 2, c = local & 3;
            const __nv_bfloat16* base = (op == 0) ? Ah : Al;
            cpasync16(sb + (uint32_t)op * 8192u + swzA(r, c),
                      base + (size_t)r * KA + k0 + c * 8);
        } else {
            const int r = local >> 4, c = local & 15;
            const int jg = k0 + r;
            const bool ishi = (q < 6);
            const __nv_bfloat16* src;
            int sz = 16;
            if (jg < 257)      src = (ishi ? Bbh : Bbl) + (size_t)jg * NN;
            else if (jg < 385) src = (ishi ? Hh : Hl) + (size_t)(jg - 257) * NN;
            else             { src = ishi ? Bbh : Bbl; sz = 0; }
            cpasync16z(sb + (uint32_t)op * 8192u + swzB(r, c), src + c * 8, sz);
        }
    }
}

// ---------------- warp compute: one k32 chunk, 3-term bf16 emulation --------
// B fragments loaded once per k16; A fragments loaded per-mi (low live range)
template<bool BT>
__device__ __forceinline__ void compute_chunk(uint32_t sb, int wmi, int wni, int lane,
                                              float (&acc)[4][4][4]) {
    #pragma unroll
    for (int k16 = 0; k16 < 2; k16++) {
        uint32_t bh[4][2], bl[4][2];
        #pragma unroll
        for (int g = 0; g < 2; g++) {
            uint32_t t[4], u[4];
            if (!BT) {
                const int r = wni * 32 + g * 16 + (lane & 15);
                const int c = k16 * 2 + (lane >> 4);
                const uint32_t bd = sb + 16384u + swzA(r, c);
                ldsm4(t, bd);
                ldsm4(u, bd + 8192u);
                bh[g*2+0][0] = t[0]; bh[g*2+0][1] = t[2];
                bh[g*2+1][0] = t[1]; bh[g*2+1][1] = t[3];
                bl[g*2+0][0] = u[0]; bl[g*2+0][1] = u[2];
                bl[g*2+1][0] = u[1]; bl[g*2+1][1] = u[3];
            } else {
                const int r = k16 * 16 + (lane & 15);
                const int c = wni * 4 + g * 2 + (lane >> 4);
                const uint32_t bd = sb + 16384u + swzB(r, c);
                ldsm4t(t, bd);
                ldsm4t(u, bd + 8192u);
                bh[g*2+0][0] = t[0]; bh[g*2+0][1] = t[1];
                bh[g*2+1][0] = t[2]; bh[g*2+1][1] = t[3];
                bl[g*2+0][0] = u[0]; bl[g*2+0][1] = u[1];
                bl[g*2+1][0] = u[2]; bl[g*2+1][1] = u[3];
            }
        }
        #pragma unroll
        for (int mi = 0; mi < 4; mi++) {
            uint32_t ah[4], al[4];
            {
                const int r = wmi * 64 + mi * 16 + (lane & 15);
                const int c = k16 * 2 + (lane >> 4);
                const uint32_t ad = sb + swzA(r, c);
                ldsm4(ah, ad);
                ldsm4(al, ad + 8192u);
            }
            #pragma unroll
            for (int ni = 0; ni < 4; ni++) {
                mma16816(acc[mi][ni], ah, bh[ni]);
                mma16816(acc[mi][ni], ah, bl[ni]);
                mma16816(acc[mi][ni], al, bh[ni]);
            }
        }
    }
}

// ---------------- G1: D[i=128][j=128-tile] = sum_x h*wb ----------------------
__global__ __launch_bounds__(256, 2) void k_mma_g1(int cur) {
    extern __shared__ __align__(128) char dsm[];
    const uint32_t sb0 = smem_to_u32(dsm);
    const int tid = threadIdx.x, lane = tid & 31, wid = tid >> 5;
    const int wmi = wid >> 2, wni = wid & 3;
    const int nt = blockIdx.x, sp = blockIdx.y, b = blockIdx.z;
    const __nv_bfloat16* Ah = g_h16h[cur] + (size_t)b * CC * NN + (size_t)sp * KSP;
    const __nv_bfloat16* Al = g_h16l[cur] + (size_t)b * CC * NN + (size_t)sp * KSP;
    const __nv_bfloat16* Bh = g_wb16h + ((size_t)b * 256 + nt * 128) * NN + (size_t)sp * KSP;
    const __nv_bfloat16* Bl = g_wb16l + ((size_t)b * 256 + nt * 128) * NN + (size_t)sp * KSP;
    float acc[4][4][4] = {};
    const int niter = KSP / 32;    // 32
    fill_g1(sb0, 0, tid, Ah, Al, Bh, Bl);
    CP_COMMIT;
    fill_g1(sb0 + STG, 32, tid, Ah, Al, Bh, Bl);
    CP_COMMIT;
    int fs = 2;                    // next stage index to fill
    for (int it = 0; it < niter; ++it) {
        CP_WAIT1;
        __syncthreads();
        if (it + 2 < niter) {
            fill_g1(sb0 + (uint32_t)fs * STG, (it + 2) * 32, tid, Ah, Al, Bh, Bl);
        }
        CP_COMMIT;
        const int cs = (fs + 1 == NSTAGE) ? 0 : fs + 1;   // == it % 3
        compute_chunk<false>(sb0 + (uint32_t)((it % NSTAGE)) * STG, wmi, wni, lane, acc);
        fs = cs;
    }
    float* pp = g_part + (((size_t)sp * BB + b) * CC) * JP + nt * 128;
    #pragma unroll
    for (int mi = 0; mi < 4; mi++) {
        #pragma unroll
        for (int ni = 0; ni < 4; ni++) {
            const int m = wmi * 64 + mi * 16 + (lane >> 2);
            const int n = wni * 32 + ni * 8 + (lane & 3) * 2;
            *(float2*)&pp[(size_t)m * JP + n]       = make_float2(acc[mi][ni][0], acc[mi][ni][1]);
            *(float2*)&pp[(size_t)(m + 8) * JP + n] = make_float2(acc[mi][ni][2], acc[mi][ni][3]);
        }
    }
}

// ---------------- G2: D[o=128][x=128-tile] = sum_j A*[bases;h] ---------------
__global__ __launch_bounds__(256, 2) void k_mma_g2(int cur, int nxt,
                                                   const float* __restrict__ conv_b,
                                                   int l, int dogelu, int dosplit) {
    extern __shared__ __align__(128) char dsm[];
    __shared__ float scb[128];
    __shared__ float s_wm[128];
    __shared__ float s_part[128][16];
    const uint32_t sb0 = smem_to_u32(dsm);
    const int tid = threadIdx.x, lane = tid & 31, wid = tid >> 5;
    const int wmi = wid >> 2, wni = wid & 3;
    const int xt = blockIdx.x, b = blockIdx.y;
    if (tid < 128) {
        scb[tid] = conv_b[l * CC + tid];
        s_wm[tid] = g_wm[(size_t)b * NN + (size_t)xt * 128 + tid];
    }
    const __nv_bfloat16* Ah = g_Ah + (size_t)b * CC * KA;
    const __nv_bfloat16* Al = g_Al + (size_t)b * CC * KA;
    const __nv_bfloat16* Bbh = g_b16h + (size_t)b * 257 * NN + (size_t)xt * 128;
    const __nv_bfloat16* Bbl = g_b16l + (size_t)b * 257 * NN + (size_t)xt * 128;
    const __nv_bfloat16* Hh = g_h16h[cur] + (size_t)b * CC * NN + (size_t)xt * 128;
    const __nv_bfloat16* Hl = g_h16l[cur] + (size_t)b * CC * NN + (size_t)xt * 128;
    float acc[4][4][4] = {};
    const int niter = KA / 32;   // 13
    fill_g2(sb0, 0, tid, Ah, Al, Bbh, Bbl, Hh, Hl);
    CP_COMMIT;
    fill_g2(sb0 + STG, 32, tid, Ah, Al, Bbh, Bbl, Hh, Hl);
    CP_COMMIT;
    int fs = 2;
    for (int it = 0; it < niter; ++it) {
        CP_WAIT1;
        __syncthreads();
        if (it + 2 < niter) {
            fill_g2(sb0 + (uint32_t)fs * STG, (it + 2) * 32, tid, Ah, Al, Bbh, Bbl, Hh, Hl);
        }
        CP_COMMIT;
        const int cs = (fs + 1 == NSTAGE) ? 0 : fs + 1;
        compute_chunk<true>(sb0 + (uint32_t)((it % NSTAGE)) * STG, wmi, wni, lane, acc);
        fs = cs;
    }
    __syncthreads();
    float* hout = g_h + (size_t)b * CC * NN + (size_t)xt * 128;
    __nv_bfloat16* hh = g_h16h[nxt] + (size_t)b * CC * NN + (size_t)xt * 128;
    __nv_bfloat16* hl = g_h16l[nxt] + (size_t)b * CC * NN + (size_t)xt * 128;
    float sx[8] = {};
    #pragma unroll
    for (int mi = 0; mi < 4; mi++) {
        #pragma unroll
        for (int ni = 0; ni < 4; ni++) {
            const int n = wni * 32 + ni * 8 + (lane & 3) * 2;
            #pragma unroll
            for (int half = 0; half < 2; half++) {
                const int o = wmi * 64 + mi * 16 + (lane >> 2) + half * 8;
                float v0 = acc[mi][ni][half * 2 + 0] + scb[o];
                float v1 = acc[mi][ni][half * 2 + 1] + scb[o];
                if (dogelu) { v0 = gelu_f(v0); v1 = gelu_f(v1); }
                if (dosplit) {
                    __nv_bfloat16 h0, l0, h1, l1;
                    split_bf16(v0, &h0, &l0);
                    split_bf16(v1, &h1, &l1);
                    __nv_bfloat162 ph; ph.x = h0; ph.y = h1;
                    __nv_bfloat162 pl; pl.x = l0; pl.y = l1;
                    *(__nv_bfloat162*)&hh[(size_t)o * NN + n] = ph;
                    *(__nv_bfloat162*)&hl[(size_t)o * NN + n] = pl;
                    sx[mi * 2 + half] = fmaf(v0, s_wm[n], sx[mi * 2 + half]);
                    sx[mi * 2 + half] = fmaf(v1, s_wm[n + 1], sx[mi * 2 + half]);
                } else {
                    *(float2*)&hout[(size_t)o * NN + n] = make_float2(v0, v1);
                }
            }
        }
    }
    if (dosplit) {
        const int slot = wni * 4 + (lane & 3);
        #pragma unroll
        for (int mi = 0; mi < 4; mi++)
            #pragma unroll
            for (int half = 0; half < 2; half++) {
                const int o = wmi * 64 + mi * 16 + (lane >> 2) + half * 8;
                s_part[o][slot] = sx[mi * 2 + half];
            }
        __syncthreads();
        if (tid < 128) {
            float s = 0.f;
            #pragma unroll
            for (int q = 0; q < 16; q++) s += s_part[tid][q];
            g_x0p[xt][b * CC + tid] = s;
        }
    }
}

// ---------------- weight transpose (once) ------------------------------------
__global__ void k_wtrans(const float* __restrict__ wc, const float* __restrict__ ws) {
    __shared__ float sm[32][33];
    const int tile = blockIdx.x;
    const int o0 = (tile >> 2) * 32, k0 = (tile & 3) * 32;
    const int i = blockIdx.y, l = blockIdx.z;
    const float scale = 1.0f / 8192.0f;
    for (int w = 0; w < 2; w++) {
        const float* src = w ? ws : wc;
        float* dst = w ? g_wst : g_wct;
        #pragma unroll
        for (int s = 0; s < 4; s++) {
            int oo = threadIdx.y + 8 * s, kk = threadIdx.x;
            sm[oo][kk] = src[(((size_t)l * CC + i) * CC + (o0 + oo)) * KK + (k0 + kk)] * scale;
        }
        __syncthreads();
        #pragma unroll
        for (int s = 0; s < 4; s++) {
            int kk = threadIdx.y + 8 * s, oo = threadIdx.x;
            dst[(((size_t)l * KK + (k0 + kk)) * CC + i) * CC + (o0 + oo)] = sm[oo][kk];
        }
        __syncthreads();
    }
}

// ---------------- precompute: bases16, wb16, wm, h0 splits --------------------
__global__ __launch_bounds__(256) void k_pre(const float* __restrict__ xin,
                                             const float* __restrict__ modes,
                                             const float* __restrict__ fc0_w,
                                             const float* __restrict__ fc0_b) {
    __shared__ float sm_modes[256];
    __shared__ float sm_w[384];
    __shared__ float sm_b[128];
    const int t = threadIdx.x;
    sm_modes[t] = modes[t];
    sm_w[t] = fc0_w[t];
    if (t < 128) { sm_w[256 + t] = fc0_w[256 + t]; sm_b[t] = fc0_b[t]; }
    __syncthreads();

    const int gid = blockIdx.x * 256 + t;
    const int b = gid / NN, xx = gid - b * NN;
    const float* xr = xin + (size_t)gid * 7;
    const float i0 = xr[0], i1 = xr[1], i2 = xr[2];
    const float d0 = xr[3], d1 = xr[4], wgt = xr[5], msk = xr[6];

    const float wsz = wgt * (float)NN;
    g_wm[gid] = wsz * msk;
    __nv_bfloat16* bh = g_b16h + (size_t)b * 257 * NN + xx;
    __nv_bfloat16* bl = g_b16l + (size_t)b * 257 * NN + xx;
    __nv_bfloat16* wbh = g_wb16h + (size_t)b * 256 * NN + xx;
    __nv_bfloat16* wbl = g_wb16l + (size_t)b * 256 * NN + xx;
    bh[(size_t)256 * NN] = __float2bfloat16(msk);
    bl[(size_t)256 * NN] = __float2bfloat16(0.f);
    #pragma unroll 4
    for (int k = 0; k < KK; k++) {
        float tt = fmaf(d0, sm_modes[2 * k], d1 * sm_modes[2 * k + 1]);
        float s, c;
        __sincosf(tt, &s, &c);
        const float cm = c * msk, smm = s * msk;
        __nv_bfloat16 hi, lo;
        split_bf16(cm, &hi, &lo);
        bh[(size_t)k * NN] = hi; bl[(size_t)k * NN] = lo;
        split_bf16(smm, &hi, &lo);
        bh[(size_t)(128 + k) * NN] = hi; bl[(size_t)(128 + k) * NN] = lo;
        split_bf16(cm * wsz, &hi, &lo);
        wbh[(size_t)k * NN] = hi; wbl[(size_t)k * NN] = lo;
        split_bf16(smm * wsz, &hi, &lo);
        wbh[(size_t)(128 + k) * NN] = hi; wbl[(size_t)(128 + k) * NN] = lo;
    }
    __nv_bfloat16* h16h = g_h16h[0] + (size_t)b * CC * NN + xx;
    __nv_bfloat16* h16l = g_h16l[0] + (size_t)b * CC * NN + xx;
    #pragma unroll 4
    for (int c = 0; c < CC; c++) {
        float v = sm_b[c];
        v = fmaf(i0, sm_w[c], v);
        v = fmaf(i1, sm_w[128 + c], v);
        v = fmaf(i2, sm_w[256 + c], v);
        __nv_bfloat16 hi, lo;
        split_bf16(v, &hi, &lo);
        h16h[(size_t)c * NN] = hi;
        h16l[(size_t)c * NN] = lo;
    }
}

// ---------------- x_0 partials for layer 0 (reads h0 splits) ------------------
__global__ __launch_bounds__(256) void k_x0() {
    const int b = blockIdx.x;
    const int i = blockIdx.y * 8 + (threadIdx.x >> 5);
    const int z = blockIdx.z;
    const int lane = threadIdx.x & 31;
    const int q = NN / 32;    // uint4 (8 bf16) per quarter = 256
    const uint4* hp = (const uint4*)(g_h16h[0] + ((size_t)b * CC + i) * NN) + (size_t)z * q;
    const uint4* lp = (const uint4*)(g_h16l[0] + ((size_t)b * CC + i) * NN) + (size_t)z * q;
    const float4* wp = (const float4*)(g_wm + (size_t)b * NN) + (size_t)z * q * 2;
    float s = 0.f;
    for (int t = lane; t < q; t += 32) {
        uint4 hv = hp[t], lv = lp[t];
        float4 w0 = wp[2 * t], w1 = wp[2 * t + 1];
        float2 v0 = rec2(hv.x, lv.x), v1 = rec2(hv.y, lv.y);
        float2 v2 = rec2(hv.z, lv.z), v3 = rec2(hv.w, lv.w);
        s = fmaf(v0.x, w0.x, s); s = fmaf(v0.y, w0.y, s);
        s = fmaf(v1.x, w0.z, s); s = fmaf(v1.y, w0.w, s);
        s = fmaf(v2.x, w1.x, s); s = fmaf(v2.y, w1.y, s);
        s = fmaf(v3.x, w1.z, s); s = fmaf(v3.y, w1.w, s);
    }
    #pragma unroll
    for (int off = 16; off; off >>= 1) s += __shfl_xor_sync(0xffffffffu, s, off);
    if (!lane) g_x0p[z][b * CC + i] = s;
}

// ---------------- k_mid: fused fmix (bx<128) + f0/conv/pad (bx>=128) ----------
__global__ __launch_bounds__(128) void k_mid(const float* __restrict__ w0,
                                             const float* __restrict__ conv_w,
                                             int l, int npart) {
    const int t = threadIdx.x;
    if (blockIdx.x < 128) {
        // per-k complex mix -> A rows [2f_c, -2f_s]
        const int k = blockIdx.x;
        const int bh = blockIdx.y * 8;
        __shared__ float xc_s[128][8];
        __shared__ float xs_s[128][8];
        #pragma unroll
        for (int b = 0; b < 8; b++) {
            float sc = 0.f, ss = 0.f;
            #pragma unroll
            for (int s = 0; s < NSPLIT; s++) {
                const float* pp = g_part + (((size_t)s * BB + bh + b) * CC + t) * JP;
                sc += pp[k];
                ss += pp[128 + k];
            }
            xc_s[t][b] = sc;
            xs_s[t][b] = -ss;
        }
        __syncthreads();
        float fc[8] = {}, fs[8] = {};
        const float* wcp = g_wct + ((size_t)(l * KK + k)) * CC * CC + t;
        const float* wsp = g_wst + ((size_t)(l * KK + k)) * CC * CC + t;
        #pragma unroll 4
        for (int i = 0; i < 128; i++) {
            const float wcv = wcp[(size_t)i * CC], wsv = wsp[(size_t)i * CC];
            #pragma unroll
            for (int b = 0; b < 8; b++) {
                const float cv = xc_s[i][b], sv = xs_s[i][b];
                fc[b] = fmaf(cv, wcv, fc[b]); fc[b] = fmaf(-sv, wsv, fc[b]);
                fs[b] = fmaf(sv, wcv, fs[b]); fs[b] = fmaf(cv, wsv, fs[b]);
            }
        }
        #pragma unroll
        for (int b = 0; b < 8; b++) {
            const size_t base = ((size_t)(bh + b) * CC + t) * KA;
            __nv_bfloat16 hi, lo;
            split_bf16(2.f * fc[b], &hi, &lo);
            g_Ah[base + k] = hi; g_Al[base + k] = lo;
            split_bf16(-2.f * fs[b], &hi, &lo);
            g_Ah[base + 128 + k] = hi; g_Al[base + 128 + k] = lo;
        }
    } else {
        // f_0 + conv rows + padding of A for one batch
        const int b = (blockIdx.x - 128) + blockIdx.y * 8;
        __shared__ float x0s[128];
        float s = 0.f;
        for (int p = 0; p < npart; p++) s += g_x0p[p][b * CC + t];
        x0s[t] = s;
        __syncthreads();
        float f0 = 0.f;
        const float* w0p = w0 + (size_t)l * CC * CC;
        #pragma unroll 8
        for (int i = 0; i < 128; i++) f0 = fmaf(x0s[i], w0p[(size_t)i * CC + t], f0);
        const size_t base = ((size_t)b * CC + t) * KA;
        __nv_bfloat16 hi, lo;
        split_bf16(f0 * (1.0f / 8192.0f), &hi, &lo);
        g_Ah[base + 256] = hi; g_Al[base + 256] = lo;
        const float* cw = conv_w + ((size_t)(l * CC) + t) * CC;
        #pragma unroll 8
        for (int i = 0; i < 128; i++) {
            split_bf16(cw[i], &hi, &lo);
            g_Ah[base + 257 + i] = hi; g_Al[base + 257 + i] = lo;
        }
        const __nv_bfloat16 z = __float2bfloat16(0.f);
        #pragma unroll
        for (int j = 385; j < KA; j++) { g_Ah[base + j] = z; g_Al[base + j] = z; }
    }
}

// ---------------- final MLP (SIMT fp32) ---------------------------------------
__global__ __launch_bounds__(256) void k_final(const float* __restrict__ fc1_w,
                                               const float* __restrict__ fc1_b,
                                               const float* __restrict__ fc2_w,
                                               const float* __restrict__ fc2_b,
                                               float* __restrict__ out) {
    __shared__ float Hs[8][128];
    __shared__ float Ws[8][128];
    __shared__ float red[16][128];
    const int xt = blockIdx.x, b = blockIdx.y;
    const int tid = threadIdx.x;
    const int tx = tid & 15, ty = tid >> 4;
    const int x0 = xt * 128;
    const float* h = g_h + (size_t)b * CC * NN;
    float acc[8][8];
    #pragma unroll
    for (int i = 0; i < 8; i++)
        #pragma unroll
        for (int j = 0; j < 8; j++) acc[i][j] = 0.f;

    const int lcc = tid >> 5;
    const int lxx = (tid & 31) * 4;
    for (int c0 = 0; c0 < CC; c0 += 8) {
        *(float4*)&Hs[lcc][lxx] = *(const float4*)(h + (size_t)(c0 + lcc) * NN + x0 + lxx);
        *(float4*)&Ws[lcc][lxx] = *(const float4*)(fc1_w + (c0 + lcc) * 128 + lxx);
        __syncthreads();
        #pragma unroll
        for (int cc = 0; cc < 8; cc++) {
            float a[8], bw[8];
            *(float4*)&a[0]  = *(const float4*)&Ws[cc][ty * 8];
            *(float4*)&a[4]  = *(const float4*)&Ws[cc][ty * 8 + 4];
            *(float4*)&bw[0] = *(const float4*)&Hs[cc][tx * 8];
            *(float4*)&bw[4] = *(const float4*)&Hs[cc][tx * 8 + 4];
            #pragma unroll
            for (int i = 0; i < 8; i++)
                #pragma unroll
                for (int j = 0; j < 8; j++) acc[i][j] = fmaf(a[i], bw[j], acc[i][j]);
        }
        __syncthreads();
    }
    float yp[8];
    #pragma unroll
    for (int j = 0; j < 8; j++) yp[j] = 0.f;
    #pragma unroll
    for (int i = 0; i < 8; i++) {
        const int f = ty * 8 + i;
        const float b1 = fc1_b[f], w2 = fc2_w[f];
        #pragma unroll
        for (int j = 0; j < 8; j++) yp[j] = fmaf(w2, gelu_f(acc[i][j] + b1), yp[j]);
    }
    #pragma unroll
    for (int j = 0; j < 8; j++) red[ty][tx * 8 + j] = yp[j];
    __syncthreads();
    if (ty == 0) {
        #pragma unroll
        for (int j = 0; j < 8; j++) {
            float s = fc2_b[0];
            #pragma unroll
            for (int r = 0; r < 16; r++) s += red[r][tx * 8 + j];
            out[(size_t)b * NN + x0 + tx * 8 + j] = s;
        }
    }
}

// ---------------- launch -------------------------------------------------------
extern "C" void kernel_launch(void* const* d_in, const int* in_sizes, int n_in,
                              void* d_out, int out_size) {
    const float* x      = (const float*)d_in[0];
    const float* modes  = (const float*)d_in[1];
    const float* fc0_w  = (const float*)d_in[2];
    const float* fc0_b  = (const float*)d_in[3];
    const float* wc     = (const float*)d_in[4];
    const float* ws     = (const float*)d_in[5];
    const float* w0     = (const float*)d_in[6];
    const float* conv_w = (const float*)d_in[7];
    const float* conv_b = (const float*)d_in[8];
    const float* fc1_w  = (const float*)d_in[9];
    const float* fc1_b  = (const float*)d_in[10];
    const float* fc2_w  = (const float*)d_in[11];
    const float* fc2_b  = (const float*)d_in[12];
    float* out = (float*)d_out;

    const int smem = NSTAGE * (int)STG;   // 96KB
    cudaFuncSetAttribute(k_mma_g1, cudaFuncAttributeMaxDynamicSharedMemorySize, smem);
    cudaFuncSetAttribute(k_mma_g2, cudaFuncAttributeMaxDynamicSharedMemorySize, smem);

    k_wtrans<<<dim3(16, 128, 4), dim3(32, 8)>>>(wc, ws);
    k_pre<<<(BB * NN) / 256, 256>>>(x, modes, fc0_w, fc0_b);
    k_x0<<<dim3(BB, 16, 4), 256>>>();
    for (int l = 0; l < LL; l++) {
        const int cur = l & 1, nxt = cur ^ 1;
        k_mma_g1<<<dim3(2, NSPLIT, BB), 256, smem>>>(cur);
        k_mid<<<dim3(136, 2), 128>>>(w0, conv_w, l, (l == 0) ? 4 : 64);
        k_mma_g2<<<dim3(NN / 128, BB), 256, smem>>>(cur, nxt, conv_b, l,
                                                    (l < LL - 1) ? 1 : 0,
                                                    (l < LL - 1) ? 1 : 0);
    }
    k_final<<<dim3(NN / 128, BB), 256>>>(fc1_w, fc1_b, fc2_w, fc2_b, out);
}

// round 9
// speedup vs baseline: 2.6893x; 1.0275x over previous
#include <cuda_runtime.h>
#include <cuda_bf16.h>
#include <math.h>
#include <stdint.h>

#define BB 16
#define NN 8192
#define CC 128
#define KK 128
#define LL 4
#define JP 256
#define KA 416            // padded K for G2 (385 -> 416 = 13*32)
#define NSPLIT 16
#define KSP (NN / NSPLIT) // 512

// ---------------- scratch (device globals) ----------------------------------
__device__ float g_wm[BB * NN];                                 // weights*size*mask
__device__ __nv_bfloat16 g_h16h[2][(size_t)BB * CC * NN];       // h split hi/lo ping-pong
__device__ __nv_bfloat16 g_h16l[2][(size_t)BB * CC * NN];
__device__ __nv_bfloat16 g_wb16h[(size_t)BB * 256 * NN];        // bases*wsz split [b][j][x]
__device__ __nv_bfloat16 g_wb16l[(size_t)BB * 256 * NN];
__device__ __nv_bfloat16 g_b16h[(size_t)BB * 257 * NN];         // bases split [b][j][x] (j=256 mask)
__device__ __nv_bfloat16 g_b16l[(size_t)BB * 257 * NN];
__device__ float g_part[(size_t)NSPLIT * BB * CC * JP];         // G1 split partials
__device__ float g_x0p[64][BB * CC];                            // x0 partials
__device__ __nv_bfloat16 g_Ah[(size_t)BB * CC * KA];            // G2 A split [b][o][j]
__device__ __nv_bfloat16 g_Al[(size_t)BB * CC * KA];
__device__ __nv_bfloat16 g_fc1h[CC * CC];                       // fc1^T split [f][c]
__device__ __nv_bfloat16 g_fc1l[CC * CC];
__device__ float g_wct[(size_t)LL * KK * CC * CC];
__device__ float g_wst[(size_t)LL * KK * CC * CC];

__device__ __forceinline__ float gelu_f(float v) {
    return 0.5f * v * (1.0f + erff(v * 0.70710678118654752f));
}
__device__ __forceinline__ void split_bf16(float v, __nv_bfloat16* hi, __nv_bfloat16* lo) {
    __nv_bfloat16 h = __float2bfloat16(v);
    *hi = h;
    *lo = __float2bfloat16(v - __bfloat162float(h));
}
__device__ __forceinline__ uint32_t smem_to_u32(const void* p) {
    uint32_t a;
    asm("{ .reg .u64 t; cvta.to.shared.u64 t, %1; cvt.u32.u64 %0, t; }" : "=r"(a) : "l"(p));
    return a;
}
__device__ __forceinline__ float2 rec2(uint32_t h, uint32_t l) {
    __nv_bfloat162 hh = *(__nv_bfloat162*)&h;
    __nv_bfloat162 ll = *(__nv_bfloat162*)&l;
    return make_float2(__bfloat162float(hh.x) + __bfloat162float(ll.x),
                       __bfloat162float(hh.y) + __bfloat162float(ll.y));
}

// ---------------- mma.sync / ldmatrix / cp.async primitives -----------------
__device__ __forceinline__ void ldsm4(uint32_t (&d)[4], uint32_t a) {
    asm volatile("ldmatrix.sync.aligned.m8n8.x4.shared.b16 {%0,%1,%2,%3}, [%4];"
        : "=r"(d[0]), "=r"(d[1]), "=r"(d[2]), "=r"(d[3]) : "r"(a));
}
__device__ __forceinline__ void ldsm4t(uint32_t (&d)[4], uint32_t a) {
    asm volatile("ldmatrix.sync.aligned.m8n8.x4.trans.shared.b16 {%0,%1,%2,%3}, [%4];"
        : "=r"(d[0]), "=r"(d[1]), "=r"(d[2]), "=r"(d[3]) : "r"(a));
}
__device__ __forceinline__ void mma16816(float (&c)[4], const uint32_t (&a)[4], const uint32_t (&b)[2]) {
    asm volatile("mma.sync.aligned.m16n8k16.row.col.f32.bf16.bf16.f32 "
        "{%0,%1,%2,%3},{%4,%5,%6,%7},{%8,%9},{%0,%1,%2,%3};"
        : "+f"(c[0]), "+f"(c[1]), "+f"(c[2]), "+f"(c[3])
        : "r"(a[0]), "r"(a[1]), "r"(a[2]), "r"(a[3]), "r"(b[0]), "r"(b[1]));
}
__device__ __forceinline__ void cpasync16(uint32_t s, const void* g) {
    asm volatile("cp.async.cg.shared.global [%0], [%1], 16;" :: "r"(s), "l"(g));
}
__device__ __forceinline__ void cpasync16z(uint32_t s, const void* g, int sz) {
    asm volatile("cp.async.cg.shared.global [%0], [%1], 16, %2;" :: "r"(s), "l"(g), "r"(sz));
}
#define CP_COMMIT asm volatile("cp.async.commit_group;" ::: "memory")
#define CP_WAIT0  asm volatile("cp.async.wait_group 0;" ::: "memory")
#define CP_WAIT1  asm volatile("cp.async.wait_group 1;" ::: "memory")

// stage layout (bytes): Ah @0, Al @8192, Bh @16384, Bl @24576; stage = 32KB, 3 stages
#define STG 32768u
#define NSTAGE 3

__device__ __forceinline__ uint32_t swzA(int r, int c) {
    return (uint32_t)(r * 64 + ((c ^ ((r >> 1) & 3)) << 4));
}
__device__ __forceinline__ uint32_t swzB(int r, int c) {
    return (uint32_t)(r * 256 + ((c ^ (r & 7)) << 4));
}

// ---------------- stage fills ------------------------------------------------
__device__ __forceinline__ void fill_g1(uint32_t sb, int k0, int tid,
    const __nv_bfloat16* Ah, const __nv_bfloat16* Al,
    const __nv_bfloat16* Bh, const __nv_bfloat16* Bl)
{
    #pragma unroll
    for (int q = 0; q < 8; q++) {
        const int op = q >> 1;
        const int local = ((q & 1) << 8) + tid;
        const int r = local >> 2, c = local & 3;
        const __nv_bfloat16* base = (op == 0) ? Ah : (op == 1) ? Al : (op == 2) ? Bh : Bl;
        cpasync16(sb + (uint32_t)op * 8192u + swzA(r, c),
                  base + (size_t)r * NN + k0 + c * 8);
    }
}
__device__ __forceinline__ void fill_g2(uint32_t sb, int k0, int tid,
    const __nv_bfloat16* Ah, const __nv_bfloat16* Al,
    const __nv_bfloat16* Bbh, const __nv_bfloat16* Bbl,
    const __nv_bfloat16* Hh, const __nv_bfloat16* Hl)
{
    #pragma unroll
    for (int q = 0; q < 8; q++) {
        const int op = q >> 1;
        const int local = ((q & 1) << 8) + tid;
        if (q < 4) {
            const int r = local >> 2, c = local & 3;
            const __nv_bfloat16* base = (op == 0) ? Ah : Al;
            cpasync16(sb + (uint32_t)op * 8192u + swzA(r, c),
                      base + (size_t)r * KA + k0 + c * 8);
        } else {
            const int r = local >> 4, c = local & 15;
            const int jg = k0 + r;
            const bool ishi = (q < 6);
            const __nv_bfloat16* src;
            int sz = 16;
            if (jg < 257)      src = (ishi ? Bbh : Bbl) + (size_t)jg * NN;
            else if (jg < 385) src = (ishi ? Hh : Hl) + (size_t)(jg - 257) * NN;
            else             { src = ishi ? Bbh : Bbl; sz = 0; }
            cpasync16z(sb + (uint32_t)op * 8192u + swzB(r, c), src + c * 8, sz);
        }
    }
}
// final-MLP fill: A = fc1T splits (stride 128), B rows all from h splits (stride NN)
__device__ __forceinline__ void fill_fc(uint32_t sb, int k0, int tid,
    const __nv_bfloat16* Hh, const __nv_bfloat16* Hl)
{
    #pragma unroll
    for (int q = 0; q < 8; q++) {
        const int op = q >> 1;
        const int local = ((q & 1) << 8) + tid;
        if (q < 4) {
            const int r = local >> 2, c = local & 3;
            const __nv_bfloat16* base = (op == 0) ? g_fc1h : g_fc1l;
            cpasync16(sb + (uint32_t)op * 8192u + swzA(r, c),
                      base + (size_t)r * CC + k0 + c * 8);
        } else {
            const int r = local >> 4, c = local & 15;
            const __nv_bfloat16* src = ((q < 6) ? Hh : Hl) + (size_t)(k0 + r) * NN;
            cpasync16(sb + (uint32_t)op * 8192u + swzB(r, c), src + c * 8);
        }
    }
}

// ---------------- warp compute: one k32 chunk, 3-term bf16 emulation --------
template<bool BT>
__device__ __forceinline__ void compute_chunk(uint32_t sb, int wmi, int wni, int lane,
                                              float (&acc)[4][4][4]) {
    #pragma unroll
    for (int k16 = 0; k16 < 2; k16++) {
        uint32_t bh[4][2], bl[4][2];
        #pragma unroll
        for (int g = 0; g < 2; g++) {
            uint32_t t[4], u[4];
            if (!BT) {
                const int r = wni * 32 + g * 16 + (lane & 15);
                const int c = k16 * 2 + (lane >> 4);
                const uint32_t bd = sb + 16384u + swzA(r, c);
                ldsm4(t, bd);
                ldsm4(u, bd + 8192u);
                bh[g*2+0][0] = t[0]; bh[g*2+0][1] = t[2];
                bh[g*2+1][0] = t[1]; bh[g*2+1][1] = t[3];
                bl[g*2+0][0] = u[0]; bl[g*2+0][1] = u[2];
                bl[g*2+1][0] = u[1]; bl[g*2+1][1] = u[3];
            } else {
                const int r = k16 * 16 + (lane & 15);
                const int c = wni * 4 + g * 2 + (lane >> 4);
                const uint32_t bd = sb + 16384u + swzB(r, c);
                ldsm4t(t, bd);
                ldsm4t(u, bd + 8192u);
                bh[g*2+0][0] = t[0]; bh[g*2+0][1] = t[1];
                bh[g*2+1][0] = t[2]; bh[g*2+1][1] = t[3];
                bl[g*2+0][0] = u[0]; bl[g*2+0][1] = u[1];
                bl[g*2+1][0] = u[2]; bl[g*2+1][1] = u[3];
            }
        }
        #pragma unroll
        for (int mi = 0; mi < 4; mi++) {
            uint32_t ah[4], al[4];
            {
                const int r = wmi * 64 + mi * 16 + (lane & 15);
                const int c = k16 * 2 + (lane >> 4);
                const uint32_t ad = sb + swzA(r, c);
                ldsm4(ah, ad);
                ldsm4(al, ad + 8192u);
            }
            #pragma unroll
            for (int ni = 0; ni < 4; ni++) {
                mma16816(acc[mi][ni], ah, bh[ni]);
                mma16816(acc[mi][ni], ah, bl[ni]);
                mma16816(acc[mi][ni], al, bh[ni]);
            }
        }
    }
}

// ---------------- G1: D[i=128][j=128-tile] = sum_x h*wb ----------------------
__global__ __launch_bounds__(256, 2) void k_mma_g1(int cur) {
    extern __shared__ __align__(128) char dsm[];
    const uint32_t sb0 = smem_to_u32(dsm);
    const int tid = threadIdx.x, lane = tid & 31, wid = tid >> 5;
    const int wmi = wid >> 2, wni = wid & 3;
    const int nt = blockIdx.x, sp = blockIdx.y, b = blockIdx.z;
    const __nv_bfloat16* Ah = g_h16h[cur] + (size_t)b * CC * NN + (size_t)sp * KSP;
    const __nv_bfloat16* Al = g_h16l[cur] + (size_t)b * CC * NN + (size_t)sp * KSP;
    const __nv_bfloat16* Bh = g_wb16h + ((size_t)b * 256 + nt * 128) * NN + (size_t)sp * KSP;
    const __nv_bfloat16* Bl = g_wb16l + ((size_t)b * 256 + nt * 128) * NN + (size_t)sp * KSP;
    float acc[4][4][4] = {};
    const int niter = KSP / 32;    // 16
    fill_g1(sb0, 0, tid, Ah, Al, Bh, Bl);
    CP_COMMIT;
    fill_g1(sb0 + STG, 32, tid, Ah, Al, Bh, Bl);
    CP_COMMIT;
    int fs = 2;
    for (int it = 0; it < niter; ++it) {
        CP_WAIT1;
        __syncthreads();
        if (it + 2 < niter) {
            fill_g1(sb0 + (uint32_t)fs * STG, (it + 2) * 32, tid, Ah, Al, Bh, Bl);
        }
        CP_COMMIT;
        const int cs = (fs + 1 == NSTAGE) ? 0 : fs + 1;
        compute_chunk<false>(sb0 + (uint32_t)((it % NSTAGE)) * STG, wmi, wni, lane, acc);
        fs = cs;
    }
    float* pp = g_part + (((size_t)sp * BB + b) * CC) * JP + nt * 128;
    #pragma unroll
    for (int mi = 0; mi < 4; mi++) {
        #pragma unroll
        for (int ni = 0; ni < 4; ni++) {
            const int m = wmi * 64 + mi * 16 + (lane >> 2);
            const int n = wni * 32 + ni * 8 + (lane & 3) * 2;
            *(float2*)&pp[(size_t)m * JP + n]       = make_float2(acc[mi][ni][0], acc[mi][ni][1]);
            *(float2*)&pp[(size_t)(m + 8) * JP + n] = make_float2(acc[mi][ni][2], acc[mi][ni][3]);
        }
    }
}

// ---------------- G2: D[o=128][x=128-tile] = sum_j A*[bases;h] ---------------
__global__ __launch_bounds__(256, 2) void k_mma_g2(int cur, int nxt,
                                                   const float* __restrict__ conv_b,
                                                   int l, int dogelu, int dox0) {
    extern __shared__ __align__(128) char dsm[];
    __shared__ float scb[128];
    __shared__ float s_wm[128];
    __shared__ float s_part[128][16];
    const uint32_t sb0 = smem_to_u32(dsm);
    const int tid = threadIdx.x, lane = tid & 31, wid = tid >> 5;
    const int wmi = wid >> 2, wni = wid & 3;
    const int xt = blockIdx.x, b = blockIdx.y;
    if (tid < 128) {
        scb[tid] = conv_b[l * CC + tid];
        s_wm[tid] = g_wm[(size_t)b * NN + (size_t)xt * 128 + tid];
    }
    const __nv_bfloat16* Ah = g_Ah + (size_t)b * CC * KA;
    const __nv_bfloat16* Al = g_Al + (size_t)b * CC * KA;
    const __nv_bfloat16* Bbh = g_b16h + (size_t)b * 257 * NN + (size_t)xt * 128;
    const __nv_bfloat16* Bbl = g_b16l + (size_t)b * 257 * NN + (size_t)xt * 128;
    const __nv_bfloat16* Hh = g_h16h[cur] + (size_t)b * CC * NN + (size_t)xt * 128;
    const __nv_bfloat16* Hl = g_h16l[cur] + (size_t)b * CC * NN + (size_t)xt * 128;
    float acc[4][4][4] = {};
    const int niter = KA / 32;   // 13
    fill_g2(sb0, 0, tid, Ah, Al, Bbh, Bbl, Hh, Hl);
    CP_COMMIT;
    fill_g2(sb0 + STG, 32, tid, Ah, Al, Bbh, Bbl, Hh, Hl);
    CP_COMMIT;
    int fs = 2;
    for (int it = 0; it < niter; ++it) {
        CP_WAIT1;
        __syncthreads();
        if (it + 2 < niter) {
            fill_g2(sb0 + (uint32_t)fs * STG, (it + 2) * 32, tid, Ah, Al, Bbh, Bbl, Hh, Hl);
        }
        CP_COMMIT;
        const int cs = (fs + 1 == NSTAGE) ? 0 : fs + 1;
        compute_chunk<true>(sb0 + (uint32_t)((it % NSTAGE)) * STG, wmi, wni, lane, acc);
        fs = cs;
    }
    __syncthreads();
    __nv_bfloat16* hh = g_h16h[nxt] + (size_t)b * CC * NN + (size_t)xt * 128;
    __nv_bfloat16* hl = g_h16l[nxt] + (size_t)b * CC * NN + (size_t)xt * 128;
    float sx[8] = {};
    #pragma unroll
    for (int mi = 0; mi < 4; mi++) {
        #pragma unroll
        for (int ni = 0; ni < 4; ni++) {
            const int n = wni * 32 + ni * 8 + (lane & 3) * 2;
            #pragma unroll
            for (int half = 0; half < 2; half++) {
                const int o = wmi * 64 + mi * 16 + (lane >> 2) + half * 8;
                float v0 = acc[mi][ni][half * 2 + 0] + scb[o];
                float v1 = acc[mi][ni][half * 2 + 1] + scb[o];
                if (dogelu) { v0 = gelu_f(v0); v1 = gelu_f(v1); }
                __nv_bfloat16 h0, l0, h1, l1;
                split_bf16(v0, &h0, &l0);
                split_bf16(v1, &h1, &l1);
                __nv_bfloat162 ph; ph.x = h0; ph.y = h1;
                __nv_bfloat162 pl; pl.x = l0; pl.y = l1;
                *(__nv_bfloat162*)&hh[(size_t)o * NN + n] = ph;
                *(__nv_bfloat162*)&hl[(size_t)o * NN + n] = pl;
                if (dox0) {
                    sx[mi * 2 + half] = fmaf(v0, s_wm[n], sx[mi * 2 + half]);
                    sx[mi * 2 + half] = fmaf(v1, s_wm[n + 1], sx[mi * 2 + half]);
                }
            }
        }
    }
    if (dox0) {
        const int slot = wni * 4 + (lane & 3);
        #pragma unroll
        for (int mi = 0; mi < 4; mi++)
            #pragma unroll
            for (int half = 0; half < 2; half++) {
                const int o = wmi * 64 + mi * 16 + (lane >> 2) + half * 8;
                s_part[o][slot] = sx[mi * 2 + half];
            }
        __syncthreads();
        if (tid < 128) {
            float s = 0.f;
            #pragma unroll
            for (int q = 0; q < 16; q++) s += s_part[tid][q];
            g_x0p[xt][b * CC + tid] = s;
        }
    }
}

// ---------------- final MLP as MMA: y[x] = fc2 . gelu(fc1T @ h + b1) + b2 ----
__global__ __launch_bounds__(256, 2) void k_final_mma(const float* __restrict__ fc1_b,
                                                      const float* __restrict__ fc2_w,
                                                      const float* __restrict__ fc2_b,
                                                      float* __restrict__ out) {
    extern __shared__ __align__(128) char dsm[];
    __shared__ float s_fb[128];
    __shared__ float s_w2[128];
    __shared__ float s_red[128][17];
    const uint32_t sb0 = smem_to_u32(dsm);
    const int tid = threadIdx.x, lane = tid & 31, wid = tid >> 5;
    const int wmi = wid >> 2, wni = wid & 3;
    const int xt = blockIdx.x, b = blockIdx.y;
    if (tid < 128) { s_fb[tid] = fc1_b[tid]; s_w2[tid] = fc2_w[tid]; }
    const __nv_bfloat16* Hh = g_h16h[0] + (size_t)b * CC * NN + (size_t)xt * 128;
    const __nv_bfloat16* Hl = g_h16l[0] + (size_t)b * CC * NN + (size_t)xt * 128;
    float acc[4][4][4] = {};
    const int niter = CC / 32;   // 4
    fill_fc(sb0, 0, tid, Hh, Hl);
    CP_COMMIT;
    fill_fc(sb0 + STG, 32, tid, Hh, Hl);
    CP_COMMIT;
    int fs = 2;
    for (int it = 0; it < niter; ++it) {
        CP_WAIT1;
        __syncthreads();
        if (it + 2 < niter) {
            fill_fc(sb0 + (uint32_t)fs * STG, (it + 2) * 32, tid, Hh, Hl);
        }
        CP_COMMIT;
        const int cs = (fs + 1 == NSTAGE) ? 0 : fs + 1;
        compute_chunk<true>(sb0 + (uint32_t)((it % NSTAGE)) * STG, wmi, wni, lane, acc);
        fs = cs;
    }
    __syncthreads();
    // epilogue: v = gelu(d + fc1_b[f]) * fc2_w[f]; reduce over f per x
    float xs[8] = {};
    #pragma unroll
    for (int mi = 0; mi < 4; mi++) {
        #pragma unroll
        for (int ni = 0; ni < 4; ni++) {
            #pragma unroll
            for (int half = 0; half < 2; half++) {
                const int f = wmi * 64 + mi * 16 + (lane >> 2) + half * 8;
                const float w2 = s_w2[f], b1 = s_fb[f];
                xs[ni * 2 + 0] = fmaf(w2, gelu_f(acc[mi][ni][half * 2 + 0] + b1), xs[ni * 2 + 0]);
                xs[ni * 2 + 1] = fmaf(w2, gelu_f(acc[mi][ni][half * 2 + 1] + b1), xs[ni * 2 + 1]);
            }
        }
    }
    const int slot = wmi * 8 + (lane >> 2);
    #pragma unroll
    for (int ni = 0; ni < 4; ni++) {
        #pragma unroll
        for (int p = 0; p < 2; p++) {
            const int x = wni * 32 + ni * 8 + (lane & 3) * 2 + p;
            if (wmi == 0 && (lane >> 2) == 0) s_red[x][16] = 0.f;   // (unused pad)
            s_red[x][slot] = (slot == 0) ? xs[ni * 2 + p] : xs[ni * 2 + p];
        }
    }
    __syncthreads();
    if (tid < 128) {
        float s = fc2_b[0];
        #pragma unroll
        for (int q = 0; q < 16; q++) s += s_red[tid][q];
        out[(size_t)b * NN + (size_t)xt * 128 + tid] = s;
    }
}

// ---------------- weight transpose (once) ------------------------------------
__global__ void k_wtrans(const float* __restrict__ wc, const float* __restrict__ ws) {
    __shared__ float sm[32][33];
    const int tile = blockIdx.x;
    const int o0 = (tile >> 2) * 32, k0 = (tile & 3) * 32;
    const int i = blockIdx.y, l = blockIdx.z;
    const float scale = 1.0f / 8192.0f;
    for (int w = 0; w < 2; w++) {
        const float* src = w ? ws : wc;
        float* dst = w ? g_wst : g_wct;
        #pragma unroll
        for (int s = 0; s < 4; s++) {
            int oo = threadIdx.y + 8 * s, kk = threadIdx.x;
            sm[oo][kk] = src[(((size_t)l * CC + i) * CC + (o0 + oo)) * KK + (k0 + kk)] * scale;
        }
        __syncthreads();
        #pragma unroll
        for (int s = 0; s < 4; s++) {
            int kk = threadIdx.y + 8 * s, oo = threadIdx.x;
            dst[(((size_t)l * KK + (k0 + kk)) * CC + i) * CC + (o0 + oo)] = sm[oo][kk];
        }
        __syncthreads();
    }
}

// ---------------- fc1^T split prep (once, tiny) -------------------------------
__global__ void k_prepfc(const float* __restrict__ fc1_w) {
    const int f = blockIdx.x, c = threadIdx.x;
    __nv_bfloat16 hi, lo;
    split_bf16(fc1_w[c * CC + f], &hi, &lo);
    g_fc1h[f * CC + c] = hi;
    g_fc1l[f * CC + c] = lo;
}

// ---------------- precompute: bases16, wb16, wm, h0 splits --------------------
__global__ __launch_bounds__(256) void k_pre(const float* __restrict__ xin,
                                             const float* __restrict__ modes,
                                             const float* __restrict__ fc0_w,
                                             const float* __restrict__ fc0_b) {
    __shared__ float sm_modes[256];
    __shared__ float sm_w[384];
    __shared__ float sm_b[128];
    const int t = threadIdx.x;
    sm_modes[t] = modes[t];
    sm_w[t] = fc0_w[t];
    if (t < 128) { sm_w[256 + t] = fc0_w[256 + t]; sm_b[t] = fc0_b[t]; }
    __syncthreads();

    const int gid = blockIdx.x * 256 + t;
    const int b = gid / NN, xx = gid - b * NN;
    const float* xr = xin + (size_t)gid * 7;
    const float i0 = xr[0], i1 = xr[1], i2 = xr[2];
    const float d0 = xr[3], d1 = xr[4], wgt = xr[5], msk = xr[6];

    const float wsz = wgt * (float)NN;
    g_wm[gid] = wsz * msk;
    __nv_bfloat16* bh = g_b16h + (size_t)b * 257 * NN + xx;
    __nv_bfloat16* bl = g_b16l + (size_t)b * 257 * NN + xx;
    __nv_bfloat16* wbh = g_wb16h + (size_t)b * 256 * NN + xx;
    __nv_bfloat16* wbl = g_wb16l + (size_t)b * 256 * NN + xx;
    bh[(size_t)256 * NN] = __float2bfloat16(msk);
    bl[(size_t)256 * NN] = __float2bfloat16(0.f);
    #pragma unroll 4
    for (int k = 0; k < KK; k++) {
        float tt = fmaf(d0, sm_modes[2 * k], d1 * sm_modes[2 * k + 1]);
        float s, c;
        __sincosf(tt, &s, &c);
        const float cm = c * msk, smm = s * msk;
        __nv_bfloat16 hi, lo;
        split_bf16(cm, &hi, &lo);
        bh[(size_t)k * NN] = hi; bl[(size_t)k * NN] = lo;
        split_bf16(smm, &hi, &lo);
        bh[(size_t)(128 + k) * NN] = hi; bl[(size_t)(128 + k) * NN] = lo;
        split_bf16(cm * wsz, &hi, &lo);
        wbh[(size_t)k * NN] = hi; wbl[(size_t)k * NN] = lo;
        split_bf16(smm * wsz, &hi, &lo);
        wbh[(size_t)(128 + k) * NN] = hi; wbl[(size_t)(128 + k) * NN] = lo;
    }
    __nv_bfloat16* h16h = g_h16h[0] + (size_t)b * CC * NN + xx;
    __nv_bfloat16* h16l = g_h16l[0] + (size_t)b * CC * NN + xx;
    #pragma unroll 4
    for (int c = 0; c < CC; c++) {
        float v = sm_b[c];
        v = fmaf(i0, sm_w[c], v);
        v = fmaf(i1, sm_w[128 + c], v);
        v = fmaf(i2, sm_w[256 + c], v);
        __nv_bfloat16 hi, lo;
        split_bf16(v, &hi, &lo);
        h16h[(size_t)c * NN] = hi;
        h16l[(size_t)c * NN] = lo;
    }
}

// ---------------- x_0 partials for layer 0 (reads h0 splits) ------------------
__global__ __launch_bounds__(256) void k_x0() {
    const int b = blockIdx.x;
    const int i = blockIdx.y * 8 + (threadIdx.x >> 5);
    const int z = blockIdx.z;
    const int lane = threadIdx.x & 31;
    const int q = NN / 32;
    const uint4* hp = (const uint4*)(g_h16h[0] + ((size_t)b * CC + i) * NN) + (size_t)z * q;
    const uint4* lp = (const uint4*)(g_h16l[0] + ((size_t)b * CC + i) * NN) + (size_t)z * q;
    const float4* wp = (const float4*)(g_wm + (size_t)b * NN) + (size_t)z * q * 2;
    float s = 0.f;
    for (int t = lane; t < q; t += 32) {
        uint4 hv = hp[t], lv = lp[t];
        float4 w0 = wp[2 * t], w1 = wp[2 * t + 1];
        float2 v0 = rec2(hv.x, lv.x), v1 = rec2(hv.y, lv.y);
        float2 v2 = rec2(hv.z, lv.z), v3 = rec2(hv.w, lv.w);
        s = fmaf(v0.x, w0.x, s); s = fmaf(v0.y, w0.y, s);
        s = fmaf(v1.x, w0.z, s); s = fmaf(v1.y, w0.w, s);
        s = fmaf(v2.x, w1.x, s); s = fmaf(v2.y, w1.y, s);
        s = fmaf(v3.x, w1.z, s); s = fmaf(v3.y, w1.w, s);
    }
    #pragma unroll
    for (int off = 16; off; off >>= 1) s += __shfl_xor_sync(0xffffffffu, s, off);
    if (!lane) g_x0p[z][b * CC + i] = s;
}

// ---------------- k_mid: fused fmix (bx<128) + f0/conv/pad (bx>=128) ----------
__global__ __launch_bounds__(128) void k_mid(const float* __restrict__ w0,
                                             const float* __restrict__ conv_w,
                                             int l, int npart) {
    const int t = threadIdx.x;
    if (blockIdx.x < 128) {
        const int k = blockIdx.x;
        const int bh = blockIdx.y * 8;
        __shared__ float xc_s[128][8];
        __shared__ float xs_s[128][8];
        #pragma unroll
        for (int b = 0; b < 8; b++) {
            float sc = 0.f, ss = 0.f;
            #pragma unroll
            for (int s = 0; s < NSPLIT; s++) {
                const float* pp = g_part + (((size_t)s * BB + bh + b) * CC + t) * JP;
                sc += pp[k];
                ss += pp[128 + k];
            }
            xc_s[t][b] = sc;
            xs_s[t][b] = -ss;
        }
        __syncthreads();
        float fc[8] = {}, fs[8] = {};
        const float* wcp = g_wct + ((size_t)(l * KK + k)) * CC * CC + t;
        const float* wsp = g_wst + ((size_t)(l * KK + k)) * CC * CC + t;
        #pragma unroll 4
        for (int i = 0; i < 128; i++) {
            const float wcv = wcp[(size_t)i * CC], wsv = wsp[(size_t)i * CC];
            #pragma unroll
            for (int b = 0; b < 8; b++) {
                const float cv = xc_s[i][b], sv = xs_s[i][b];
                fc[b] = fmaf(cv, wcv, fc[b]); fc[b] = fmaf(-sv, wsv, fc[b]);
                fs[b] = fmaf(sv, wcv, fs[b]); fs[b] = fmaf(cv, wsv, fs[b]);
            }
        }
        #pragma unroll
        for (int b = 0; b < 8; b++) {
            const size_t base = ((size_t)(bh + b) * CC + t) * KA;
            __nv_bfloat16 hi, lo;
            split_bf16(2.f * fc[b], &hi, &lo);
            g_Ah[base + k] = hi; g_Al[base + k] = lo;
            split_bf16(-2.f * fs[b], &hi, &lo);
            g_Ah[base + 128 + k] = hi; g_Al[base + 128 + k] = lo;
        }
    } else {
        const int b = (blockIdx.x - 128) + blockIdx.y * 8;
        __shared__ float x0s[128];
        float s = 0.f;
        for (int p = 0; p < npart; p++) s += g_x0p[p][b * CC + t];
        x0s[t] = s;
        __syncthreads();
        float f0 = 0.f;
        const float* w0p = w0 + (size_t)l * CC * CC;
        #pragma unroll 8
        for (int i = 0; i < 128; i++) f0 = fmaf(x0s[i], w0p[(size_t)i * CC + t], f0);
        const size_t base = ((size_t)b * CC + t) * KA;
        __nv_bfloat16 hi, lo;
        split_bf16(f0 * (1.0f / 8192.0f), &hi, &lo);
        g_Ah[base + 256] = hi; g_Al[base + 256] = lo;
        const float* cw = conv_w + ((size_t)(l * CC) + t) * CC;
        #pragma unroll 8
        for (int i = 0; i < 128; i++) {
            split_bf16(cw[i], &hi, &lo);
            g_Ah[base + 257 + i] = hi; g_Al[base + 257 + i] = lo;
        }
        const __nv_bfloat16 z = __float2bfloat16(0.f);
        #pragma unroll
        for (int j = 385; j < KA; j++) { g_Ah[base + j] = z; g_Al[base + j] = z; }
    }
}

// ---------------- launch -------------------------------------------------------
extern "C" void kernel_launch(void* const* d_in, const int* in_sizes, int n_in,
                              void* d_out, int out_size) {
    const float* x      = (const float*)d_in[0];
    const float* modes  = (const float*)d_in[1];
    const float* fc0_w  = (const float*)d_in[2];
    const float* fc0_b  = (const float*)d_in[3];
    const float* wc     = (const float*)d_in[4];
    const float* ws     = (const float*)d_in[5];
    const float* w0     = (const float*)d_in[6];
    const float* conv_w = (const float*)d_in[7];
    const float* conv_b = (const float*)d_in[8];
    const float* fc1_w  = (const float*)d_in[9];
    const float* fc1_b  = (const float*)d_in[10];
    const float* fc2_w  = (const float*)d_in[11];
    const float* fc2_b  = (const float*)d_in[12];
    float* out = (float*)d_out;

    const int smem = NSTAGE * (int)STG;   // 96KB
    cudaFuncSetAttribute(k_mma_g1, cudaFuncAttributeMaxDynamicSharedMemorySize, smem);
    cudaFuncSetAttribute(k_mma_g2, cudaFuncAttributeMaxDynamicSharedMemorySize, smem);
    cudaFuncSetAttribute(k_final_mma, cudaFuncAttributeMaxDynamicSharedMemorySize, smem);

    k_wtrans<<<dim3(16, 128, 4), dim3(32, 8)>>>(wc, ws);
    k_prepfc<<<CC, CC>>>(fc1_w);
    k_pre<<<(BB * NN) / 256, 256>>>(x, modes, fc0_w, fc0_b);
    k_x0<<<dim3(BB, 16, 4), 256>>>();
    for (int l = 0; l < LL; l++) {
        const int cur = l & 1, nxt = cur ^ 1;
        k_mma_g1<<<dim3(2, NSPLIT, BB), 256, smem>>>(cur);
        k_mid<<<dim3(136, 2), 128>>>(w0, conv_w, l, (l == 0) ? 4 : 64);
        k_mma_g2<<<dim3(NN / 128, BB), 256, smem>>>(cur, nxt, conv_b, l,
                                                    (l < LL - 1) ? 1 : 0,
                                                    (l < LL - 1) ? 1 : 0);
    }
    k_final_mma<<<dim3(NN / 128, BB), 256, smem>>>(fc1_b, fc2_w, fc2_b, out);
}

// round 10
// speedup vs baseline: 2.7774x; 1.0328x over previous
#include <cuda_runtime.h>
#include <cuda_bf16.h>
#include <math.h>
#include <stdint.h>

#define BB 16
#define NN 8192
#define CC 128
#define KK 128
#define LL 4
#define JP 256
#define KA 416            // padded K for G2 (385 -> 416 = 13*32)
#define NSPLIT 8
#define KSP (NN / NSPLIT) // 1024

// ---------------- scratch (device globals) ----------------------------------
__device__ float g_wm[BB * NN];                                 // weights*size*mask
__device__ __nv_bfloat16 g_h16h[2][(size_t)BB * CC * NN];       // h split hi/lo ping-pong
__device__ __nv_bfloat16 g_h16l[2][(size_t)BB * CC * NN];
__device__ __nv_bfloat16 g_wb16h[(size_t)BB * 256 * NN];        // bases*wsz split [b][j][x]
__device__ __nv_bfloat16 g_wb16l[(size_t)BB * 256 * NN];
__device__ __nv_bfloat16 g_b16h[(size_t)BB * 257 * NN];         // bases split [b][j][x] (j=256 mask)
__device__ __nv_bfloat16 g_b16l[(size_t)BB * 257 * NN];
__device__ float g_part[(size_t)NSPLIT * BB * CC * JP];         // G1 split partials
__device__ float g_x0p[64][BB * CC];                            // x0 partials
__device__ __nv_bfloat16 g_Ah[(size_t)BB * CC * KA];            // G2 A split [b][o][j]
__device__ __nv_bfloat16 g_Al[(size_t)BB * CC * KA];
__device__ __nv_bfloat16 g_fc1h[CC * CC];                       // fc1^T split [f][c]
__device__ __nv_bfloat16 g_fc1l[CC * CC];
__device__ float g_wct[(size_t)LL * KK * CC * CC];
__device__ float g_wst[(size_t)LL * KK * CC * CC];

__device__ __forceinline__ float gelu_f(float v) {
    return 0.5f * v * (1.0f + erff(v * 0.70710678118654752f));
}
__device__ __forceinline__ void split_bf16(float v, __nv_bfloat16* hi, __nv_bfloat16* lo) {
    __nv_bfloat16 h = __float2bfloat16(v);
    *hi = h;
    *lo = __float2bfloat16(v - __bfloat162float(h));
}
__device__ __forceinline__ uint32_t pack_split2(float v0, float v1, uint32_t* lo_out) {
    __nv_bfloat16 h0, l0, h1, l1;
    split_bf16(v0, &h0, &l0);
    split_bf16(v1, &h1, &l1);
    __nv_bfloat162 ph; ph.x = h0; ph.y = h1;
    __nv_bfloat162 pl; pl.x = l0; pl.y = l1;
    *lo_out = *(uint32_t*)&pl;
    return *(uint32_t*)&ph;
}
__device__ __forceinline__ uint32_t smem_to_u32(const void* p) {
    uint32_t a;
    asm("{ .reg .u64 t; cvta.to.shared.u64 t, %1; cvt.u32.u64 %0, t; }" : "=r"(a) : "l"(p));
    return a;
}
__device__ __forceinline__ float2 rec2(uint32_t h, uint32_t l) {
    __nv_bfloat162 hh = *(__nv_bfloat162*)&h;
    __nv_bfloat162 ll = *(__nv_bfloat162*)&l;
    return make_float2(__bfloat162float(hh.x) + __bfloat162float(ll.x),
                       __bfloat162float(hh.y) + __bfloat162float(ll.y));
}

// ---------------- FMA-pipe sincos (no MUFU): Cody-Waite + minimax ------------
__device__ __forceinline__ void fast_sincos(float t, float* sout, float* cout) {
    const float fn = rintf(t * 0.636619772f);       // 2/pi
    const int n = (int)fn;
    float r = fmaf(fn, -1.57079637e0f, t);          // pi/2 hi
    r = fmaf(fn, 4.37113883e-8f, r);                // pi/2 lo correction
    const float r2 = r * r;
    float ps = fmaf(fmaf(-1.9515296e-4f, r2, 8.3321608e-3f), r2, -1.6666654e-1f);
    ps = fmaf(ps * r2, r, r);                       // sin(r)
    float pc = fmaf(fmaf(2.44331571e-5f, r2, -1.38873163e-3f), r2, 4.16666456e-2f);
    pc = fmaf(pc, r2 * r2, fmaf(-0.5f, r2, 1.0f));  // cos(r)
    const int q = n & 3;
    float s = (q & 1) ? pc : ps;
    float c = (q & 1) ? ps : pc;
    if ((q + 1) & 2) c = -c;
    if (q & 2) s = -s;
    *sout = s;
    *cout = c;
}

// ---------------- mma.sync / ldmatrix / cp.async primitives -----------------
__device__ __forceinline__ void ldsm4(uint32_t (&d)[4], uint32_t a) {
    asm volatile("ldmatrix.sync.aligned.m8n8.x4.shared.b16 {%0,%1,%2,%3}, [%4];"
        : "=r"(d[0]), "=r"(d[1]), "=r"(d[2]), "=r"(d[3]) : "r"(a));
}
__device__ __forceinline__ void ldsm4t(uint32_t (&d)[4], uint32_t a) {
    asm volatile("ldmatrix.sync.aligned.m8n8.x4.trans.shared.b16 {%0,%1,%2,%3}, [%4];"
        : "=r"(d[0]), "=r"(d[1]), "=r"(d[2]), "=r"(d[3]) : "r"(a));
}
__device__ __forceinline__ void mma16816(float (&c)[4], const uint32_t (&a)[4], const uint32_t (&b)[2]) {
    asm volatile("mma.sync.aligned.m16n8k16.row.col.f32.bf16.bf16.f32 "
        "{%0,%1,%2,%3},{%4,%5,%6,%7},{%8,%9},{%0,%1,%2,%3};"
        : "+f"(c[0]), "+f"(c[1]), "+f"(c[2]), "+f"(c[3])
        : "r"(a[0]), "r"(a[1]), "r"(a[2]), "r"(a[3]), "r"(b[0]), "r"(b[1]));
}
__device__ __forceinline__ void cpasync16(uint32_t s, const void* g) {
    asm volatile("cp.async.cg.shared.global [%0], [%1], 16;" :: "r"(s), "l"(g));
}
__device__ __forceinline__ void cpasync16z(uint32_t s, const void* g, int sz) {
    asm volatile("cp.async.cg.shared.global [%0], [%1], 16, %2;" :: "r"(s), "l"(g), "r"(sz));
}
#define CP_COMMIT asm volatile("cp.async.commit_group;" ::: "memory")
#define CP_WAIT0  asm volatile("cp.async.wait_group 0;" ::: "memory")
#define CP_WAIT1  asm volatile("cp.async.wait_group 1;" ::: "memory")

// stage layout (bytes): Ah @0, Al @8192, Bh @16384, Bl @24576; stage = 32KB, 3 stages
#define STG 32768u
#define NSTAGE 3

__device__ __forceinline__ uint32_t swzA(int r, int c) {
    return (uint32_t)(r * 64 + ((c ^ ((r >> 1) & 3)) << 4));
}
__device__ __forceinline__ uint32_t swzB(int r, int c) {
    return (uint32_t)(r * 256 + ((c ^ (r & 7)) << 4));
}

// ---------------- stage fills ------------------------------------------------
__device__ __forceinline__ void fill_g1(uint32_t sb, int k0, int tid,
    const __nv_bfloat16* Ah, const __nv_bfloat16* Al,
    const __nv_bfloat16* Bh, const __nv_bfloat16* Bl)
{
    #pragma unroll
    for (int q = 0; q < 8; q++) {
        const int op = q >> 1;
        const int local = ((q & 1) << 8) + tid;
        const int r = local >> 2, c = local & 3;
        const __nv_bfloat16* base = (op == 0) ? Ah : (op == 1) ? Al : (op == 2) ? Bh : Bl;
        cpasync16(sb + (uint32_t)op * 8192u + swzA(r, c),
                  base + (size_t)r * NN + k0 + c * 8);
    }
}
__device__ __forceinline__ void fill_g2(uint32_t sb, int k0, int tid,
    const __nv_bfloat16* Ah, const __nv_bfloat16* Al,
    const __nv_bfloat16* Bbh, const __nv_bfloat16* Bbl,
    const __nv_bfloat16* Hh, const __nv_bfloat16* Hl)
{
    #pragma unroll
    for (int q = 0; q < 8; q++) {
        const int op = q >> 1;
        const int local = ((q & 1) << 8) + tid;
        if (q < 4) {
            const int r = local >> 2, c = local & 3;
            const __nv_bfloat16* base = (op == 0) ? Ah : Al;
            cpasync16(sb + (uint32_t)op * 8192u + swzA(r, c),
                      base + (size_t)r * KA + k0 + c * 8);
        } else {
            const int r = local >> 4, c = local & 15;
            const int jg = k0 + r;
            const bool ishi = (q < 6);
            const __nv_bfloat16* src;
            int sz = 16;
            if (jg < 257)      src = (ishi ? Bbh : Bbl) + (size_t)jg * NN;
            else if (jg < 385) src = (ishi ? Hh : Hl) + (size_t)(jg - 257) * NN;
            else             { src = ishi ? Bbh : Bbl; sz = 0; }
            cpasync16z(sb + (uint32_t)op * 8192u + swzB(r, c), src + c * 8, sz);
        }
    }
}
// final-MLP fill: A = fc1T splits (stride 128), B rows all from h splits (stride NN)
__device__ __forceinline__ void fill_fc(uint32_t sb, int k0, int tid,
    const __nv_bfloat16* Hh, const __nv_bfloat16* Hl)
{
    #pragma unroll
    for (int q = 0; q < 8; q++) {
        const int op = q >> 1;
        const int local = ((q & 1) << 8) + tid;
        if (q < 4) {
            const int r = local >> 2, c = local & 3;
            const __nv_bfloat16* base = (op == 0) ? g_fc1h : g_fc1l;
            cpasync16(sb + (uint32_t)op * 8192u + swzA(r, c),
                      base + (size_t)r * CC + k0 + c * 8);
        } else {
            const int r = local >> 4, c = local & 15;
            const __nv_bfloat16* src = ((q < 6) ? Hh : Hl) + (size_t)(k0 + r) * NN;
            cpasync16(sb + (uint32_t)op * 8192u + swzB(r, c), src + c * 8);
        }
    }
}

// ---------------- warp compute: one k32 chunk, 3-term bf16 emulation --------
template<bool BT>
__device__ __forceinline__ void compute_chunk(uint32_t sb, int wmi, int wni, int lane,
                                              float (&acc)[4][4][4]) {
    #pragma unroll
    for (int k16 = 0; k16 < 2; k16++) {
        uint32_t bh[4][2], bl[4][2];
        #pragma unroll
        for (int g = 0; g < 2; g++) {
            uint32_t t[4], u[4];
            if (!BT) {
                const int r = wni * 32 + g * 16 + (lane & 15);
                const int c = k16 * 2 + (lane >> 4);
                const uint32_t bd = sb + 16384u + swzA(r, c);
                ldsm4(t, bd);
                ldsm4(u, bd + 8192u);
                bh[g*2+0][0] = t[0]; bh[g*2+0][1] = t[2];
                bh[g*2+1][0] = t[1]; bh[g*2+1][1] = t[3];
                bl[g*2+0][0] = u[0]; bl[g*2+0][1] = u[2];
                bl[g*2+1][0] = u[1]; bl[g*2+1][1] = u[3];
            } else {
                const int r = k16 * 16 + (lane & 15);
                const int c = wni * 4 + g * 2 + (lane >> 4);
                const uint32_t bd = sb + 16384u + swzB(r, c);
                ldsm4t(t, bd);
                ldsm4t(u, bd + 8192u);
                bh[g*2+0][0] = t[0]; bh[g*2+0][1] = t[1];
                bh[g*2+1][0] = t[2]; bh[g*2+1][1] = t[3];
                bl[g*2+0][0] = u[0]; bl[g*2+0][1] = u[1];
                bl[g*2+1][0] = u[2]; bl[g*2+1][1] = u[3];
            }
        }
        #pragma unroll
        for (int mi = 0; mi < 4; mi++) {
            uint32_t ah[4], al[4];
            {
                const int r = wmi * 64 + mi * 16 + (lane & 15);
                const int c = k16 * 2 + (lane >> 4);
                const uint32_t ad = sb + swzA(r, c);
                ldsm4(ah, ad);
                ldsm4(al, ad + 8192u);
            }
            #pragma unroll
            for (int ni = 0; ni < 4; ni++) {
                mma16816(acc[mi][ni], ah, bh[ni]);
                mma16816(acc[mi][ni], ah, bl[ni]);
                mma16816(acc[mi][ni], al, bh[ni]);
            }
        }
    }
}

// ---------------- G1: D[i=128][j=128-tile] = sum_x h*wb ----------------------
__global__ __launch_bounds__(256, 2) void k_mma_g1(int cur) {
    extern __shared__ __align__(128) char dsm[];
    const uint32_t sb0 = smem_to_u32(dsm);
    const int tid = threadIdx.x, lane = tid & 31, wid = tid >> 5;
    const int wmi = wid >> 2, wni = wid & 3;
    const int nt = blockIdx.x, sp = blockIdx.y, b = blockIdx.z;
    const __nv_bfloat16* Ah = g_h16h[cur] + (size_t)b * CC * NN + (size_t)sp * KSP;
    const __nv_bfloat16* Al = g_h16l[cur] + (size_t)b * CC * NN + (size_t)sp * KSP;
    const __nv_bfloat16* Bh = g_wb16h + ((size_t)b * 256 + nt * 128) * NN + (size_t)sp * KSP;
    const __nv_bfloat16* Bl = g_wb16l + ((size_t)b * 256 + nt * 128) * NN + (size_t)sp * KSP;
    float acc[4][4][4] = {};
    const int niter = KSP / 32;    // 32
    fill_g1(sb0, 0, tid, Ah, Al, Bh, Bl);
    CP_COMMIT;
    fill_g1(sb0 + STG, 32, tid, Ah, Al, Bh, Bl);
    CP_COMMIT;
    int fs = 2;
    for (int it = 0; it < niter; ++it) {
        CP_WAIT1;
        __syncthreads();
        if (it + 2 < niter) {
            fill_g1(sb0 + (uint32_t)fs * STG, (it + 2) * 32, tid, Ah, Al, Bh, Bl);
        }
        CP_COMMIT;
        const int cs = (fs + 1 == NSTAGE) ? 0 : fs + 1;
        compute_chunk<false>(sb0 + (uint32_t)((it % NSTAGE)) * STG, wmi, wni, lane, acc);
        fs = cs;
    }
    float* pp = g_part + (((size_t)sp * BB + b) * CC) * JP + nt * 128;
    #pragma unroll
    for (int mi = 0; mi < 4; mi++) {
        #pragma unroll
        for (int ni = 0; ni < 4; ni++) {
            const int m = wmi * 64 + mi * 16 + (lane >> 2);
            const int n = wni * 32 + ni * 8 + (lane & 3) * 2;
            *(float2*)&pp[(size_t)m * JP + n]       = make_float2(acc[mi][ni][0], acc[mi][ni][1]);
            *(float2*)&pp[(size_t)(m + 8) * JP + n] = make_float2(acc[mi][ni][2], acc[mi][ni][3]);
        }
    }
}

// ---------------- G2: D[o=128][x=128-tile] = sum_j A*[bases;h] ---------------
__global__ __launch_bounds__(256, 2) void k_mma_g2(int cur, int nxt,
                                                   const float* __restrict__ conv_b,
                                                   int l, int dogelu, int dox0) {
    extern __shared__ __align__(128) char dsm[];
    __shared__ float scb[128];
    __shared__ float s_wm[128];
    __shared__ float s_part[128][16];
    const uint32_t sb0 = smem_to_u32(dsm);
    const int tid = threadIdx.x, lane = tid & 31, wid = tid >> 5;
    const int wmi = wid >> 2, wni = wid & 3;
    const int xt = blockIdx.x, b = blockIdx.y;
    if (tid < 128) {
        scb[tid] = conv_b[l * CC + tid];
        s_wm[tid] = g_wm[(size_t)b * NN + (size_t)xt * 128 + tid];
    }
    const __nv_bfloat16* Ah = g_Ah + (size_t)b * CC * KA;
    const __nv_bfloat16* Al = g_Al + (size_t)b * CC * KA;
    const __nv_bfloat16* Bbh = g_b16h + (size_t)b * 257 * NN + (size_t)xt * 128;
    const __nv_bfloat16* Bbl = g_b16l + (size_t)b * 257 * NN + (size_t)xt * 128;
    const __nv_bfloat16* Hh = g_h16h[cur] + (size_t)b * CC * NN + (size_t)xt * 128;
    const __nv_bfloat16* Hl = g_h16l[cur] + (size_t)b * CC * NN + (size_t)xt * 128;
    float acc[4][4][4] = {};
    const int niter = KA / 32;   // 13
    fill_g2(sb0, 0, tid, Ah, Al, Bbh, Bbl, Hh, Hl);
    CP_COMMIT;
    fill_g2(sb0 + STG, 32, tid, Ah, Al, Bbh, Bbl, Hh, Hl);
    CP_COMMIT;
    int fs = 2;
    for (int it = 0; it < niter; ++it) {
        CP_WAIT1;
        __syncthreads();
        if (it + 2 < niter) {
            fill_g2(sb0 + (uint32_t)fs * STG, (it + 2) * 32, tid, Ah, Al, Bbh, Bbl, Hh, Hl);
        }
        CP_COMMIT;
        const int cs = (fs + 1 == NSTAGE) ? 0 : fs + 1;
        compute_chunk<true>(sb0 + (uint32_t)((it % NSTAGE)) * STG, wmi, wni, lane, acc);
        fs = cs;
    }
    __syncthreads();
    __nv_bfloat16* hh = g_h16h[nxt] + (size_t)b * CC * NN + (size_t)xt * 128;
    __nv_bfloat16* hl = g_h16l[nxt] + (size_t)b * CC * NN + (size_t)xt * 128;
    float sx[8] = {};
    #pragma unroll
    for (int mi = 0; mi < 4; mi++) {
        #pragma unroll
        for (int ni = 0; ni < 4; ni++) {
            const int n = wni * 32 + ni * 8 + (lane & 3) * 2;
            #pragma unroll
            for (int half = 0; half < 2; half++) {
                const int o = wmi * 64 + mi * 16 + (lane >> 2) + half * 8;
                float v0 = acc[mi][ni][half * 2 + 0] + scb[o];
                float v1 = acc[mi][ni][half * 2 + 1] + scb[o];
                if (dogelu) { v0 = gelu_f(v0); v1 = gelu_f(v1); }
                uint32_t pl, ph = pack_split2(v0, v1, &pl);
                *(uint32_t*)&hh[(size_t)o * NN + n] = ph;
                *(uint32_t*)&hl[(size_t)o * NN + n] = pl;
                if (dox0) {
                    sx[mi * 2 + half] = fmaf(v0, s_wm[n], sx[mi * 2 + half]);
                    sx[mi * 2 + half] = fmaf(v1, s_wm[n + 1], sx[mi * 2 + half]);
                }
            }
        }
    }
    if (dox0) {
        const int slot = wni * 4 + (lane & 3);
        #pragma unroll
        for (int mi = 0; mi < 4; mi++)
            #pragma unroll
            for (int half = 0; half < 2; half++) {
                const int o = wmi * 64 + mi * 16 + (lane >> 2) + half * 8;
                s_part[o][slot] = sx[mi * 2 + half];
            }
        __syncthreads();
        if (tid < 128) {
            float s = 0.f;
            #pragma unroll
            for (int q = 0; q < 16; q++) s += s_part[tid][q];
            g_x0p[xt][b * CC + tid] = s;
        }
    }
}

// ---------------- final MLP as MMA: y[x] = fc2 . gelu(fc1T @ h + b1) + b2 ----
__global__ __launch_bounds__(256, 2) void k_final_mma(const float* __restrict__ fc1_b,
                                                      const float* __restrict__ fc2_w,
                                                      const float* __restrict__ fc2_b,
                                                      float* __restrict__ out) {
    extern __shared__ __align__(128) char dsm[];
    __shared__ float s_fb[128];
    __shared__ float s_w2[128];
    __shared__ float s_red[128][17];
    const uint32_t sb0 = smem_to_u32(dsm);
    const int tid = threadIdx.x, lane = tid & 31, wid = tid >> 5;
    const int wmi = wid >> 2, wni = wid & 3;
    const int xt = blockIdx.x, b = blockIdx.y;
    if (tid < 128) { s_fb[tid] = fc1_b[tid]; s_w2[tid] = fc2_w[tid]; }
    const __nv_bfloat16* Hh = g_h16h[0] + (size_t)b * CC * NN + (size_t)xt * 128;
    const __nv_bfloat16* Hl = g_h16l[0] + (size_t)b * CC * NN + (size_t)xt * 128;
    float acc[4][4][4] = {};
    const int niter = CC / 32;   // 4
    fill_fc(sb0, 0, tid, Hh, Hl);
    CP_COMMIT;
    fill_fc(sb0 + STG, 32, tid, Hh, Hl);
    CP_COMMIT;
    int fs = 2;
    for (int it = 0; it < niter; ++it) {
        CP_WAIT1;
        __syncthreads();
        if (it + 2 < niter) {
            fill_fc(sb0 + (uint32_t)fs * STG, (it + 2) * 32, tid, Hh, Hl);
        }
        CP_COMMIT;
        const int cs = (fs + 1 == NSTAGE) ? 0 : fs + 1;
        compute_chunk<true>(sb0 + (uint32_t)((it % NSTAGE)) * STG, wmi, wni, lane, acc);
        fs = cs;
    }
    __syncthreads();
    float xs[8] = {};
    #pragma unroll
    for (int mi = 0; mi < 4; mi++) {
        #pragma unroll
        for (int ni = 0; ni < 4; ni++) {
            #pragma unroll
            for (int half = 0; half < 2; half++) {
                const int f = wmi * 64 + mi * 16 + (lane >> 2) + half * 8;
                const float w2 = s_w2[f], b1 = s_fb[f];
                xs[ni * 2 + 0] = fmaf(w2, gelu_f(acc[mi][ni][half * 2 + 0] + b1), xs[ni * 2 + 0]);
                xs[ni * 2 + 1] = fmaf(w2, gelu_f(acc[mi][ni][half * 2 + 1] + b1), xs[ni * 2 + 1]);
            }
        }
    }
    const int slot = wmi * 8 + (lane >> 2);
    #pragma unroll
    for (int ni = 0; ni < 4; ni++) {
        #pragma unroll
        for (int p = 0; p < 2; p++) {
            const int x = wni * 32 + ni * 8 + (lane & 3) * 2 + p;
            s_red[x][slot] = xs[ni * 2 + p];
        }
    }
    __syncthreads();
    if (tid < 128) {
        float s = fc2_b[0];
        #pragma unroll
        for (int q = 0; q < 16; q++) s += s_red[tid][q];
        out[(size_t)b * NN + (size_t)xt * 128 + tid] = s;
    }
}

// ---------------- weight transpose (once) ------------------------------------
__global__ void k_wtrans(const float* __restrict__ wc, const float* __restrict__ ws) {
    __shared__ float sm[32][33];
    const int tile = blockIdx.x;
    const int o0 = (tile >> 2) * 32, k0 = (tile & 3) * 32;
    const int i = blockIdx.y, l = blockIdx.z;
    const float scale = 1.0f / 8192.0f;
    for (int w = 0; w < 2; w++) {
        const float* src = w ? ws : wc;
        float* dst = w ? g_wst : g_wct;
        #pragma unroll
        for (int s = 0; s < 4; s++) {
            int oo = threadIdx.y + 8 * s, kk = threadIdx.x;
            sm[oo][kk] = src[(((size_t)l * CC + i) * CC + (o0 + oo)) * KK + (k0 + kk)] * scale;
        }
        __syncthreads();
        #pragma unroll
        for (int s = 0; s < 4; s++) {
            int kk = threadIdx.y + 8 * s, oo = threadIdx.x;
            dst[(((size_t)l * KK + (k0 + kk)) * CC + i) * CC + (o0 + oo)] = sm[oo][kk];
        }
        __syncthreads();
    }
}

// ---------------- fc1^T split prep (once, tiny) -------------------------------
__global__ void k_prepfc(const float* __restrict__ fc1_w) {
    const int f = blockIdx.x, c = threadIdx.x;
    __nv_bfloat16 hi, lo;
    split_bf16(fc1_w[c * CC + f], &hi, &lo);
    g_fc1h[f * CC + c] = hi;
    g_fc1l[f * CC + c] = lo;
}

// ---------------- precompute: bases16, wb16, wm, h0 (2 x per thread) ----------
__global__ __launch_bounds__(256) void k_pre(const float* __restrict__ xin,
                                             const float* __restrict__ modes,
                                             const float* __restrict__ fc0_w,
                                             const float* __restrict__ fc0_b) {
    __shared__ float sm_modes[256];
    __shared__ float sm_w[384];
    __shared__ float sm_b[128];
    const int t = threadIdx.x;
    sm_modes[t] = modes[t];
    sm_w[t] = fc0_w[t];
    if (t < 128) { sm_w[256 + t] = fc0_w[256 + t]; sm_b[t] = fc0_b[t]; }
    __syncthreads();

    const int gid = (blockIdx.x * 256 + t) * 2;       // even x pair over B*N
    const int b = gid / NN, xx = gid - b * NN;
    const float* xr = xin + (size_t)gid * 7;
    const float p0i0 = xr[0], p0i1 = xr[1], p0i2 = xr[2];
    const float p0d0 = xr[3], p0d1 = xr[4], p0w = xr[5], p0m = xr[6];
    const float p1i0 = xr[7], p1i1 = xr[8], p1i2 = xr[9];
    const float p1d0 = xr[10], p1d1 = xr[11], p1w = xr[12], p1m = xr[13];

    const float wsz0 = p0w * (float)NN, wsz1 = p1w * (float)NN;
    *(float2*)&g_wm[gid] = make_float2(wsz0 * p0m, wsz1 * p1m);

    uint32_t* bh = (uint32_t*)(g_b16h + (size_t)b * 257 * NN + xx);
    uint32_t* bl = (uint32_t*)(g_b16l + (size_t)b * 257 * NN + xx);
    uint32_t* wbh = (uint32_t*)(g_wb16h + (size_t)b * 256 * NN + xx);
    uint32_t* wbl = (uint32_t*)(g_wb16l + (size_t)b * 256 * NN + xx);
    {
        __nv_bfloat162 pm; pm.x = __float2bfloat16(p0m); pm.y = __float2bfloat16(p1m);
        bh[(size_t)128 * NN] = *(uint32_t*)&pm;    // row 256, /2 since u32 ptr
        bl[(size_t)128 * NN] = 0u;
    }
    #pragma unroll 2
    for (int k = 0; k < KK; k++) {
        const float m0 = sm_modes[2 * k], m1 = sm_modes[2 * k + 1];
        float s0, c0, s1, c1;
        fast_sincos(fmaf(p0d0, m0, p0d1 * m1), &s0, &c0);
        fast_sincos(fmaf(p1d0, m0, p1d1 * m1), &s1, &c1);
        const float cm0 = c0 * p0m, sm0 = s0 * p0m;
        const float cm1 = c1 * p1m, sm1 = s1 * p1m;
        uint32_t lo, hi;
        hi = pack_split2(cm0, cm1, &lo);
        bh[(size_t)k * (NN / 2)] = hi; bl[(size_t)k * (NN / 2)] = lo;
        hi = pack_split2(sm0, sm1, &lo);
        bh[(size_t)(128 + k) * (NN / 2)] = hi; bl[(size_t)(128 + k) * (NN / 2)] = lo;
        hi = pack_split2(cm0 * wsz0, cm1 * wsz1, &lo);
        wbh[(size_t)k * (NN / 2)] = hi; wbl[(size_t)k * (NN / 2)] = lo;
        hi = pack_split2(sm0 * wsz0, sm1 * wsz1, &lo);
        wbh[(size_t)(128 + k) * (NN / 2)] = hi; wbl[(size_t)(128 + k) * (NN / 2)] = lo;
    }
    uint32_t* h16h = (uint32_t*)(g_h16h[0] + (size_t)b * CC * NN + xx);
    uint32_t* h16l = (uint32_t*)(g_h16l[0] + (size_t)b * CC * NN + xx);
    #pragma unroll 4
    for (int c = 0; c < CC; c++) {
        float v0 = sm_b[c], v1 = sm_b[c];
        v0 = fmaf(p0i0, sm_w[c], v0);
        v0 = fmaf(p0i1, sm_w[128 + c], v0);
        v0 = fmaf(p0i2, sm_w[256 + c], v0);
        v1 = fmaf(p1i0, sm_w[c], v1);
        v1 = fmaf(p1i1, sm_w[128 + c], v1);
        v1 = fmaf(p1i2, sm_w[256 + c], v1);
        uint32_t lo, hi = pack_split2(v0, v1, &lo);
        h16h[(size_t)c * (NN / 2)] = hi;
        h16l[(size_t)c * (NN / 2)] = lo;
    }
}

// NOTE: bh/bl row-256 indexing above: the u32 pointer strides are in 4-byte units,
// so row j is at j*(NN/2); row 256 = 128*NN in u32 units. (256*NN/2 == 128*NN.)

// ---------------- x_0 partials for layer 0 (reads h0 splits) ------------------
__global__ __launch_bounds__(256) void k_x0() {
    const int b = blockIdx.x;
    const int i = blockIdx.y * 8 + (threadIdx.x >> 5);
    const int z = blockIdx.z;
    const int lane = threadIdx.x & 31;
    const int q = NN / 32;
    const uint4* hp = (const uint4*)(g_h16h[0] + ((size_t)b * CC + i) * NN) + (size_t)z * q;
    const uint4* lp = (const uint4*)(g_h16l[0] + ((size_t)b * CC + i) * NN) + (size_t)z * q;
    const float4* wp = (const float4*)(g_wm + (size_t)b * NN) + (size_t)z * q * 2;
    float s = 0.f;
    for (int t = lane; t < q; t += 32) {
        uint4 hv = hp[t], lv = lp[t];
        float4 w0 = wp[2 * t], w1 = wp[2 * t + 1];
        float2 v0 = rec2(hv.x, lv.x), v1 = rec2(hv.y, lv.y);
        float2 v2 = rec2(hv.z, lv.z), v3 = rec2(hv.w, lv.w);
        s = fmaf(v0.x, w0.x, s); s = fmaf(v0.y, w0.y, s);
        s = fmaf(v1.x, w0.z, s); s = fmaf(v1.y, w0.w, s);
        s = fmaf(v2.x, w1.x, s); s = fmaf(v2.y, w1.y, s);
        s = fmaf(v3.x, w1.z, s); s = fmaf(v3.y, w1.w, s);
    }
    #pragma unroll
    for (int off = 16; off; off >>= 1) s += __shfl_xor_sync(0xffffffffu, s, off);
    if (!lane) g_x0p[z][b * CC + i] = s;
}

// ---------------- k_mid: fused fmix (bx<128) + f0/conv/pad (bx>=128) ----------
__global__ __launch_bounds__(128) void k_mid(const float* __restrict__ w0,
                                             const float* __restrict__ conv_w,
                                             int l, int npart) {
    const int t = threadIdx.x;
    if (blockIdx.x < 128) {
        const int k = blockIdx.x;
        const int bh = blockIdx.y * 8;
        __shared__ float xc_s[128][8];
        __shared__ float xs_s[128][8];
        #pragma unroll
        for (int b = 0; b < 8; b++) {
            float sc = 0.f, ss = 0.f;
            #pragma unroll
            for (int s = 0; s < NSPLIT; s++) {
                const float* pp = g_part + (((size_t)s * BB + bh + b) * CC + t) * JP;
                sc += pp[k];
                ss += pp[128 + k];
            }
            xc_s[t][b] = sc;
            xs_s[t][b] = -ss;
        }
        __syncthreads();
        float fc[8] = {}, fs[8] = {};
        const float* wcp = g_wct + ((size_t)(l * KK + k)) * CC * CC + t;
        const float* wsp = g_wst + ((size_t)(l * KK + k)) * CC * CC + t;
        #pragma unroll 4
        for (int i = 0; i < 128; i++) {
            const float wcv = wcp[(size_t)i * CC], wsv = wsp[(size_t)i * CC];
            #pragma unroll
            for (int b = 0; b < 8; b++) {
                const float cv = xc_s[i][b], sv = xs_s[i][b];
                fc[b] = fmaf(cv, wcv, fc[b]); fc[b] = fmaf(-sv, wsv, fc[b]);
                fs[b] = fmaf(sv, wcv, fs[b]); fs[b] = fmaf(cv, wsv, fs[b]);
            }
        }
        #pragma unroll
        for (int b = 0; b < 8; b++) {
            const size_t base = ((size_t)(bh + b) * CC + t) * KA;
            __nv_bfloat16 hi, lo;
            split_bf16(2.f * fc[b], &hi, &lo);
            g_Ah[base + k] = hi; g_Al[base + k] = lo;
            split_bf16(-2.f * fs[b], &hi, &lo);
            g_Ah[base + 128 + k] = hi; g_Al[base + 128 + k] = lo;
        }
    } else {
        const int b = (blockIdx.x - 128) + blockIdx.y * 8;
        __shared__ float x0s[128];
        float s = 0.f;
        for (int p = 0; p < npart; p++) s += g_x0p[p][b * CC + t];
        x0s[t] = s;
        __syncthreads();
        float f0 = 0.f;
        const float* w0p = w0 + (size_t)l * CC * CC;
        #pragma unroll 8
        for (int i = 0; i < 128; i++) f0 = fmaf(x0s[i], w0p[(size_t)i * CC + t], f0);
        const size_t base = ((size_t)b * CC + t) * KA;
        __nv_bfloat16 hi, lo;
        split_bf16(f0 * (1.0f / 8192.0f), &hi, &lo);
        g_Ah[base + 256] = hi; g_Al[base + 256] = lo;
        const float* cw = conv_w + ((size_t)(l * CC) + t) * CC;
        #pragma unroll 8
        for (int i = 0; i < 128; i++) {
            split_bf16(cw[i], &hi, &lo);
            g_Ah[base + 257 + i] = hi; g_Al[base + 257 + i] = lo;
        }
        const __nv_bfloat16 z = __float2bfloat16(0.f);
        #pragma unroll
        for (int j = 385; j < KA; j++) { g_Ah[base + j] = z; g_Al[base + j] = z; }
    }
}

// ---------------- launch -------------------------------------------------------
extern "C" void kernel_launch(void* const* d_in, const int* in_sizes, int n_in,
                              void* d_out, int out_size) {
    const float* x      = (const float*)d_in[0];
    const float* modes  = (const float*)d_in[1];
    const float* fc0_w  = (const float*)d_in[2];
    const float* fc0_b  = (const float*)d_in[3];
    const float* wc     = (const float*)d_in[4];
    const float* ws     = (const float*)d_in[5];
    const float* w0     = (const float*)d_in[6];
    const float* conv_w = (const float*)d_in[7];
    const float* conv_b = (const float*)d_in[8];
    const float* fc1_w  = (const float*)d_in[9];
    const float* fc1_b  = (const float*)d_in[10];
    const float* fc2_w  = (const float*)d_in[11];
    const float* fc2_b  = (const float*)d_in[12];
    float* out = (float*)d_out;

    const int smem = NSTAGE * (int)STG;   // 96KB
    cudaFuncSetAttribute(k_mma_g1, cudaFuncAttributeMaxDynamicSharedMemorySize, smem);
    cudaFuncSetAttribute(k_mma_g2, cudaFuncAttributeMaxDynamicSharedMemorySize, smem);
    cudaFuncSetAttribute(k_final_mma, cudaFuncAttributeMaxDynamicSharedMemorySize, smem);

    k_wtrans<<<dim3(16, 128, 4), dim3(32, 8)>>>(wc, ws);
    k_prepfc<<<CC, CC>>>(fc1_w);
    k_pre<<<(BB * NN) / 512, 256>>>(x, modes, fc0_w, fc0_b);
    k_x0<<<dim3(BB, 16, 4), 256>>>();
    for (int l = 0; l < LL; l++) {
        const int cur = l & 1, nxt = cur ^ 1;
        k_mma_g1<<<dim3(2, NSPLIT, BB), 256, smem>>>(cur);
        k_mid<<<dim3(136, 2), 128>>>(w0, conv_w, l, (l == 0) ? 4 : 64);
        k_mma_g2<<<dim3(NN / 128, BB), 256, smem>>>(cur, nxt, conv_b, l,
                                                    (l < LL - 1) ? 1 : 0,
                                                    (l < LL - 1) ? 1 : 0);
    }
    k_final_mma<<<dim3(NN / 128, BB), 256, smem>>>(fc1_b, fc2_w, fc2_b, out);
}